// round 1
// baseline (speedup 1.0000x reference)
#include <cuda_runtime.h>
#include <cstdint>

// ---------------------------------------------------------------------------
// Problem constants
//   x: [B=4, T=8, N=512, D=512]  -> R = B*T*N = 16384 rows of D=512
//   heads K=8, dh=64, H = B*T*K = 256, DFF = 2048
// ---------------------------------------------------------------------------
#define R_ROWS 16384
#define N_NODES 512
#define D_DIM 512
#define H_HEADS 256
#define DH 64
#define DFF 2048

// Single scratch arena (device global: allocation-free per harness rules).
// Layout (float offsets):
//   xn      [16384*512]      @ 0
//   q       [16384*512]      @ 8388608
//   k       [16384*512]      @ 16777216
//   v       [16384*512]      @ 25165824
//   attnout [16384*512]      @ 33554432
//   x1      [16384*512]      @ 41943040
//   hin     [16384*512]      @ 50331648
//   h       [16384*2048]     @ 58720256
//   logits  [256*512*512]    @ 92274688
//   gbias   [512*512]        @ 159383552
__device__ float g_scratch[159645696];

#define OFF_XN   0ull
#define OFF_Q    8388608ull
#define OFF_K    16777216ull
#define OFF_V    25165824ull
#define OFF_AO   33554432ull
#define OFF_X1   41943040ull
#define OFF_HIN  50331648ull
#define OFF_H    58720256ull
#define OFF_LOG  92274688ull
#define OFF_GB   159383552ull

// ---------------------------------------------------------------------------
// Graph bias precompute:
//   supports = softmax(relu(E @ E^T), axis=1)   (E = node_embeddings [512,64])
//   gbias[i][j] = alpha*supports[i][j] + beta*lap[i][j] + (lap[i][j]!=0 ? 0 : -1e9)
// One CTA per row i, 256 threads, 2 columns each.
// ---------------------------------------------------------------------------
__global__ __launch_bounds__(256) void bias_kernel(
    const float* __restrict__ E, const float* __restrict__ lap,
    const float* __restrict__ alphap, const float* __restrict__ betap,
    float* __restrict__ gb)
{
    __shared__ __align__(16) float ei[64];
    __shared__ float reda[8];
    __shared__ float redb[8];
    int i = blockIdx.x;
    int tid = threadIdx.x;
    if (tid < 16) ((float4*)ei)[tid] = ((const float4*)(E + (size_t)i * 64))[tid];
    __syncthreads();

    int j0 = tid, j1 = tid + 256;
    const float* e0 = E + (size_t)j0 * 64;
    const float* e1 = E + (size_t)j1 * 64;
    float r0 = 0.f, r1 = 0.f;
#pragma unroll
    for (int e = 0; e < 64; e += 4) {
        float4 a = *(const float4*)(ei + e);
        float4 u = *(const float4*)(e0 + e);
        float4 w = *(const float4*)(e1 + e);
        r0 += a.x * u.x + a.y * u.y + a.z * u.z + a.w * u.w;
        r1 += a.x * w.x + a.y * w.y + a.z * w.z + a.w * w.w;
    }
    r0 = fmaxf(r0, 0.f);
    r1 = fmaxf(r1, 0.f);

    // block max
    float mx = fmaxf(r0, r1);
#pragma unroll
    for (int o = 16; o; o >>= 1) mx = fmaxf(mx, __shfl_xor_sync(0xffffffffu, mx, o));
    if ((tid & 31) == 0) reda[tid >> 5] = mx;
    __syncthreads();
    mx = fmaxf(fmaxf(fmaxf(reda[0], reda[1]), fmaxf(reda[2], reda[3])),
               fmaxf(fmaxf(reda[4], reda[5]), fmaxf(reda[6], reda[7])));

    float ex0 = __expf(r0 - mx), ex1 = __expf(r1 - mx);
    float s = ex0 + ex1;
#pragma unroll
    for (int o = 16; o; o >>= 1) s += __shfl_xor_sync(0xffffffffu, s, o);
    if ((tid & 31) == 0) redb[tid >> 5] = s;
    __syncthreads();
    s = redb[0] + redb[1] + redb[2] + redb[3] + redb[4] + redb[5] + redb[6] + redb[7];
    float inv = 1.0f / s;

    float alpha = *alphap, beta = *betap;
    float lp0 = lap[(size_t)i * 512 + j0];
    float lp1 = lap[(size_t)i * 512 + j1];
    float m0 = (lp0 != 0.f) ? 0.f : -1e9f;
    float m1 = (lp1 != 0.f) ? 0.f : -1e9f;
    gb[(size_t)i * 512 + j0] = alpha * ex0 * inv + beta * lp0 + m0;
    gb[(size_t)i * 512 + j1] = alpha * ex1 * inv + beta * lp1 + m1;
}

// ---------------------------------------------------------------------------
// LayerNorm over D=512. One warp per row.
// ---------------------------------------------------------------------------
__global__ __launch_bounds__(256) void ln_kernel(
    const float* __restrict__ X, const float* __restrict__ g,
    const float* __restrict__ b, float* __restrict__ Y, int rows)
{
    int gw = (blockIdx.x * 256 + threadIdx.x) >> 5;
    if (gw >= rows) return;
    int lane = threadIdx.x & 31;
    const float* xr = X + (size_t)gw * 512;
    float* yr = Y + (size_t)gw * 512;
    float4 v[4];
    float s = 0.f, ss = 0.f;
#pragma unroll
    for (int w = 0; w < 4; w++) {
        v[w] = *(const float4*)(xr + w * 128 + lane * 4);
        s += v[w].x + v[w].y + v[w].z + v[w].w;
        ss += v[w].x * v[w].x + v[w].y * v[w].y + v[w].z * v[w].z + v[w].w * v[w].w;
    }
#pragma unroll
    for (int o = 16; o; o >>= 1) {
        s += __shfl_xor_sync(0xffffffffu, s, o);
        ss += __shfl_xor_sync(0xffffffffu, ss, o);
    }
    float mean = s * (1.0f / 512.0f);
    float var = ss * (1.0f / 512.0f) - mean * mean;
    float rstd = rsqrtf(var + 1e-5f);
#pragma unroll
    for (int w = 0; w < 4; w++) {
        int c = w * 128 + lane * 4;
        float4 gg = *(const float4*)(g + c);
        float4 bb = *(const float4*)(b + c);
        float4 o;
        o.x = (v[w].x - mean) * rstd * gg.x + bb.x;
        o.y = (v[w].y - mean) * rstd * gg.y + bb.y;
        o.z = (v[w].z - mean) * rstd * gg.z + bb.z;
        o.w = (v[w].w - mean) * rstd * gg.w + bb.w;
        *(float4*)(yr + c) = o;
    }
}

// ---------------------------------------------------------------------------
// NT SGEMM: C[m,n] = sum_k A[m,k]*Bw[n,k] + bias[n]  (+relu)(+res[m,n])
// A: [M,Kd] row-major, Bw: [N,Kd] row-major. All dims % {128,128,8} == 0.
// 128x128 block, 256 threads, 8x8 register tile, BK=8.
// ---------------------------------------------------------------------------
__global__ __launch_bounds__(256) void gemm_nt_kernel(
    const float* __restrict__ A, const float* __restrict__ Bw,
    const float* __restrict__ bias, const float* __restrict__ res,
    float* __restrict__ C, int M, int N, int Kd, int relu)
{
    __shared__ __align__(16) float As[8][128];
    __shared__ __align__(16) float Bs[8][128];
    int tid = threadIdx.x;
    int bm = blockIdx.y << 7;
    int bn = blockIdx.x << 7;
    int trow = (tid >> 4) << 3;
    int tcol = (tid & 15) << 3;
    int arow = tid >> 1;
    int acol = (tid & 1) << 2;
    const float* Ag = A + (size_t)(bm + arow) * Kd + acol;
    const float* Bg = Bw + (size_t)(bn + arow) * Kd + acol;

    float acc[8][8];
#pragma unroll
    for (int i = 0; i < 8; i++)
#pragma unroll
        for (int j = 0; j < 8; j++) acc[i][j] = 0.f;

    for (int k0 = 0; k0 < Kd; k0 += 8) {
        float4 a4 = *(const float4*)(Ag + k0);
        float4 b4 = *(const float4*)(Bg + k0);
        As[acol + 0][arow] = a4.x;
        As[acol + 1][arow] = a4.y;
        As[acol + 2][arow] = a4.z;
        As[acol + 3][arow] = a4.w;
        Bs[acol + 0][arow] = b4.x;
        Bs[acol + 1][arow] = b4.y;
        Bs[acol + 2][arow] = b4.z;
        Bs[acol + 3][arow] = b4.w;
        __syncthreads();
#pragma unroll
        for (int kk = 0; kk < 8; kk++) {
            float4 a0 = *(const float4*)&As[kk][trow];
            float4 a1 = *(const float4*)&As[kk][trow + 4];
            float4 b0 = *(const float4*)&Bs[kk][tcol];
            float4 b1 = *(const float4*)&Bs[kk][tcol + 4];
            float ar[8] = {a0.x, a0.y, a0.z, a0.w, a1.x, a1.y, a1.z, a1.w};
            float br[8] = {b0.x, b0.y, b0.z, b0.w, b1.x, b1.y, b1.z, b1.w};
#pragma unroll
            for (int ii = 0; ii < 8; ii++)
#pragma unroll
                for (int jj = 0; jj < 8; jj++)
                    acc[ii][jj] = fmaf(ar[ii], br[jj], acc[ii][jj]);
        }
        __syncthreads();
    }

    float bv[8];
#pragma unroll
    for (int jj = 0; jj < 8; jj++) bv[jj] = bias[bn + tcol + jj];
#pragma unroll
    for (int ii = 0; ii < 8; ii++) {
        size_t row = (size_t)(bm + trow + ii);
        float* Cp = C + row * N + bn + tcol;
#pragma unroll
        for (int jj = 0; jj < 8; jj++) {
            float c = acc[ii][jj] + bv[jj];
            if (relu) c = fmaxf(c, 0.f);
            acc[ii][jj] = c;
        }
        if (res) {
            const float* Rp = res + row * N + bn + tcol;
            float4 r0 = *(const float4*)(Rp);
            float4 r1 = *(const float4*)(Rp + 4);
            acc[ii][0] += r0.x; acc[ii][1] += r0.y; acc[ii][2] += r0.z; acc[ii][3] += r0.w;
            acc[ii][4] += r1.x; acc[ii][5] += r1.y; acc[ii][6] += r1.z; acc[ii][7] += r1.w;
        }
        float4 o0 = make_float4(acc[ii][0], acc[ii][1], acc[ii][2], acc[ii][3]);
        float4 o1 = make_float4(acc[ii][4], acc[ii][5], acc[ii][6], acc[ii][7]);
        *(float4*)(Cp) = o0;
        *(float4*)(Cp + 4) = o1;
    }
}

// ---------------------------------------------------------------------------
// Attention scores: logits[h][i][j] = (Q_h[i] . K_h[j]) / 8 + gbias[i][j]
// grid (jTile=8, iTile=8, head=256); 64x64 tile, full K=64 in smem.
// q/k layout: [B*T*N, D] with head slice at col kh*64.
// ---------------------------------------------------------------------------
__global__ __launch_bounds__(256) void attn_scores_kernel(
    const float* __restrict__ q, const float* __restrict__ kmat,
    const float* __restrict__ gb, float* __restrict__ logits)
{
    __shared__ __align__(16) float Qs[64][64];  // [e][i]
    __shared__ __align__(16) float Ks[64][64];  // [e][j]
    int h = blockIdx.z;
    int bt = h >> 3;
    int kh = h & 7;
    int i0 = blockIdx.y << 6;
    int j0 = blockIdx.x << 6;
    int tid = threadIdx.x;

    int lr = tid >> 2;
    int lc = (tid & 3) << 4;
    const float* qg = q + ((size_t)(bt * 512 + i0 + lr)) * 512 + kh * 64 + lc;
    const float* kg = kmat + ((size_t)(bt * 512 + j0 + lr)) * 512 + kh * 64 + lc;
#pragma unroll
    for (int c = 0; c < 16; c += 4) {
        float4 a = *(const float4*)(qg + c);
        Qs[lc + c + 0][lr] = a.x;
        Qs[lc + c + 1][lr] = a.y;
        Qs[lc + c + 2][lr] = a.z;
        Qs[lc + c + 3][lr] = a.w;
        float4 b = *(const float4*)(kg + c);
        Ks[lc + c + 0][lr] = b.x;
        Ks[lc + c + 1][lr] = b.y;
        Ks[lc + c + 2][lr] = b.z;
        Ks[lc + c + 3][lr] = b.w;
    }
    __syncthreads();

    int ty = tid >> 4, tx = tid & 15;
    float acc[4][4];
#pragma unroll
    for (int i = 0; i < 4; i++)
#pragma unroll
        for (int j = 0; j < 4; j++) acc[i][j] = 0.f;

#pragma unroll
    for (int e = 0; e < 64; e++) {
        float4 a4 = *(const float4*)&Qs[e][ty << 2];
        float4 b4 = *(const float4*)&Ks[e][tx << 2];
        float ar[4] = {a4.x, a4.y, a4.z, a4.w};
        float br[4] = {b4.x, b4.y, b4.z, b4.w};
#pragma unroll
        for (int ii = 0; ii < 4; ii++)
#pragma unroll
            for (int jj = 0; jj < 4; jj++)
                acc[ii][jj] = fmaf(ar[ii], br[jj], acc[ii][jj]);
    }

#pragma unroll
    for (int ii = 0; ii < 4; ii++) {
        int gi = i0 + (ty << 2) + ii;
#pragma unroll
        for (int jj = 0; jj < 4; jj++) {
            int gj = j0 + (tx << 2) + jj;
            logits[((size_t)h * 512 + gi) * 512 + gj] =
                acc[ii][jj] * 0.125f + gb[(size_t)gi * 512 + gj];
        }
    }
}

// ---------------------------------------------------------------------------
// Row softmax, in place, one warp per row of 512.
// ---------------------------------------------------------------------------
__global__ __launch_bounds__(256) void softmax_kernel(float* __restrict__ L, int rows)
{
    int r = (blockIdx.x * 256 + threadIdx.x) >> 5;
    if (r >= rows) return;
    int lane = threadIdx.x & 31;
    float* row = L + (size_t)r * 512;
    float4 v[4];
    float mx = -3.0e38f;
#pragma unroll
    for (int w = 0; w < 4; w++) {
        v[w] = *(const float4*)(row + w * 128 + lane * 4);
        mx = fmaxf(mx, fmaxf(fmaxf(v[w].x, v[w].y), fmaxf(v[w].z, v[w].w)));
    }
#pragma unroll
    for (int o = 16; o; o >>= 1) mx = fmaxf(mx, __shfl_xor_sync(0xffffffffu, mx, o));
    float s = 0.f;
#pragma unroll
    for (int w = 0; w < 4; w++) {
        v[w].x = __expf(v[w].x - mx);
        v[w].y = __expf(v[w].y - mx);
        v[w].z = __expf(v[w].z - mx);
        v[w].w = __expf(v[w].w - mx);
        s += v[w].x + v[w].y + v[w].z + v[w].w;
    }
#pragma unroll
    for (int o = 16; o; o >>= 1) s += __shfl_xor_sync(0xffffffffu, s, o);
    float inv = 1.0f / s;
#pragma unroll
    for (int w = 0; w < 4; w++) {
        v[w].x *= inv; v[w].y *= inv; v[w].z *= inv; v[w].w *= inv;
        *(float4*)(row + w * 128 + lane * 4) = v[w];
    }
}

// ---------------------------------------------------------------------------
// out_h = attn_h @ V_h.  NN batched GEMM: M=512, N=64(dh), K=512 per head.
// grid (mTile=8, head=256). BM=64, BN=64, BK=32.
// Writes to attnout at [bt*512 + m, kh*64 + n].
// ---------------------------------------------------------------------------
__global__ __launch_bounds__(256) void attn_av_kernel(
    const float* __restrict__ attn, const float* __restrict__ v,
    float* __restrict__ out)
{
    __shared__ __align__(16) float Ast[32][64];  // [k][m]
    __shared__ __align__(16) float Bs[32][64];   // [k][n]
    int h = blockIdx.y;
    int bt = h >> 3;
    int kh = h & 7;
    int i0 = blockIdx.x << 6;
    int tid = threadIdx.x;

    int am = tid >> 2;
    int ak = (tid & 3) << 3;
    int bk = tid >> 3;
    int bn = (tid & 7) << 3;
    const float* Ag = attn + ((size_t)h * 512 + i0 + am) * 512 + ak;
    const float* Bgb = v + (size_t)(bt * 512) * 512 + kh * 64 + bn;

    int ty = tid >> 4, tx = tid & 15;
    float acc[4][4];
#pragma unroll
    for (int i = 0; i < 4; i++)
#pragma unroll
        for (int j = 0; j < 4; j++) acc[i][j] = 0.f;

    for (int k0 = 0; k0 < 512; k0 += 32) {
        float4 a0 = *(const float4*)(Ag + k0);
        float4 a1 = *(const float4*)(Ag + k0 + 4);
        Ast[ak + 0][am] = a0.x; Ast[ak + 1][am] = a0.y;
        Ast[ak + 2][am] = a0.z; Ast[ak + 3][am] = a0.w;
        Ast[ak + 4][am] = a1.x; Ast[ak + 5][am] = a1.y;
        Ast[ak + 6][am] = a1.z; Ast[ak + 7][am] = a1.w;
        const float* Bg = Bgb + (size_t)(k0 + bk) * 512;
        float4 b0 = *(const float4*)(Bg);
        float4 b1 = *(const float4*)(Bg + 4);
        *(float4*)&Bs[bk][bn] = b0;
        *(float4*)&Bs[bk][bn + 4] = b1;
        __syncthreads();
#pragma unroll
        for (int kk = 0; kk < 32; kk++) {
            float4 a4 = *(const float4*)&Ast[kk][ty << 2];
            float4 b4 = *(const float4*)&Bs[kk][tx << 2];
            float ar[4] = {a4.x, a4.y, a4.z, a4.w};
            float br[4] = {b4.x, b4.y, b4.z, b4.w};
#pragma unroll
            for (int ii = 0; ii < 4; ii++)
#pragma unroll
                for (int jj = 0; jj < 4; jj++)
                    acc[ii][jj] = fmaf(ar[ii], br[jj], acc[ii][jj]);
        }
        __syncthreads();
    }

#pragma unroll
    for (int ii = 0; ii < 4; ii++) {
        size_t row = (size_t)(bt * 512 + i0 + (ty << 2) + ii);
        float* Op = out + row * 512 + kh * 64 + (tx << 2);
        float4 o = make_float4(acc[ii][0], acc[ii][1], acc[ii][2], acc[ii][3]);
        *(float4*)Op = o;
    }
}

// ---------------------------------------------------------------------------
// Host launcher
// ---------------------------------------------------------------------------
extern "C" void kernel_launch(void* const* d_in, const int* in_sizes, int n_in,
                              void* d_out, int out_size)
{
    const float* x    = (const float*)d_in[0];
    const float* lap  = (const float*)d_in[1];
    const float* emb  = (const float*)d_in[2];
    const float* Wq   = (const float*)d_in[3];
    const float* bq   = (const float*)d_in[4];
    const float* Wk   = (const float*)d_in[5];
    const float* bk   = (const float*)d_in[6];
    const float* Wv   = (const float*)d_in[7];
    const float* bv   = (const float*)d_in[8];
    const float* ln1g = (const float*)d_in[9];
    const float* ln1b = (const float*)d_in[10];
    const float* ln2g = (const float*)d_in[11];
    const float* ln2b = (const float*)d_in[12];
    const float* alpha = (const float*)d_in[13];
    const float* beta  = (const float*)d_in[14];
    const float* Wo   = (const float*)d_in[15];
    const float* bo   = (const float*)d_in[16];
    const float* W1   = (const float*)d_in[17];
    const float* b1   = (const float*)d_in[18];
    const float* W2   = (const float*)d_in[19];
    const float* b2   = (const float*)d_in[20];
    float* out = (float*)d_out;

    float* base = nullptr;
    cudaGetSymbolAddress((void**)&base, g_scratch);
    float* xn     = base + OFF_XN;
    float* q      = base + OFF_Q;
    float* kbuf   = base + OFF_K;
    float* vbuf   = base + OFF_V;
    float* ao     = base + OFF_AO;
    float* x1     = base + OFF_X1;
    float* hin    = base + OFF_HIN;
    float* hbuf   = base + OFF_H;
    float* logits = base + OFF_LOG;
    float* gb     = base + OFF_GB;

    // 1. graph bias (supports softmax + lap + mask)
    bias_kernel<<<512, 256>>>(emb, lap, alpha, beta, gb);

    // 2. LN1
    ln_kernel<<<R_ROWS / 8, 256>>>(x, ln1g, ln1b, xn, R_ROWS);

    // 3. QKV projections (NT gemms, M=16384, N=512, K=512)
    dim3 gq(D_DIM / 128, R_ROWS / 128);
    gemm_nt_kernel<<<gq, 256>>>(xn, Wq, bq, nullptr, q,    R_ROWS, D_DIM, D_DIM, 0);
    gemm_nt_kernel<<<gq, 256>>>(xn, Wk, bk, nullptr, kbuf, R_ROWS, D_DIM, D_DIM, 0);
    gemm_nt_kernel<<<gq, 256>>>(xn, Wv, bv, nullptr, vbuf, R_ROWS, D_DIM, D_DIM, 0);

    // 4. scores + bias
    attn_scores_kernel<<<dim3(8, 8, H_HEADS), 256>>>(q, kbuf, gb, logits);

    // 5. softmax over last axis (256*512 rows)
    softmax_kernel<<<(H_HEADS * N_NODES) / 8, 256>>>(logits, H_HEADS * N_NODES);

    // 6. attn @ V -> attnout (head-interleaved [R, D])
    attn_av_kernel<<<dim3(8, H_HEADS), 256>>>(logits, vbuf, ao);

    // 7. output projection + residual: x1 = x + ao @ Wo^T + bo
    gemm_nt_kernel<<<gq, 256>>>(ao, Wo, bo, x, x1, R_ROWS, D_DIM, D_DIM, 0);

    // 8. LN2
    ln_kernel<<<R_ROWS / 8, 256>>>(x1, ln2g, ln2b, hin, R_ROWS);

    // 9. FF up: h = relu(hin @ W1^T + b1)   [16384, 2048]
    gemm_nt_kernel<<<dim3(DFF / 128, R_ROWS / 128), 256>>>(
        hin, W1, b1, nullptr, hbuf, R_ROWS, DFF, D_DIM, 1);

    // 10. FF down + residual: out = x1 + h @ W2^T + b2
    gemm_nt_kernel<<<dim3(D_DIM / 128, R_ROWS / 128), 256>>>(
        hbuf, W2, b2, x1, out, R_ROWS, D_DIM, DFF, 0);
}

// round 4
// speedup vs baseline: 1.3733x; 1.3733x over previous
#include <cuda_runtime.h>
#include <cstdint>

// ---------------------------------------------------------------------------
// Problem constants
//   x: [B=4, T=8, N=512, D=512]  -> R = B*T*N = 16384 rows of D=512
//   heads K=8, dh=64, H = B*T*K = 256, DFF = 2048
// ---------------------------------------------------------------------------
#define R_ROWS 16384
#define N_NODES 512
#define D_DIM 512
#define H_HEADS 256
#define DFF 2048

__device__ float g_scratch[159645696];

#define OFF_XN   0ull
#define OFF_Q    8388608ull
#define OFF_K    16777216ull
#define OFF_V    25165824ull
#define OFF_AO   33554432ull
#define OFF_X1   41943040ull
#define OFF_HIN  50331648ull
#define OFF_H    58720256ull
#define OFF_LOG  92274688ull
#define OFF_GB   159383552ull

// ===========================================================================
// Helpers: cp.async + mma.sync tf32 (compute_103-safe PTX, no 'a' features)
// ===========================================================================
__device__ __forceinline__ uint32_t smem_u32(const void* p) {
    uint32_t a;
    asm("{ .reg .u64 t; cvta.to.shared.u64 t, %1; cvt.u32.u64 %0, t; }"
        : "=r"(a) : "l"(p));
    return a;
}

#define CP_ASYNC16(dst, src) \
    asm volatile("cp.async.cg.shared.global [%0], [%1], 16;" :: "r"(dst), "l"(src))
#define CP_COMMIT() asm volatile("cp.async.commit_group;" ::: "memory")
#define CP_WAIT1()  asm volatile("cp.async.wait_group 1;" ::: "memory")
#define CP_WAIT0()  asm volatile("cp.async.wait_group 0;" ::: "memory")

// D(f32) += A(tf32) * B(tf32), m16n8k8, A row-major, B col-major
#define MMA_TF32(d, a0, a1, a2, a3, b0, b1) \
    asm volatile("mma.sync.aligned.m16n8k8.row.col.f32.tf32.tf32.f32 " \
        "{%0,%1,%2,%3}, {%4,%5,%6,%7}, {%8,%9}, {%0,%1,%2,%3};" \
        : "+f"((d)[0]), "+f"((d)[1]), "+f"((d)[2]), "+f"((d)[3]) \
        : "r"(a0), "r"(a1), "r"(a2), "r"(a3), "r"(b0), "r"(b1))

// 3xTF32 split: hi = tf32_rna(x), lo = tf32_rna(x - hi)
__device__ __forceinline__ void split_tf32(float x, uint32_t& hi, uint32_t& lo) {
    uint32_t h;
    asm("cvt.rna.tf32.f32 %0, %1;" : "=r"(h) : "f"(x));
    float l = x - __uint_as_float(h);
    uint32_t lb;
    asm("cvt.rna.tf32.f32 %0, %1;" : "=r"(lb) : "f"(l));
    hi = h; lo = lb;
}

// ===========================================================================
// 3xTF32 tensor-core NT GEMM:
//   C[m,n] = sum_k A[m,k]*Bw[n,k] + bias[n] (+relu)(+res)
// A: [M,Kd] row-major, Bw: [N,Kd] row-major (both K-contiguous).
// CTA tile 128x128, 8 warps (4 m x 2 n), warp tile 32x64, BK=32,
// cp.async double buffer. SMEM row stride 36 floats -> conflict-free frags.
// Each accumulate does hi*hi + hi*lo + lo*hi  (~fp32 accuracy).
// ===========================================================================
#define GM_STAGE_FLOATS 9216   // 128*36 (A) + 128*36 (B)
#define GM_SMEM_BYTES  (2 * GM_STAGE_FLOATS * 4)

__global__ __launch_bounds__(256, 2)
void gemm_tc_kernel(const float* __restrict__ A, const float* __restrict__ Bw,
                    const float* __restrict__ bias, const float* __restrict__ res,
                    float* __restrict__ C, int M, int N, int Kd, int relu)
{
    extern __shared__ float sm[];
    const int tid  = threadIdx.x;
    const int wid  = tid >> 5;
    const int lane = tid & 31;
    const int grp  = lane >> 2;   // 0..7
    const int qr   = lane & 3;    // 0..3
    const int bm   = blockIdx.y << 7;
    const int bn   = blockIdx.x << 7;
    const uint32_t sbase = smem_u32(sm);

    // staging slots: 1024 float4 per operand tile / 256 threads = 4 each
    uint32_t soff[4];
    const float* gA[4];
    const float* gB[4];
#pragma unroll
    for (int i = 0; i < 4; i++) {
        int idx = i * 256 + tid;
        int row = idx >> 3;     // 0..127
        int c4  = idx & 7;      // float4 within 32-float K-slab
        soff[i] = (uint32_t)(row * 36 + c4 * 4) * 4u;
        gA[i] = A  + (size_t)(bm + row) * Kd + (c4 << 2);
        gB[i] = Bw + (size_t)(bn + row) * Kd + (c4 << 2);
    }

    const int nc = Kd >> 5;  // K-chunks of 32

    // prologue: stage 0
#pragma unroll
    for (int i = 0; i < 4; i++) {
        CP_ASYNC16(sbase + soff[i], gA[i]);
        CP_ASYNC16(sbase + 4608u * 4u + soff[i], gB[i]);
    }
    CP_COMMIT();

    const int wm = (wid & 3) << 5;   // warp m offset: 0/32/64/96
    const int wn = (wid >> 2) << 6;  // warp n offset: 0/64

    float acc[2][8][4];
#pragma unroll
    for (int mt = 0; mt < 2; mt++)
#pragma unroll
        for (int nt = 0; nt < 8; nt++)
#pragma unroll
            for (int r = 0; r < 4; r++) acc[mt][nt][r] = 0.f;

    for (int c = 0; c < nc; c++) {
        if (c + 1 < nc) {
            const int k1 = (c + 1) << 5;
            const uint32_t st = sbase + (uint32_t)((c + 1) & 1) * (GM_STAGE_FLOATS * 4u);
#pragma unroll
            for (int i = 0; i < 4; i++) {
                CP_ASYNC16(st + soff[i], gA[i] + k1);
                CP_ASYNC16(st + 4608u * 4u + soff[i], gB[i] + k1);
            }
            CP_COMMIT();
            CP_WAIT1();
        } else {
            CP_WAIT0();
        }
        __syncthreads();

        const float* Asb = sm + (c & 1) * GM_STAGE_FLOATS;
        const float* Bsb = Asb + 4608;
#pragma unroll
        for (int ks = 0; ks < 4; ks++) {
            const float* Ac = Asb + ks * 8 + qr;
            const float* Bc = Bsb + ks * 8 + qr;
            uint32_t ah[2][4], al[2][4];
#pragma unroll
            for (int mt = 0; mt < 2; mt++) {
                int r0 = wm + mt * 16 + grp;
                split_tf32(Ac[r0 * 36],           ah[mt][0], al[mt][0]);
                split_tf32(Ac[(r0 + 8) * 36],     ah[mt][1], al[mt][1]);
                split_tf32(Ac[r0 * 36 + 4],       ah[mt][2], al[mt][2]);
                split_tf32(Ac[(r0 + 8) * 36 + 4], ah[mt][3], al[mt][3]);
            }
            uint32_t bh[8][2], bl[8][2];
#pragma unroll
            for (int nt = 0; nt < 8; nt++) {
                int rn = wn + nt * 8 + grp;
                split_tf32(Bc[rn * 36],     bh[nt][0], bl[nt][0]);
                split_tf32(Bc[rn * 36 + 4], bh[nt][1], bl[nt][1]);
            }
#pragma unroll
            for (int mt = 0; mt < 2; mt++)
#pragma unroll
                for (int nt = 0; nt < 8; nt++) {
                    MMA_TF32(acc[mt][nt], ah[mt][0], ah[mt][1], ah[mt][2], ah[mt][3],
                             bh[nt][0], bh[nt][1]);
                    MMA_TF32(acc[mt][nt], al[mt][0], al[mt][1], al[mt][2], al[mt][3],
                             bh[nt][0], bh[nt][1]);
                    MMA_TF32(acc[mt][nt], ah[mt][0], ah[mt][1], ah[mt][2], ah[mt][3],
                             bl[nt][0], bl[nt][1]);
                }
        }
        __syncthreads();
    }

    // epilogue: c0,c1 -> (r0, col..col+1), c2,c3 -> (r0+8, col..col+1)
#pragma unroll
    for (int mt = 0; mt < 2; mt++) {
        const int r0 = bm + wm + mt * 16 + grp;
#pragma unroll
        for (int nt = 0; nt < 8; nt++) {
            const int col = bn + wn + nt * 8 + (qr << 1);
            float2 bb = *(const float2*)(bias + col);
            float v0 = acc[mt][nt][0] + bb.x;
            float v1 = acc[mt][nt][1] + bb.y;
            float v2 = acc[mt][nt][2] + bb.x;
            float v3 = acc[mt][nt][3] + bb.y;
            if (relu) {
                v0 = fmaxf(v0, 0.f); v1 = fmaxf(v1, 0.f);
                v2 = fmaxf(v2, 0.f); v3 = fmaxf(v3, 0.f);
            }
            if (res) {
                float2 ra = *(const float2*)(res + (size_t)r0 * N + col);
                float2 rb = *(const float2*)(res + (size_t)(r0 + 8) * N + col);
                v0 += ra.x; v1 += ra.y; v2 += rb.x; v3 += rb.y;
            }
            *(float2*)(C + (size_t)r0 * N + col)       = make_float2(v0, v1);
            *(float2*)(C + (size_t)(r0 + 8) * N + col) = make_float2(v2, v3);
        }
    }
}

// ---------------------------------------------------------------------------
// Graph bias precompute
// ---------------------------------------------------------------------------
__global__ __launch_bounds__(256) void bias_kernel(
    const float* __restrict__ E, const float* __restrict__ lap,
    const float* __restrict__ alphap, const float* __restrict__ betap,
    float* __restrict__ gb)
{
    __shared__ __align__(16) float ei[64];
    __shared__ float reda[8];
    __shared__ float redb[8];
    int i = blockIdx.x;
    int tid = threadIdx.x;
    if (tid < 16) ((float4*)ei)[tid] = ((const float4*)(E + (size_t)i * 64))[tid];
    __syncthreads();

    int j0 = tid, j1 = tid + 256;
    const float* e0 = E + (size_t)j0 * 64;
    const float* e1 = E + (size_t)j1 * 64;
    float r0 = 0.f, r1 = 0.f;
#pragma unroll
    for (int e = 0; e < 64; e += 4) {
        float4 a = *(const float4*)(ei + e);
        float4 u = *(const float4*)(e0 + e);
        float4 w = *(const float4*)(e1 + e);
        r0 += a.x * u.x + a.y * u.y + a.z * u.z + a.w * u.w;
        r1 += a.x * w.x + a.y * w.y + a.z * w.z + a.w * w.w;
    }
    r0 = fmaxf(r0, 0.f);
    r1 = fmaxf(r1, 0.f);

    float mx = fmaxf(r0, r1);
#pragma unroll
    for (int o = 16; o; o >>= 1) mx = fmaxf(mx, __shfl_xor_sync(0xffffffffu, mx, o));
    if ((tid & 31) == 0) reda[tid >> 5] = mx;
    __syncthreads();
    mx = fmaxf(fmaxf(fmaxf(reda[0], reda[1]), fmaxf(reda[2], reda[3])),
               fmaxf(fmaxf(reda[4], reda[5]), fmaxf(reda[6], reda[7])));

    float ex0 = __expf(r0 - mx), ex1 = __expf(r1 - mx);
    float s = ex0 + ex1;
#pragma unroll
    for (int o = 16; o; o >>= 1) s += __shfl_xor_sync(0xffffffffu, s, o);
    if ((tid & 31) == 0) redb[tid >> 5] = s;
    __syncthreads();
    s = redb[0] + redb[1] + redb[2] + redb[3] + redb[4] + redb[5] + redb[6] + redb[7];
    float inv = 1.0f / s;

    float alpha = *alphap, beta = *betap;
    float lp0 = lap[(size_t)i * 512 + j0];
    float lp1 = lap[(size_t)i * 512 + j1];
    float m0 = (lp0 != 0.f) ? 0.f : -1e9f;
    float m1 = (lp1 != 0.f) ? 0.f : -1e9f;
    gb[(size_t)i * 512 + j0] = alpha * ex0 * inv + beta * lp0 + m0;
    gb[(size_t)i * 512 + j1] = alpha * ex1 * inv + beta * lp1 + m1;
}

// ---------------------------------------------------------------------------
// LayerNorm over D=512. One warp per row.
// ---------------------------------------------------------------------------
__global__ __launch_bounds__(256) void ln_kernel(
    const float* __restrict__ X, const float* __restrict__ g,
    const float* __restrict__ b, float* __restrict__ Y, int rows)
{
    int gw = (blockIdx.x * 256 + threadIdx.x) >> 5;
    if (gw >= rows) return;
    int lane = threadIdx.x & 31;
    const float* xr = X + (size_t)gw * 512;
    float* yr = Y + (size_t)gw * 512;
    float4 v[4];
    float s = 0.f, ss = 0.f;
#pragma unroll
    for (int w = 0; w < 4; w++) {
        v[w] = *(const float4*)(xr + w * 128 + lane * 4);
        s += v[w].x + v[w].y + v[w].z + v[w].w;
        ss += v[w].x * v[w].x + v[w].y * v[w].y + v[w].z * v[w].z + v[w].w * v[w].w;
    }
#pragma unroll
    for (int o = 16; o; o >>= 1) {
        s += __shfl_xor_sync(0xffffffffu, s, o);
        ss += __shfl_xor_sync(0xffffffffu, ss, o);
    }
    float mean = s * (1.0f / 512.0f);
    float var = ss * (1.0f / 512.0f) - mean * mean;
    float rstd = rsqrtf(var + 1e-5f);
#pragma unroll
    for (int w = 0; w < 4; w++) {
        int c = w * 128 + lane * 4;
        float4 gg = *(const float4*)(g + c);
        float4 bb = *(const float4*)(b + c);
        float4 o;
        o.x = (v[w].x - mean) * rstd * gg.x + bb.x;
        o.y = (v[w].y - mean) * rstd * gg.y + bb.y;
        o.z = (v[w].z - mean) * rstd * gg.z + bb.z;
        o.w = (v[w].w - mean) * rstd * gg.w + bb.w;
        *(float4*)(yr + c) = o;
    }
}

// ---------------------------------------------------------------------------
// Attention scores: logits[h][i][j] = (Q_h[i].K_h[j]) / 8 + gbias[i][j]
// ---------------------------------------------------------------------------
__global__ __launch_bounds__(256) void attn_scores_kernel(
    const float* __restrict__ q, const float* __restrict__ kmat,
    const float* __restrict__ gb, float* __restrict__ logits)
{
    __shared__ __align__(16) float Qs[64][64];
    __shared__ __align__(16) float Ks[64][64];
    int h = blockIdx.z;
    int bt = h >> 3;
    int kh = h & 7;
    int i0 = blockIdx.y << 6;
    int j0 = blockIdx.x << 6;
    int tid = threadIdx.x;

    int lr = tid >> 2;
    int lc = (tid & 3) << 4;
    const float* qg = q + ((size_t)(bt * 512 + i0 + lr)) * 512 + kh * 64 + lc;
    const float* kg = kmat + ((size_t)(bt * 512 + j0 + lr)) * 512 + kh * 64 + lc;
#pragma unroll
    for (int c = 0; c < 16; c += 4) {
        float4 a = *(const float4*)(qg + c);
        Qs[lc + c + 0][lr] = a.x;
        Qs[lc + c + 1][lr] = a.y;
        Qs[lc + c + 2][lr] = a.z;
        Qs[lc + c + 3][lr] = a.w;
        float4 b = *(const float4*)(kg + c);
        Ks[lc + c + 0][lr] = b.x;
        Ks[lc + c + 1][lr] = b.y;
        Ks[lc + c + 2][lr] = b.z;
        Ks[lc + c + 3][lr] = b.w;
    }
    __syncthreads();

    int ty = tid >> 4, tx = tid & 15;
    float acc[4][4];
#pragma unroll
    for (int i = 0; i < 4; i++)
#pragma unroll
        for (int j = 0; j < 4; j++) acc[i][j] = 0.f;

#pragma unroll
    for (int e = 0; e < 64; e++) {
        float4 a4 = *(const float4*)&Qs[e][ty << 2];
        float4 b4 = *(const float4*)&Ks[e][tx << 2];
        float ar[4] = {a4.x, a4.y, a4.z, a4.w};
        float br[4] = {b4.x, b4.y, b4.z, b4.w};
#pragma unroll
        for (int ii = 0; ii < 4; ii++)
#pragma unroll
            for (int jj = 0; jj < 4; jj++)
                acc[ii][jj] = fmaf(ar[ii], br[jj], acc[ii][jj]);
    }

#pragma unroll
    for (int ii = 0; ii < 4; ii++) {
        int gi = i0 + (ty << 2) + ii;
#pragma unroll
        for (int jj = 0; jj < 4; jj++) {
            int gj = j0 + (tx << 2) + jj;
            logits[((size_t)h * 512 + gi) * 512 + gj] =
                acc[ii][jj] * 0.125f + gb[(size_t)gi * 512 + gj];
        }
    }
}

// ---------------------------------------------------------------------------
// Row softmax, in place
// ---------------------------------------------------------------------------
__global__ __launch_bounds__(256) void softmax_kernel(float* __restrict__ L, int rows)
{
    int r = (blockIdx.x * 256 + threadIdx.x) >> 5;
    if (r >= rows) return;
    int lane = threadIdx.x & 31;
    float* row = L + (size_t)r * 512;
    float4 v[4];
    float mx = -3.0e38f;
#pragma unroll
    for (int w = 0; w < 4; w++) {
        v[w] = *(const float4*)(row + w * 128 + lane * 4);
        mx = fmaxf(mx, fmaxf(fmaxf(v[w].x, v[w].y), fmaxf(v[w].z, v[w].w)));
    }
#pragma unroll
    for (int o = 16; o; o >>= 1) mx = fmaxf(mx, __shfl_xor_sync(0xffffffffu, mx, o));
    float s = 0.f;
#pragma unroll
    for (int w = 0; w < 4; w++) {
        v[w].x = __expf(v[w].x - mx);
        v[w].y = __expf(v[w].y - mx);
        v[w].z = __expf(v[w].z - mx);
        v[w].w = __expf(v[w].w - mx);
        s += v[w].x + v[w].y + v[w].z + v[w].w;
    }
#pragma unroll
    for (int o = 16; o; o >>= 1) s += __shfl_xor_sync(0xffffffffu, s, o);
    float inv = 1.0f / s;
#pragma unroll
    for (int w = 0; w < 4; w++) {
        v[w].x *= inv; v[w].y *= inv; v[w].z *= inv; v[w].w *= inv;
        *(float4*)(row + w * 128 + lane * 4) = v[w];
    }
}

// ---------------------------------------------------------------------------
// attn @ V
// ---------------------------------------------------------------------------
__global__ __launch_bounds__(256) void attn_av_kernel(
    const float* __restrict__ attn, const float* __restrict__ v,
    float* __restrict__ out)
{
    __shared__ __align__(16) float Ast[32][64];
    __shared__ __align__(16) float Bs[32][64];
    int h = blockIdx.y;
    int bt = h >> 3;
    int kh = h & 7;
    int i0 = blockIdx.x << 6;
    int tid = threadIdx.x;

    int am = tid >> 2;
    int ak = (tid & 3) << 3;
    int bk = tid >> 3;
    int bn = (tid & 7) << 3;
    const float* Ag = attn + ((size_t)h * 512 + i0 + am) * 512 + ak;
    const float* Bgb = v + (size_t)(bt * 512) * 512 + kh * 64 + bn;

    int ty = tid >> 4, tx = tid & 15;
    float acc[4][4];
#pragma unroll
    for (int i = 0; i < 4; i++)
#pragma unroll
        for (int j = 0; j < 4; j++) acc[i][j] = 0.f;

    for (int k0 = 0; k0 < 512; k0 += 32) {
        float4 a0 = *(const float4*)(Ag + k0);
        float4 a1 = *(const float4*)(Ag + k0 + 4);
        Ast[ak + 0][am] = a0.x; Ast[ak + 1][am] = a0.y;
        Ast[ak + 2][am] = a0.z; Ast[ak + 3][am] = a0.w;
        Ast[ak + 4][am] = a1.x; Ast[ak + 5][am] = a1.y;
        Ast[ak + 6][am] = a1.z; Ast[ak + 7][am] = a1.w;
        const float* Bg = Bgb + (size_t)(k0 + bk) * 512;
        float4 b0 = *(const float4*)(Bg);
        float4 b1 = *(const float4*)(Bg + 4);
        *(float4*)&Bs[bk][bn] = b0;
        *(float4*)&Bs[bk][bn + 4] = b1;
        __syncthreads();
#pragma unroll
        for (int kk = 0; kk < 32; kk++) {
            float4 a4 = *(const float4*)&Ast[kk][ty << 2];
            float4 b4 = *(const float4*)&Bs[kk][tx << 2];
            float ar[4] = {a4.x, a4.y, a4.z, a4.w};
            float br[4] = {b4.x, b4.y, b4.z, b4.w};
#pragma unroll
            for (int ii = 0; ii < 4; ii++)
#pragma unroll
                for (int jj = 0; jj < 4; jj++)
                    acc[ii][jj] = fmaf(ar[ii], br[jj], acc[ii][jj]);
        }
        __syncthreads();
    }

#pragma unroll
    for (int ii = 0; ii < 4; ii++) {
        size_t row = (size_t)(bt * 512 + i0 + (ty << 2) + ii);
        float* Op = out + row * 512 + kh * 64 + (tx << 2);
        float4 o = make_float4(acc[ii][0], acc[ii][1], acc[ii][2], acc[ii][3]);
        *(float4*)Op = o;
    }
}

// ---------------------------------------------------------------------------
// Host launcher
// ---------------------------------------------------------------------------
extern "C" void kernel_launch(void* const* d_in, const int* in_sizes, int n_in,
                              void* d_out, int out_size)
{
    const float* x    = (const float*)d_in[0];
    const float* lap  = (const float*)d_in[1];
    const float* emb  = (const float*)d_in[2];
    const float* Wq   = (const float*)d_in[3];
    const float* bq   = (const float*)d_in[4];
    const float* Wk   = (const float*)d_in[5];
    const float* bk   = (const float*)d_in[6];
    const float* Wv   = (const float*)d_in[7];
    const float* bv   = (const float*)d_in[8];
    const float* ln1g = (const float*)d_in[9];
    const float* ln1b = (const float*)d_in[10];
    const float* ln2g = (const float*)d_in[11];
    const float* ln2b = (const float*)d_in[12];
    const float* alpha = (const float*)d_in[13];
    const float* beta  = (const float*)d_in[14];
    const float* Wo   = (const float*)d_in[15];
    const float* bo   = (const float*)d_in[16];
    const float* W1   = (const float*)d_in[17];
    const float* b1   = (const float*)d_in[18];
    const float* W2   = (const float*)d_in[19];
    const float* b2   = (const float*)d_in[20];
    float* out = (float*)d_out;

    float* base = nullptr;
    cudaGetSymbolAddress((void**)&base, g_scratch);
    float* xn     = base + OFF_XN;
    float* q      = base + OFF_Q;
    float* kbuf   = base + OFF_K;
    float* vbuf   = base + OFF_V;
    float* ao     = base + OFF_AO;
    float* x1     = base + OFF_X1;
    float* hin    = base + OFF_HIN;
    float* hbuf   = base + OFF_H;
    float* logits = base + OFF_LOG;
    float* gb     = base + OFF_GB;

    static bool attr_done = false;
    if (!attr_done) {
        cudaFuncSetAttribute(gemm_tc_kernel,
                             cudaFuncAttributeMaxDynamicSharedMemorySize, GM_SMEM_BYTES);
        attr_done = true;
    }

    // 1. graph bias
    bias_kernel<<<512, 256>>>(emb, lap, alpha, beta, gb);

    // 2. LN1
    ln_kernel<<<R_ROWS / 8, 256>>>(x, ln1g, ln1b, xn, R_ROWS);

    // 3. QKV projections (3xTF32 mma.sync tensor cores)
    dim3 gq(D_DIM / 128, R_ROWS / 128);
    gemm_tc_kernel<<<gq, 256, GM_SMEM_BYTES>>>(xn, Wq, bq, nullptr, q,    R_ROWS, D_DIM, D_DIM, 0);
    gemm_tc_kernel<<<gq, 256, GM_SMEM_BYTES>>>(xn, Wk, bk, nullptr, kbuf, R_ROWS, D_DIM, D_DIM, 0);
    gemm_tc_kernel<<<gq, 256, GM_SMEM_BYTES>>>(xn, Wv, bv, nullptr, vbuf, R_ROWS, D_DIM, D_DIM, 0);

    // 4. scores + bias
    attn_scores_kernel<<<dim3(8, 8, H_HEADS), 256>>>(q, kbuf, gb, logits);

    // 5. softmax
    softmax_kernel<<<(H_HEADS * N_NODES) / 8, 256>>>(logits, H_HEADS * N_NODES);

    // 6. attn @ V
    attn_av_kernel<<<dim3(8, H_HEADS), 256>>>(logits, vbuf, ao);

    // 7. output projection + residual
    gemm_tc_kernel<<<gq, 256, GM_SMEM_BYTES>>>(ao, Wo, bo, x, x1, R_ROWS, D_DIM, D_DIM, 0);

    // 8. LN2
    ln_kernel<<<R_ROWS / 8, 256>>>(x1, ln2g, ln2b, hin, R_ROWS);

    // 9. FF up (relu)
    gemm_tc_kernel<<<dim3(DFF / 128, R_ROWS / 128), 256, GM_SMEM_BYTES>>>(
        hin, W1, b1, nullptr, hbuf, R_ROWS, DFF, D_DIM, 1);

    // 10. FF down + residual
    gemm_tc_kernel<<<dim3(D_DIM / 128, R_ROWS / 128), 256, GM_SMEM_BYTES>>>(
        hbuf, W2, b2, x1, out, R_ROWS, D_DIM, DFF, 0);
}

// round 5
// speedup vs baseline: 1.5223x; 1.1085x over previous
#include <cuda_runtime.h>
#include <cstdint>

// ---------------------------------------------------------------------------
// Problem constants
//   x: [B=4, T=8, N=512, D=512]  -> R = B*T*N = 16384 rows of D=512
//   heads K=8, dh=64, H = B*T*K = 256, DFF = 2048
// ---------------------------------------------------------------------------
#define R_ROWS 16384
#define N_NODES 512
#define D_DIM 512
#define H_HEADS 256
#define DFF 2048

__device__ float g_scratch[159645696];

#define OFF_XN   0ull
#define OFF_Q    8388608ull
#define OFF_K    16777216ull
#define OFF_V    25165824ull
#define OFF_AO   33554432ull
#define OFF_X1   41943040ull
#define OFF_HIN  50331648ull
#define OFF_H    58720256ull
#define OFF_LOG  92274688ull
#define OFF_GB   159383552ull

// ===========================================================================
// Helpers: cp.async + mma.sync tf32 (compute_103-safe PTX, no 'a' features)
// ===========================================================================
__device__ __forceinline__ uint32_t smem_u32(const void* p) {
    uint32_t a;
    asm("{ .reg .u64 t; cvta.to.shared.u64 t, %1; cvt.u32.u64 %0, t; }"
        : "=r"(a) : "l"(p));
    return a;
}

#define CP_ASYNC16(dst, src) \
    asm volatile("cp.async.cg.shared.global [%0], [%1], 16;" :: "r"(dst), "l"(src))
#define CP_COMMIT() asm volatile("cp.async.commit_group;" ::: "memory")
#define CP_WAIT1()  asm volatile("cp.async.wait_group 1;" ::: "memory")
#define CP_WAIT0()  asm volatile("cp.async.wait_group 0;" ::: "memory")

// D(f32) += A(tf32) * B(tf32), m16n8k8, A row-major, B col-major
#define MMA_TF32(d, a0, a1, a2, a3, b0, b1) \
    asm volatile("mma.sync.aligned.m16n8k8.row.col.f32.tf32.tf32.f32 " \
        "{%0,%1,%2,%3}, {%4,%5,%6,%7}, {%8,%9}, {%0,%1,%2,%3};" \
        : "+f"((d)[0]), "+f"((d)[1]), "+f"((d)[2]), "+f"((d)[3]) \
        : "r"(a0), "r"(a1), "r"(a2), "r"(a3), "r"(b0), "r"(b1))

// 3xTF32 split: hi = tf32_rna(x), lo = tf32_rna(x - hi)
__device__ __forceinline__ void split_tf32(float x, uint32_t& hi, uint32_t& lo) {
    uint32_t h;
    asm("cvt.rna.tf32.f32 %0, %1;" : "=r"(h) : "f"(x));
    float l = x - __uint_as_float(h);
    uint32_t lb;
    asm("cvt.rna.tf32.f32 %0, %1;" : "=r"(lb) : "f"(l));
    hi = h; lo = lb;
}

// ===========================================================================
// 3xTF32 tensor-core NT GEMM (dense projections / MLP)
// ===========================================================================
#define GM_STAGE_FLOATS 9216   // 128*36 (A) + 128*36 (B)
#define GM_SMEM_BYTES  (2 * GM_STAGE_FLOATS * 4)

__global__ __launch_bounds__(256, 2)
void gemm_tc_kernel(const float* __restrict__ A, const float* __restrict__ Bw,
                    const float* __restrict__ bias, const float* __restrict__ res,
                    float* __restrict__ C, int M, int N, int Kd, int relu)
{
    extern __shared__ float sm[];
    const int tid  = threadIdx.x;
    const int wid  = tid >> 5;
    const int lane = tid & 31;
    const int grp  = lane >> 2;
    const int qr   = lane & 3;
    const int bm   = blockIdx.y << 7;
    const int bn   = blockIdx.x << 7;
    const uint32_t sbase = smem_u32(sm);

    uint32_t soff[4];
    const float* gA[4];
    const float* gB[4];
#pragma unroll
    for (int i = 0; i < 4; i++) {
        int idx = i * 256 + tid;
        int row = idx >> 3;
        int c4  = idx & 7;
        soff[i] = (uint32_t)(row * 36 + c4 * 4) * 4u;
        gA[i] = A  + (size_t)(bm + row) * Kd + (c4 << 2);
        gB[i] = Bw + (size_t)(bn + row) * Kd + (c4 << 2);
    }

    const int nc = Kd >> 5;

#pragma unroll
    for (int i = 0; i < 4; i++) {
        CP_ASYNC16(sbase + soff[i], gA[i]);
        CP_ASYNC16(sbase + 4608u * 4u + soff[i], gB[i]);
    }
    CP_COMMIT();

    const int wm = (wid & 3) << 5;
    const int wn = (wid >> 2) << 6;

    float acc[2][8][4];
#pragma unroll
    for (int mt = 0; mt < 2; mt++)
#pragma unroll
        for (int nt = 0; nt < 8; nt++)
#pragma unroll
            for (int r = 0; r < 4; r++) acc[mt][nt][r] = 0.f;

    for (int c = 0; c < nc; c++) {
        if (c + 1 < nc) {
            const int k1 = (c + 1) << 5;
            const uint32_t st = sbase + (uint32_t)((c + 1) & 1) * (GM_STAGE_FLOATS * 4u);
#pragma unroll
            for (int i = 0; i < 4; i++) {
                CP_ASYNC16(st + soff[i], gA[i] + k1);
                CP_ASYNC16(st + 4608u * 4u + soff[i], gB[i] + k1);
            }
            CP_COMMIT();
            CP_WAIT1();
        } else {
            CP_WAIT0();
        }
        __syncthreads();

        const float* Asb = sm + (c & 1) * GM_STAGE_FLOATS;
        const float* Bsb = Asb + 4608;
#pragma unroll
        for (int ks = 0; ks < 4; ks++) {
            const float* Ac = Asb + ks * 8 + qr;
            const float* Bc = Bsb + ks * 8 + qr;
            uint32_t ah[2][4], al[2][4];
#pragma unroll
            for (int mt = 0; mt < 2; mt++) {
                int r0 = wm + mt * 16 + grp;
                split_tf32(Ac[r0 * 36],           ah[mt][0], al[mt][0]);
                split_tf32(Ac[(r0 + 8) * 36],     ah[mt][1], al[mt][1]);
                split_tf32(Ac[r0 * 36 + 4],       ah[mt][2], al[mt][2]);
                split_tf32(Ac[(r0 + 8) * 36 + 4], ah[mt][3], al[mt][3]);
            }
            uint32_t bh[8][2], bl[8][2];
#pragma unroll
            for (int nt = 0; nt < 8; nt++) {
                int rn = wn + nt * 8 + grp;
                split_tf32(Bc[rn * 36],     bh[nt][0], bl[nt][0]);
                split_tf32(Bc[rn * 36 + 4], bh[nt][1], bl[nt][1]);
            }
#pragma unroll
            for (int mt = 0; mt < 2; mt++)
#pragma unroll
                for (int nt = 0; nt < 8; nt++) {
                    MMA_TF32(acc[mt][nt], ah[mt][0], ah[mt][1], ah[mt][2], ah[mt][3],
                             bh[nt][0], bh[nt][1]);
                    MMA_TF32(acc[mt][nt], al[mt][0], al[mt][1], al[mt][2], al[mt][3],
                             bh[nt][0], bh[nt][1]);
                    MMA_TF32(acc[mt][nt], ah[mt][0], ah[mt][1], ah[mt][2], ah[mt][3],
                             bl[nt][0], bl[nt][1]);
                }
        }
        __syncthreads();
    }

#pragma unroll
    for (int mt = 0; mt < 2; mt++) {
        const int r0 = bm + wm + mt * 16 + grp;
#pragma unroll
        for (int nt = 0; nt < 8; nt++) {
            const int col = bn + wn + nt * 8 + (qr << 1);
            float2 bb = *(const float2*)(bias + col);
            float v0 = acc[mt][nt][0] + bb.x;
            float v1 = acc[mt][nt][1] + bb.y;
            float v2 = acc[mt][nt][2] + bb.x;
            float v3 = acc[mt][nt][3] + bb.y;
            if (relu) {
                v0 = fmaxf(v0, 0.f); v1 = fmaxf(v1, 0.f);
                v2 = fmaxf(v2, 0.f); v3 = fmaxf(v3, 0.f);
            }
            if (res) {
                float2 ra = *(const float2*)(res + (size_t)r0 * N + col);
                float2 rb = *(const float2*)(res + (size_t)(r0 + 8) * N + col);
                v0 += ra.x; v1 += ra.y; v2 += rb.x; v3 += rb.y;
            }
            *(float2*)(C + (size_t)r0 * N + col)       = make_float2(v0, v1);
            *(float2*)(C + (size_t)(r0 + 8) * N + col) = make_float2(v2, v3);
        }
    }
}

// ===========================================================================
// 3xTF32 attention scores: logits[h][i][j] = (Q_h[i].K_h[j])*0.125 + gb[i][j]
// Per (j-tile, i-tile, head): 128x128 tile, K=64 (2 chunks of 32), cp.async.
// Q/K layout: [B*T*N, 512] with head slice at col kh*64 (K-contiguous -> NT).
// ===========================================================================
__global__ __launch_bounds__(256, 2)
void tc_scores_kernel(const float* __restrict__ q, const float* __restrict__ kmat,
                      const float* __restrict__ gb, float* __restrict__ logits)
{
    extern __shared__ float sm[];
    const int tid  = threadIdx.x;
    const int wid  = tid >> 5;
    const int lane = tid & 31;
    const int grp  = lane >> 2;
    const int qr   = lane & 3;
    const int h  = blockIdx.z;
    const int bt = h >> 3;
    const int kh = h & 7;
    const int bm = blockIdx.y << 7;   // i tile
    const int bn = blockIdx.x << 7;   // j tile
    const uint32_t sbase = smem_u32(sm);

    uint32_t soff[4];
    const float* gA[4];
    const float* gB[4];
#pragma unroll
    for (int i = 0; i < 4; i++) {
        int idx = i * 256 + tid;
        int row = idx >> 3;
        int c4  = idx & 7;
        soff[i] = (uint32_t)(row * 36 + c4 * 4) * 4u;
        gA[i] = q    + (size_t)(bt * 512 + bm + row) * 512 + kh * 64 + (c4 << 2);
        gB[i] = kmat + (size_t)(bt * 512 + bn + row) * 512 + kh * 64 + (c4 << 2);
    }

#pragma unroll
    for (int i = 0; i < 4; i++) {
        CP_ASYNC16(sbase + soff[i], gA[i]);
        CP_ASYNC16(sbase + 4608u * 4u + soff[i], gB[i]);
    }
    CP_COMMIT();

    const int wm = (wid & 3) << 5;
    const int wn = (wid >> 2) << 6;

    float acc[2][8][4];
#pragma unroll
    for (int mt = 0; mt < 2; mt++)
#pragma unroll
        for (int nt = 0; nt < 8; nt++)
#pragma unroll
            for (int r = 0; r < 4; r++) acc[mt][nt][r] = 0.f;

#pragma unroll
    for (int c = 0; c < 2; c++) {
        if (c == 0) {
            const uint32_t st = sbase + (GM_STAGE_FLOATS * 4u);
#pragma unroll
            for (int i = 0; i < 4; i++) {
                CP_ASYNC16(st + soff[i], gA[i] + 32);
                CP_ASYNC16(st + 4608u * 4u + soff[i], gB[i] + 32);
            }
            CP_COMMIT();
            CP_WAIT1();
        } else {
            CP_WAIT0();
        }
        __syncthreads();

        const float* Asb = sm + c * GM_STAGE_FLOATS;
        const float* Bsb = Asb + 4608;
#pragma unroll
        for (int ks = 0; ks < 4; ks++) {
            const float* Ac = Asb + ks * 8 + qr;
            const float* Bc = Bsb + ks * 8 + qr;
            uint32_t ah[2][4], al[2][4];
#pragma unroll
            for (int mt = 0; mt < 2; mt++) {
                int r0 = wm + mt * 16 + grp;
                split_tf32(Ac[r0 * 36],           ah[mt][0], al[mt][0]);
                split_tf32(Ac[(r0 + 8) * 36],     ah[mt][1], al[mt][1]);
                split_tf32(Ac[r0 * 36 + 4],       ah[mt][2], al[mt][2]);
                split_tf32(Ac[(r0 + 8) * 36 + 4], ah[mt][3], al[mt][3]);
            }
            uint32_t bh[8][2], bl[8][2];
#pragma unroll
            for (int nt = 0; nt < 8; nt++) {
                int rn = wn + nt * 8 + grp;
                split_tf32(Bc[rn * 36],     bh[nt][0], bl[nt][0]);
                split_tf32(Bc[rn * 36 + 4], bh[nt][1], bl[nt][1]);
            }
#pragma unroll
            for (int mt = 0; mt < 2; mt++)
#pragma unroll
                for (int nt = 0; nt < 8; nt++) {
                    MMA_TF32(acc[mt][nt], ah[mt][0], ah[mt][1], ah[mt][2], ah[mt][3],
                             bh[nt][0], bh[nt][1]);
                    MMA_TF32(acc[mt][nt], al[mt][0], al[mt][1], al[mt][2], al[mt][3],
                             bh[nt][0], bh[nt][1]);
                    MMA_TF32(acc[mt][nt], ah[mt][0], ah[mt][1], ah[mt][2], ah[mt][3],
                             bl[nt][0], bl[nt][1]);
                }
        }
        __syncthreads();
    }

    // epilogue: logits = acc * 0.125 + gbias
    float* Lh = logits + (size_t)h * 512 * 512;
#pragma unroll
    for (int mt = 0; mt < 2; mt++) {
        const int gi = bm + wm + mt * 16 + grp;
#pragma unroll
        for (int nt = 0; nt < 8; nt++) {
            const int gj = bn + wn + nt * 8 + (qr << 1);
            float2 g0 = *(const float2*)(gb + (size_t)gi * 512 + gj);
            float2 g1 = *(const float2*)(gb + (size_t)(gi + 8) * 512 + gj);
            float v0 = fmaf(acc[mt][nt][0], 0.125f, g0.x);
            float v1 = fmaf(acc[mt][nt][1], 0.125f, g0.y);
            float v2 = fmaf(acc[mt][nt][2], 0.125f, g1.x);
            float v3 = fmaf(acc[mt][nt][3], 0.125f, g1.y);
            *(float2*)(Lh + (size_t)gi * 512 + gj)       = make_float2(v0, v1);
            *(float2*)(Lh + (size_t)(gi + 8) * 512 + gj) = make_float2(v2, v3);
        }
    }
}

// ===========================================================================
// 3xTF32 AV: out_h = P_h @ V_h.  Per (i-tile, head): BM=128, BN=64, K=512.
// A = P (row-major, K-contiguous). B = V^T staged into SMEM [n][k] (stride 36).
// Register-pipelined direct loads, double-buffered SMEM, 1 sync per chunk.
// Warp tile 32x32 (mt=2, nt=4).
// ===========================================================================
#define AV_STAGE_FLOATS 6912   // A 128*36 + B 64*36
#define AV_SMEM_BYTES  (2 * AV_STAGE_FLOATS * 4)

__global__ __launch_bounds__(256, 2)
void tc_av_kernel(const float* __restrict__ attn, const float* __restrict__ v,
                  float* __restrict__ out)
{
    extern __shared__ float sm[];
    const int tid  = threadIdx.x;
    const int wid  = tid >> 5;
    const int lane = tid & 31;
    const int grp  = lane >> 2;
    const int qr   = lane & 3;
    const int h  = blockIdx.y;
    const int bt = h >> 3;
    const int kh = h & 7;
    const int bm = blockIdx.x << 7;

    // A slots: 4 float4/thread (128 rows x 32 k)
    int arow[4], ac4[4];
#pragma unroll
    for (int i = 0; i < 4; i++) {
        int idx = i * 256 + tid;
        arow[i] = idx >> 3;
        ac4[i]  = (idx & 7) << 2;
    }
    // B slots: 2 float4/thread (32 k x 64 n), transposed store
    int bk_[2], bn4[2];
#pragma unroll
    for (int i = 0; i < 2; i++) {
        int idx = i * 256 + tid;
        bk_[i] = idx >> 4;          // 0..31
        bn4[i] = (idx & 15) << 2;   // 0..60
    }

    const float* Abase = attn + (size_t)(h * 512 + bm) * 512;
    const float* Vbase = v + (size_t)(bt * 512) * 512 + kh * 64;

    // preload chunk 0
    float4 ra[4], rb[2];
#pragma unroll
    for (int i = 0; i < 4; i++)
        ra[i] = *(const float4*)(Abase + (size_t)arow[i] * 512 + ac4[i]);
#pragma unroll
    for (int i = 0; i < 2; i++)
        rb[i] = *(const float4*)(Vbase + (size_t)bk_[i] * 512 + bn4[i]);

    const int wm = (wid & 3) << 5;   // 0/32/64/96
    const int wn = (wid >> 2) << 5;  // 0/32

    float acc[2][4][4];
#pragma unroll
    for (int mt = 0; mt < 2; mt++)
#pragma unroll
        for (int nt = 0; nt < 4; nt++)
#pragma unroll
            for (int r = 0; r < 4; r++) acc[mt][nt][r] = 0.f;

    for (int c = 0; c < 16; c++) {
        float* Asb = sm + (c & 1) * AV_STAGE_FLOATS;
        float* Bsb = Asb + 4608;
        // store current regs
#pragma unroll
        for (int i = 0; i < 4; i++) {
            float* p = Asb + arow[i] * 36 + ac4[i];
            p[0] = ra[i].x; p[1] = ra[i].y; p[2] = ra[i].z; p[3] = ra[i].w;
        }
#pragma unroll
        for (int i = 0; i < 2; i++) {
            Bsb[(bn4[i] + 0) * 36 + bk_[i]] = rb[i].x;
            Bsb[(bn4[i] + 1) * 36 + bk_[i]] = rb[i].y;
            Bsb[(bn4[i] + 2) * 36 + bk_[i]] = rb[i].z;
            Bsb[(bn4[i] + 3) * 36 + bk_[i]] = rb[i].w;
        }
        __syncthreads();
        // prefetch next chunk
        if (c + 1 < 16) {
            const int k1 = (c + 1) << 5;
#pragma unroll
            for (int i = 0; i < 4; i++)
                ra[i] = *(const float4*)(Abase + (size_t)arow[i] * 512 + k1 + ac4[i]);
#pragma unroll
            for (int i = 0; i < 2; i++)
                rb[i] = *(const float4*)(Vbase + (size_t)(k1 + bk_[i]) * 512 + bn4[i]);
        }
#pragma unroll
        for (int ks = 0; ks < 4; ks++) {
            const float* Ac = Asb + ks * 8 + qr;
            const float* Bc = Bsb + ks * 8 + qr;
            uint32_t ah[2][4], al[2][4];
#pragma unroll
            for (int mt = 0; mt < 2; mt++) {
                int r0 = wm + mt * 16 + grp;
                split_tf32(Ac[r0 * 36],           ah[mt][0], al[mt][0]);
                split_tf32(Ac[(r0 + 8) * 36],     ah[mt][1], al[mt][1]);
                split_tf32(Ac[r0 * 36 + 4],       ah[mt][2], al[mt][2]);
                split_tf32(Ac[(r0 + 8) * 36 + 4], ah[mt][3], al[mt][3]);
            }
            uint32_t bh[4][2], bl[4][2];
#pragma unroll
            for (int nt = 0; nt < 4; nt++) {
                int rn = wn + nt * 8 + grp;
                split_tf32(Bc[rn * 36],     bh[nt][0], bl[nt][0]);
                split_tf32(Bc[rn * 36 + 4], bh[nt][1], bl[nt][1]);
            }
#pragma unroll
            for (int mt = 0; mt < 2; mt++)
#pragma unroll
                for (int nt = 0; nt < 4; nt++) {
                    MMA_TF32(acc[mt][nt], ah[mt][0], ah[mt][1], ah[mt][2], ah[mt][3],
                             bh[nt][0], bh[nt][1]);
                    MMA_TF32(acc[mt][nt], al[mt][0], al[mt][1], al[mt][2], al[mt][3],
                             bh[nt][0], bh[nt][1]);
                    MMA_TF32(acc[mt][nt], ah[mt][0], ah[mt][1], ah[mt][2], ah[mt][3],
                             bl[nt][0], bl[nt][1]);
                }
        }
        __syncthreads();
    }

    // epilogue: out[(bt*512 + i)*512 + kh*64 + n]
#pragma unroll
    for (int mt = 0; mt < 2; mt++) {
        const int r0 = bt * 512 + bm + wm + mt * 16 + grp;
#pragma unroll
        for (int nt = 0; nt < 4; nt++) {
            const int col = kh * 64 + wn + nt * 8 + (qr << 1);
            *(float2*)(out + (size_t)r0 * 512 + col) =
                make_float2(acc[mt][nt][0], acc[mt][nt][1]);
            *(float2*)(out + (size_t)(r0 + 8) * 512 + col) =
                make_float2(acc[mt][nt][2], acc[mt][nt][3]);
        }
    }
}

// ---------------------------------------------------------------------------
// Graph bias precompute
// ---------------------------------------------------------------------------
__global__ __launch_bounds__(256) void bias_kernel(
    const float* __restrict__ E, const float* __restrict__ lap,
    const float* __restrict__ alphap, const float* __restrict__ betap,
    float* __restrict__ gb)
{
    __shared__ __align__(16) float ei[64];
    __shared__ float reda[8];
    __shared__ float redb[8];
    int i = blockIdx.x;
    int tid = threadIdx.x;
    if (tid < 16) ((float4*)ei)[tid] = ((const float4*)(E + (size_t)i * 64))[tid];
    __syncthreads();

    int j0 = tid, j1 = tid + 256;
    const float* e0 = E + (size_t)j0 * 64;
    const float* e1 = E + (size_t)j1 * 64;
    float r0 = 0.f, r1 = 0.f;
#pragma unroll
    for (int e = 0; e < 64; e += 4) {
        float4 a = *(const float4*)(ei + e);
        float4 u = *(const float4*)(e0 + e);
        float4 w = *(const float4*)(e1 + e);
        r0 += a.x * u.x + a.y * u.y + a.z * u.z + a.w * u.w;
        r1 += a.x * w.x + a.y * w.y + a.z * w.z + a.w * w.w;
    }
    r0 = fmaxf(r0, 0.f);
    r1 = fmaxf(r1, 0.f);

    float mx = fmaxf(r0, r1);
#pragma unroll
    for (int o = 16; o; o >>= 1) mx = fmaxf(mx, __shfl_xor_sync(0xffffffffu, mx, o));
    if ((tid & 31) == 0) reda[tid >> 5] = mx;
    __syncthreads();
    mx = fmaxf(fmaxf(fmaxf(reda[0], reda[1]), fmaxf(reda[2], reda[3])),
               fmaxf(fmaxf(reda[4], reda[5]), fmaxf(reda[6], reda[7])));

    float ex0 = __expf(r0 - mx), ex1 = __expf(r1 - mx);
    float s = ex0 + ex1;
#pragma unroll
    for (int o = 16; o; o >>= 1) s += __shfl_xor_sync(0xffffffffu, s, o);
    if ((tid & 31) == 0) redb[tid >> 5] = s;
    __syncthreads();
    s = redb[0] + redb[1] + redb[2] + redb[3] + redb[4] + redb[5] + redb[6] + redb[7];
    float inv = 1.0f / s;

    float alpha = *alphap, beta = *betap;
    float lp0 = lap[(size_t)i * 512 + j0];
    float lp1 = lap[(size_t)i * 512 + j1];
    float m0 = (lp0 != 0.f) ? 0.f : -1e9f;
    float m1 = (lp1 != 0.f) ? 0.f : -1e9f;
    gb[(size_t)i * 512 + j0] = alpha * ex0 * inv + beta * lp0 + m0;
    gb[(size_t)i * 512 + j1] = alpha * ex1 * inv + beta * lp1 + m1;
}

// ---------------------------------------------------------------------------
// LayerNorm over D=512. One warp per row.
// ---------------------------------------------------------------------------
__global__ __launch_bounds__(256) void ln_kernel(
    const float* __restrict__ X, const float* __restrict__ g,
    const float* __restrict__ b, float* __restrict__ Y, int rows)
{
    int gw = (blockIdx.x * 256 + threadIdx.x) >> 5;
    if (gw >= rows) return;
    int lane = threadIdx.x & 31;
    const float* xr = X + (size_t)gw * 512;
    float* yr = Y + (size_t)gw * 512;
    float4 v[4];
    float s = 0.f, ss = 0.f;
#pragma unroll
    for (int w = 0; w < 4; w++) {
        v[w] = *(const float4*)(xr + w * 128 + lane * 4);
        s += v[w].x + v[w].y + v[w].z + v[w].w;
        ss += v[w].x * v[w].x + v[w].y * v[w].y + v[w].z * v[w].z + v[w].w * v[w].w;
    }
#pragma unroll
    for (int o = 16; o; o >>= 1) {
        s += __shfl_xor_sync(0xffffffffu, s, o);
        ss += __shfl_xor_sync(0xffffffffu, ss, o);
    }
    float mean = s * (1.0f / 512.0f);
    float var = ss * (1.0f / 512.0f) - mean * mean;
    float rstd = rsqrtf(var + 1e-5f);
#pragma unroll
    for (int w = 0; w < 4; w++) {
        int c = w * 128 + lane * 4;
        float4 gg = *(const float4*)(g + c);
        float4 bb = *(const float4*)(b + c);
        float4 o;
        o.x = (v[w].x - mean) * rstd * gg.x + bb.x;
        o.y = (v[w].y - mean) * rstd * gg.y + bb.y;
        o.z = (v[w].z - mean) * rstd * gg.z + bb.z;
        o.w = (v[w].w - mean) * rstd * gg.w + bb.w;
        *(float4*)(yr + c) = o;
    }
}

// ---------------------------------------------------------------------------
// Row softmax, in place
// ---------------------------------------------------------------------------
__global__ __launch_bounds__(256) void softmax_kernel(float* __restrict__ L, int rows)
{
    int r = (blockIdx.x * 256 + threadIdx.x) >> 5;
    if (r >= rows) return;
    int lane = threadIdx.x & 31;
    float* row = L + (size_t)r * 512;
    float4 v[4];
    float mx = -3.0e38f;
#pragma unroll
    for (int w = 0; w < 4; w++) {
        v[w] = *(const float4*)(row + w * 128 + lane * 4);
        mx = fmaxf(mx, fmaxf(fmaxf(v[w].x, v[w].y), fmaxf(v[w].z, v[w].w)));
    }
#pragma unroll
    for (int o = 16; o; o >>= 1) mx = fmaxf(mx, __shfl_xor_sync(0xffffffffu, mx, o));
    float s = 0.f;
#pragma unroll
    for (int w = 0; w < 4; w++) {
        v[w].x = __expf(v[w].x - mx);
        v[w].y = __expf(v[w].y - mx);
        v[w].z = __expf(v[w].z - mx);
        v[w].w = __expf(v[w].w - mx);
        s += v[w].x + v[w].y + v[w].z + v[w].w;
    }
#pragma unroll
    for (int o = 16; o; o >>= 1) s += __shfl_xor_sync(0xffffffffu, s, o);
    float inv = 1.0f / s;
#pragma unroll
    for (int w = 0; w < 4; w++) {
        v[w].x *= inv; v[w].y *= inv; v[w].z *= inv; v[w].w *= inv;
        *(float4*)(row + w * 128 + lane * 4) = v[w];
    }
}

// ---------------------------------------------------------------------------
// Host launcher
// ---------------------------------------------------------------------------
extern "C" void kernel_launch(void* const* d_in, const int* in_sizes, int n_in,
                              void* d_out, int out_size)
{
    const float* x    = (const float*)d_in[0];
    const float* lap  = (const float*)d_in[1];
    const float* emb  = (const float*)d_in[2];
    const float* Wq   = (const float*)d_in[3];
    const float* bq   = (const float*)d_in[4];
    const float* Wk   = (const float*)d_in[5];
    const float* bk   = (const float*)d_in[6];
    const float* Wv   = (const float*)d_in[7];
    const float* bv   = (const float*)d_in[8];
    const float* ln1g = (const float*)d_in[9];
    const float* ln1b = (const float*)d_in[10];
    const float* ln2g = (const float*)d_in[11];
    const float* ln2b = (const float*)d_in[12];
    const float* alpha = (const float*)d_in[13];
    const float* beta  = (const float*)d_in[14];
    const float* Wo   = (const float*)d_in[15];
    const float* bo   = (const float*)d_in[16];
    const float* W1   = (const float*)d_in[17];
    const float* b1   = (const float*)d_in[18];
    const float* W2   = (const float*)d_in[19];
    const float* b2   = (const float*)d_in[20];
    float* out = (float*)d_out;

    float* base = nullptr;
    cudaGetSymbolAddress((void**)&base, g_scratch);
    float* xn     = base + OFF_XN;
    float* q      = base + OFF_Q;
    float* kbuf   = base + OFF_K;
    float* vbuf   = base + OFF_V;
    float* ao     = base + OFF_AO;
    float* x1     = base + OFF_X1;
    float* hin    = base + OFF_HIN;
    float* hbuf   = base + OFF_H;
    float* logits = base + OFF_LOG;
    float* gb     = base + OFF_GB;

    static bool attr_done = false;
    if (!attr_done) {
        cudaFuncSetAttribute(gemm_tc_kernel,
                             cudaFuncAttributeMaxDynamicSharedMemorySize, GM_SMEM_BYTES);
        cudaFuncSetAttribute(tc_scores_kernel,
                             cudaFuncAttributeMaxDynamicSharedMemorySize, GM_SMEM_BYTES);
        cudaFuncSetAttribute(tc_av_kernel,
                             cudaFuncAttributeMaxDynamicSharedMemorySize, AV_SMEM_BYTES);
        attr_done = true;
    }

    // 1. graph bias
    bias_kernel<<<512, 256>>>(emb, lap, alpha, beta, gb);

    // 2. LN1
    ln_kernel<<<R_ROWS / 8, 256>>>(x, ln1g, ln1b, xn, R_ROWS);

    // 3. QKV projections (3xTF32 mma.sync)
    dim3 gq(D_DIM / 128, R_ROWS / 128);
    gemm_tc_kernel<<<gq, 256, GM_SMEM_BYTES>>>(xn, Wq, bq, nullptr, q,    R_ROWS, D_DIM, D_DIM, 0);
    gemm_tc_kernel<<<gq, 256, GM_SMEM_BYTES>>>(xn, Wk, bk, nullptr, kbuf, R_ROWS, D_DIM, D_DIM, 0);
    gemm_tc_kernel<<<gq, 256, GM_SMEM_BYTES>>>(xn, Wv, bv, nullptr, vbuf, R_ROWS, D_DIM, D_DIM, 0);

    // 4. scores + bias (tensor core)
    tc_scores_kernel<<<dim3(4, 4, H_HEADS), 256, GM_SMEM_BYTES>>>(q, kbuf, gb, logits);

    // 5. softmax
    softmax_kernel<<<(H_HEADS * N_NODES) / 8, 256>>>(logits, H_HEADS * N_NODES);

    // 6. attn @ V (tensor core)
    tc_av_kernel<<<dim3(4, H_HEADS), 256, AV_SMEM_BYTES>>>(logits, vbuf, ao);

    // 7. output projection + residual
    gemm_tc_kernel<<<gq, 256, GM_SMEM_BYTES>>>(ao, Wo, bo, x, x1, R_ROWS, D_DIM, D_DIM, 0);

    // 8. LN2
    ln_kernel<<<R_ROWS / 8, 256>>>(x1, ln2g, ln2b, hin, R_ROWS);

    // 9. FF up (relu)
    gemm_tc_kernel<<<dim3(DFF / 128, R_ROWS / 128), 256, GM_SMEM_BYTES>>>(
        hin, W1, b1, nullptr, hbuf, R_ROWS, DFF, D_DIM, 1);

    // 10. FF down + residual
    gemm_tc_kernel<<<dim3(D_DIM / 128, R_ROWS / 128), 256, GM_SMEM_BYTES>>>(
        hbuf, W2, b2, x1, out, R_ROWS, D_DIM, DFF, 0);
}

// round 6
// speedup vs baseline: 1.5282x; 1.0039x over previous
#include <cuda_runtime.h>
#include <cstdint>

// ---------------------------------------------------------------------------
// Problem constants
// ---------------------------------------------------------------------------
#define R_ROWS 16384
#define N_NODES 512
#define D_DIM 512
#define H_HEADS 256
#define DFF 2048

// Scratch layout (float offsets)
#define OFF_XN   0ull
#define OFF_Q    8388608ull
#define OFF_KH   16777216ull
#define OFF_KL   25165824ull
#define OFF_VH   33554432ull
#define OFF_VL   41943040ull
#define OFF_AO   50331648ull
#define OFF_X1   58720256ull
#define OFF_HIN  67108864ull
#define OFF_HB   75497472ull
#define OFF_LOG  109051904ull
#define OFF_GB   176160768ull
#define OFF_WQH  176422912ull
#define OFF_WQL  176685056ull
#define OFF_WKH  176947200ull
#define OFF_WKL  177209344ull
#define OFF_WVH  177471488ull
#define OFF_WVL  177733632ull
#define OFF_WOH  177995776ull
#define OFF_WOL  178257920ull
#define OFF_W1H  178520064ull
#define OFF_W1L  179568640ull
#define OFF_W2H  180617216ull
#define OFF_W2L  181665792ull

__device__ float g_scratch[182714368];

// ===========================================================================
// Helpers
// ===========================================================================
__device__ __forceinline__ uint32_t smem_u32(const void* p) {
    uint32_t a;
    asm("{ .reg .u64 t; cvta.to.shared.u64 t, %1; cvt.u32.u64 %0, t; }"
        : "=r"(a) : "l"(p));
    return a;
}

#define CP_ASYNC16(dst, src) \
    asm volatile("cp.async.cg.shared.global [%0], [%1], 16;" :: "r"(dst), "l"(src))
#define CP_COMMIT() asm volatile("cp.async.commit_group;" ::: "memory")
#define CP_WAIT1()  asm volatile("cp.async.wait_group 1;" ::: "memory")
#define CP_WAIT0()  asm volatile("cp.async.wait_group 0;" ::: "memory")

#define MMA_TF32(d, a0, a1, a2, a3, b0, b1) \
    asm volatile("mma.sync.aligned.m16n8k8.row.col.f32.tf32.tf32.f32 " \
        "{%0,%1,%2,%3}, {%4,%5,%6,%7}, {%8,%9}, {%0,%1,%2,%3};" \
        : "+f"((d)[0]), "+f"((d)[1]), "+f"((d)[2]), "+f"((d)[3]) \
        : "r"(a0), "r"(a1), "r"(a2), "r"(a3), "r"(b0), "r"(b1))

__device__ __forceinline__ void split_tf32(float x, uint32_t& hi, uint32_t& lo) {
    uint32_t h;
    asm("cvt.rna.tf32.f32 %0, %1;" : "=r"(h) : "f"(x));
    float l = x - __uint_as_float(h);
    uint32_t lb;
    asm("cvt.rna.tf32.f32 %0, %1;" : "=r"(lb) : "f"(l));
    hi = h; lo = lb;
}
__device__ __forceinline__ void split_f(float x, float& h, float& l) {
    uint32_t a, b;
    split_tf32(x, a, b);
    h = __uint_as_float(a); l = __uint_as_float(b);
}

// ===========================================================================
// Elementwise pre-split: X -> (Xh, Xl), n4 = n/4 float4 slots
// ===========================================================================
__global__ __launch_bounds__(256) void split_kernel(
    const float* __restrict__ X, float* __restrict__ Xh, float* __restrict__ Xl, int n4)
{
    int i = blockIdx.x * 256 + threadIdx.x;
    if (i >= n4) return;
    float4 x = ((const float4*)X)[i];
    float4 h, l;
    split_f(x.x, h.x, l.x);
    split_f(x.y, h.y, l.y);
    split_f(x.z, h.z, l.z);
    split_f(x.w, h.w, l.w);
    ((float4*)Xh)[i] = h;
    ((float4*)Xl)[i] = l;
}

// ===========================================================================
// 3xTF32 GEMM, B pre-split: C[m,n] = sum_k A[m,k]*B[n,k] + bias[n] (+relu)(+res)
// A raw (in-loop split). Bh/Bl: tf32 hi/lo of B, [N,Kd] row-major.
// Outputs: C raw (optional) and/or (Ch, Cl) split pair (optional).
// CTA 128x128, 8 warps (4m x 2n), BK=32, cp.async double-buffered.
// Stage: A 4608 + Bh 4608 + Bl 4608 floats = 13824; 2 stages = 110592 B.
// ===========================================================================
#define G2_STAGE_FLOATS 13824
#define G2_SMEM_BYTES  (2 * G2_STAGE_FLOATS * 4)

__global__ __launch_bounds__(256, 2)
void gemm_tc2_kernel(const float* __restrict__ A, const float* __restrict__ Bh,
                     const float* __restrict__ Bl,
                     const float* __restrict__ bias, const float* __restrict__ res,
                     float* __restrict__ C, float* __restrict__ Ch, float* __restrict__ Cl,
                     int M, int N, int Kd, int relu)
{
    extern __shared__ float sm[];
    const int tid  = threadIdx.x;
    const int wid  = tid >> 5;
    const int lane = tid & 31;
    const int grp  = lane >> 2;
    const int qr   = lane & 3;
    const int bm   = blockIdx.y << 7;
    const int bn   = blockIdx.x << 7;
    const uint32_t sbase = smem_u32(sm);

    uint32_t soff[4];
    const float* gA[4];
    const float* gBh[4];
    const float* gBl[4];
#pragma unroll
    for (int i = 0; i < 4; i++) {
        int idx = i * 256 + tid;
        int row = idx >> 3;
        int c4  = idx & 7;
        soff[i] = (uint32_t)(row * 36 + c4 * 4) * 4u;
        gA[i]  = A  + (size_t)(bm + row) * Kd + (c4 << 2);
        gBh[i] = Bh + (size_t)(bn + row) * Kd + (c4 << 2);
        gBl[i] = Bl + (size_t)(bn + row) * Kd + (c4 << 2);
    }

    const int nc = Kd >> 5;

#pragma unroll
    for (int i = 0; i < 4; i++) {
        CP_ASYNC16(sbase + soff[i], gA[i]);
        CP_ASYNC16(sbase + 4608u * 4u + soff[i], gBh[i]);
        CP_ASYNC16(sbase + 9216u * 4u + soff[i], gBl[i]);
    }
    CP_COMMIT();

    const int wm = (wid & 3) << 5;
    const int wn = (wid >> 2) << 6;

    float acc[2][8][4];
#pragma unroll
    for (int mt = 0; mt < 2; mt++)
#pragma unroll
        for (int nt = 0; nt < 8; nt++)
#pragma unroll
            for (int r = 0; r < 4; r++) acc[mt][nt][r] = 0.f;

    for (int c = 0; c < nc; c++) {
        if (c + 1 < nc) {
            const int k1 = (c + 1) << 5;
            const uint32_t st = sbase + (uint32_t)((c + 1) & 1) * (G2_STAGE_FLOATS * 4u);
#pragma unroll
            for (int i = 0; i < 4; i++) {
                CP_ASYNC16(st + soff[i], gA[i] + k1);
                CP_ASYNC16(st + 4608u * 4u + soff[i], gBh[i] + k1);
                CP_ASYNC16(st + 9216u * 4u + soff[i], gBl[i] + k1);
            }
            CP_COMMIT();
            CP_WAIT1();
        } else {
            CP_WAIT0();
        }
        __syncthreads();

        const float* Asb = sm + (c & 1) * G2_STAGE_FLOATS;
        const float* Bhb = Asb + 4608;
        const float* Blb = Asb + 9216;
#pragma unroll
        for (int ks = 0; ks < 4; ks++) {
            const float* Ac  = Asb + ks * 8 + qr;
            const float* Bch = Bhb + ks * 8 + qr;
            const float* Bcl = Blb + ks * 8 + qr;
            uint32_t ah[2][4], al[2][4];
#pragma unroll
            for (int mt = 0; mt < 2; mt++) {
                int r0 = wm + mt * 16 + grp;
                split_tf32(Ac[r0 * 36],           ah[mt][0], al[mt][0]);
                split_tf32(Ac[(r0 + 8) * 36],     ah[mt][1], al[mt][1]);
                split_tf32(Ac[r0 * 36 + 4],       ah[mt][2], al[mt][2]);
                split_tf32(Ac[(r0 + 8) * 36 + 4], ah[mt][3], al[mt][3]);
            }
            uint32_t bh[8][2], bl[8][2];
#pragma unroll
            for (int nt = 0; nt < 8; nt++) {
                int rn = wn + nt * 8 + grp;
                bh[nt][0] = __float_as_uint(Bch[rn * 36]);
                bh[nt][1] = __float_as_uint(Bch[rn * 36 + 4]);
                bl[nt][0] = __float_as_uint(Bcl[rn * 36]);
                bl[nt][1] = __float_as_uint(Bcl[rn * 36 + 4]);
            }
#pragma unroll
            for (int mt = 0; mt < 2; mt++)
#pragma unroll
                for (int nt = 0; nt < 8; nt++) {
                    MMA_TF32(acc[mt][nt], ah[mt][0], ah[mt][1], ah[mt][2], ah[mt][3],
                             bh[nt][0], bh[nt][1]);
                    MMA_TF32(acc[mt][nt], al[mt][0], al[mt][1], al[mt][2], al[mt][3],
                             bh[nt][0], bh[nt][1]);
                    MMA_TF32(acc[mt][nt], ah[mt][0], ah[mt][1], ah[mt][2], ah[mt][3],
                             bl[nt][0], bl[nt][1]);
                }
        }
        __syncthreads();
    }

#pragma unroll
    for (int mt = 0; mt < 2; mt++) {
        const int r0 = bm + wm + mt * 16 + grp;
#pragma unroll
        for (int nt = 0; nt < 8; nt++) {
            const int col = bn + wn + nt * 8 + (qr << 1);
            float2 bb = *(const float2*)(bias + col);
            float v0 = acc[mt][nt][0] + bb.x;
            float v1 = acc[mt][nt][1] + bb.y;
            float v2 = acc[mt][nt][2] + bb.x;
            float v3 = acc[mt][nt][3] + bb.y;
            if (relu) {
                v0 = fmaxf(v0, 0.f); v1 = fmaxf(v1, 0.f);
                v2 = fmaxf(v2, 0.f); v3 = fmaxf(v3, 0.f);
            }
            if (res) {
                float2 ra = *(const float2*)(res + (size_t)r0 * N + col);
                float2 rb = *(const float2*)(res + (size_t)(r0 + 8) * N + col);
                v0 += ra.x; v1 += ra.y; v2 += rb.x; v3 += rb.y;
            }
            if (C) {
                *(float2*)(C + (size_t)r0 * N + col)       = make_float2(v0, v1);
                *(float2*)(C + (size_t)(r0 + 8) * N + col) = make_float2(v2, v3);
            }
            if (Ch) {
                float h0, l0, h1, l1, h2, l2, h3, l3;
                split_f(v0, h0, l0); split_f(v1, h1, l1);
                split_f(v2, h2, l2); split_f(v3, h3, l3);
                *(float2*)(Ch + (size_t)r0 * N + col)       = make_float2(h0, h1);
                *(float2*)(Cl + (size_t)r0 * N + col)       = make_float2(l0, l1);
                *(float2*)(Ch + (size_t)(r0 + 8) * N + col) = make_float2(h2, h3);
                *(float2*)(Cl + (size_t)(r0 + 8) * N + col) = make_float2(l2, l3);
            }
        }
    }
}

// ===========================================================================
// Scores: logits[h][i][j] = (Q_h[i].K_h[j])*0.125 + gb[i][j]
// A = q raw (in-loop split); B = (k_h, k_l) pre-split. K=64 (2 chunks).
// ===========================================================================
__global__ __launch_bounds__(256, 2)
void tc_scores2_kernel(const float* __restrict__ q, const float* __restrict__ kh_,
                       const float* __restrict__ kl_, const float* __restrict__ gb,
                       float* __restrict__ logits)
{
    extern __shared__ float sm[];
    const int tid  = threadIdx.x;
    const int wid  = tid >> 5;
    const int lane = tid & 31;
    const int grp  = lane >> 2;
    const int qr   = lane & 3;
    const int h  = blockIdx.z;
    const int bt = h >> 3;
    const int kh = h & 7;
    const int bm = blockIdx.y << 7;
    const int bn = blockIdx.x << 7;
    const uint32_t sbase = smem_u32(sm);

    uint32_t soff[4];
    const float* gA[4];
    const float* gBh[4];
    const float* gBl[4];
#pragma unroll
    for (int i = 0; i < 4; i++) {
        int idx = i * 256 + tid;
        int row = idx >> 3;
        int c4  = idx & 7;
        soff[i] = (uint32_t)(row * 36 + c4 * 4) * 4u;
        gA[i]  = q   + (size_t)(bt * 512 + bm + row) * 512 + kh * 64 + (c4 << 2);
        gBh[i] = kh_ + (size_t)(bt * 512 + bn + row) * 512 + kh * 64 + (c4 << 2);
        gBl[i] = kl_ + (size_t)(bt * 512 + bn + row) * 512 + kh * 64 + (c4 << 2);
    }

#pragma unroll
    for (int i = 0; i < 4; i++) {
        CP_ASYNC16(sbase + soff[i], gA[i]);
        CP_ASYNC16(sbase + 4608u * 4u + soff[i], gBh[i]);
        CP_ASYNC16(sbase + 9216u * 4u + soff[i], gBl[i]);
    }
    CP_COMMIT();

    const int wm = (wid & 3) << 5;
    const int wn = (wid >> 2) << 6;

    float acc[2][8][4];
#pragma unroll
    for (int mt = 0; mt < 2; mt++)
#pragma unroll
        for (int nt = 0; nt < 8; nt++)
#pragma unroll
            for (int r = 0; r < 4; r++) acc[mt][nt][r] = 0.f;

#pragma unroll
    for (int c = 0; c < 2; c++) {
        if (c == 0) {
            const uint32_t st = sbase + (G2_STAGE_FLOATS * 4u);
#pragma unroll
            for (int i = 0; i < 4; i++) {
                CP_ASYNC16(st + soff[i], gA[i] + 32);
                CP_ASYNC16(st + 4608u * 4u + soff[i], gBh[i] + 32);
                CP_ASYNC16(st + 9216u * 4u + soff[i], gBl[i] + 32);
            }
            CP_COMMIT();
            CP_WAIT1();
        } else {
            CP_WAIT0();
        }
        __syncthreads();

        const float* Asb = sm + c * G2_STAGE_FLOATS;
        const float* Bhb = Asb + 4608;
        const float* Blb = Asb + 9216;
#pragma unroll
        for (int ks = 0; ks < 4; ks++) {
            const float* Ac  = Asb + ks * 8 + qr;
            const float* Bch = Bhb + ks * 8 + qr;
            const float* Bcl = Blb + ks * 8 + qr;
            uint32_t ah[2][4], al[2][4];
#pragma unroll
            for (int mt = 0; mt < 2; mt++) {
                int r0 = wm + mt * 16 + grp;
                split_tf32(Ac[r0 * 36],           ah[mt][0], al[mt][0]);
                split_tf32(Ac[(r0 + 8) * 36],     ah[mt][1], al[mt][1]);
                split_tf32(Ac[r0 * 36 + 4],       ah[mt][2], al[mt][2]);
                split_tf32(Ac[(r0 + 8) * 36 + 4], ah[mt][3], al[mt][3]);
            }
            uint32_t bh[8][2], bl[8][2];
#pragma unroll
            for (int nt = 0; nt < 8; nt++) {
                int rn = wn + nt * 8 + grp;
                bh[nt][0] = __float_as_uint(Bch[rn * 36]);
                bh[nt][1] = __float_as_uint(Bch[rn * 36 + 4]);
                bl[nt][0] = __float_as_uint(Bcl[rn * 36]);
                bl[nt][1] = __float_as_uint(Bcl[rn * 36 + 4]);
            }
#pragma unroll
            for (int mt = 0; mt < 2; mt++)
#pragma unroll
                for (int nt = 0; nt < 8; nt++) {
                    MMA_TF32(acc[mt][nt], ah[mt][0], ah[mt][1], ah[mt][2], ah[mt][3],
                             bh[nt][0], bh[nt][1]);
                    MMA_TF32(acc[mt][nt], al[mt][0], al[mt][1], al[mt][2], al[mt][3],
                             bh[nt][0], bh[nt][1]);
                    MMA_TF32(acc[mt][nt], ah[mt][0], ah[mt][1], ah[mt][2], ah[mt][3],
                             bl[nt][0], bl[nt][1]);
                }
        }
        __syncthreads();
    }

    float* Lh = logits + (size_t)h * 512 * 512;
#pragma unroll
    for (int mt = 0; mt < 2; mt++) {
        const int gi = bm + wm + mt * 16 + grp;
#pragma unroll
        for (int nt = 0; nt < 8; nt++) {
            const int gj = bn + wn + nt * 8 + (qr << 1);
            float2 g0 = *(const float2*)(gb + (size_t)gi * 512 + gj);
            float2 g1 = *(const float2*)(gb + (size_t)(gi + 8) * 512 + gj);
            float v0 = fmaf(acc[mt][nt][0], 0.125f, g0.x);
            float v1 = fmaf(acc[mt][nt][1], 0.125f, g0.y);
            float v2 = fmaf(acc[mt][nt][2], 0.125f, g1.x);
            float v3 = fmaf(acc[mt][nt][3], 0.125f, g1.y);
            *(float2*)(Lh + (size_t)gi * 512 + gj)       = make_float2(v0, v1);
            *(float2*)(Lh + (size_t)(gi + 8) * 512 + gj) = make_float2(v2, v3);
        }
    }
}

// ===========================================================================
// AV: out_h = P_h @ V_h. A = P raw (in-loop split); B = (v_h, v_l) pre-split,
// transposed into SMEM [n][k]. BM=128, BN=64, K=512, 16 chunks.
// Stage: A 4608 + Bh 2304 + Bl 2304 = 9216 floats; 2 stages = 73728 B.
// ===========================================================================
#define AV2_STAGE_FLOATS 9216
#define AV2_SMEM_BYTES  (2 * AV2_STAGE_FLOATS * 4)

__global__ __launch_bounds__(256, 2)
void tc_av2_kernel(const float* __restrict__ attn, const float* __restrict__ vh_,
                   const float* __restrict__ vl_, float* __restrict__ out)
{
    extern __shared__ float sm[];
    const int tid  = threadIdx.x;
    const int wid  = tid >> 5;
    const int lane = tid & 31;
    const int grp  = lane >> 2;
    const int qr   = lane & 3;
    const int h  = blockIdx.y;
    const int bt = h >> 3;
    const int kh = h & 7;
    const int bm = blockIdx.x << 7;

    int arow[4], ac4[4];
#pragma unroll
    for (int i = 0; i < 4; i++) {
        int idx = i * 256 + tid;
        arow[i] = idx >> 3;
        ac4[i]  = (idx & 7) << 2;
    }
    int bk_[2], bn4[2];
#pragma unroll
    for (int i = 0; i < 2; i++) {
        int idx = i * 256 + tid;
        bk_[i] = idx >> 4;
        bn4[i] = (idx & 15) << 2;
    }

    const float* Abase  = attn + (size_t)(h * 512 + bm) * 512;
    const float* Vhbase = vh_ + (size_t)(bt * 512) * 512 + kh * 64;
    const float* Vlbase = vl_ + (size_t)(bt * 512) * 512 + kh * 64;

    float4 ra[4], rbh[2], rbl[2];
#pragma unroll
    for (int i = 0; i < 4; i++)
        ra[i] = *(const float4*)(Abase + (size_t)arow[i] * 512 + ac4[i]);
#pragma unroll
    for (int i = 0; i < 2; i++) {
        rbh[i] = *(const float4*)(Vhbase + (size_t)bk_[i] * 512 + bn4[i]);
        rbl[i] = *(const float4*)(Vlbase + (size_t)bk_[i] * 512 + bn4[i]);
    }

    const int wm = (wid & 3) << 5;
    const int wn = (wid >> 2) << 5;

    float acc[2][4][4];
#pragma unroll
    for (int mt = 0; mt < 2; mt++)
#pragma unroll
        for (int nt = 0; nt < 4; nt++)
#pragma unroll
            for (int r = 0; r < 4; r++) acc[mt][nt][r] = 0.f;

    for (int c = 0; c < 16; c++) {
        float* Asb = sm + (c & 1) * AV2_STAGE_FLOATS;
        float* Bhb = Asb + 4608;
        float* Blb = Asb + 6912;
#pragma unroll
        for (int i = 0; i < 4; i++) {
            float* p = Asb + arow[i] * 36 + ac4[i];
            p[0] = ra[i].x; p[1] = ra[i].y; p[2] = ra[i].z; p[3] = ra[i].w;
        }
#pragma unroll
        for (int i = 0; i < 2; i++) {
            Bhb[(bn4[i] + 0) * 36 + bk_[i]] = rbh[i].x;
            Bhb[(bn4[i] + 1) * 36 + bk_[i]] = rbh[i].y;
            Bhb[(bn4[i] + 2) * 36 + bk_[i]] = rbh[i].z;
            Bhb[(bn4[i] + 3) * 36 + bk_[i]] = rbh[i].w;
            Blb[(bn4[i] + 0) * 36 + bk_[i]] = rbl[i].x;
            Blb[(bn4[i] + 1) * 36 + bk_[i]] = rbl[i].y;
            Blb[(bn4[i] + 2) * 36 + bk_[i]] = rbl[i].z;
            Blb[(bn4[i] + 3) * 36 + bk_[i]] = rbl[i].w;
        }
        __syncthreads();
        if (c + 1 < 16) {
            const int k1 = (c + 1) << 5;
#pragma unroll
            for (int i = 0; i < 4; i++)
                ra[i] = *(const float4*)(Abase + (size_t)arow[i] * 512 + k1 + ac4[i]);
#pragma unroll
            for (int i = 0; i < 2; i++) {
                rbh[i] = *(const float4*)(Vhbase + (size_t)(k1 + bk_[i]) * 512 + bn4[i]);
                rbl[i] = *(const float4*)(Vlbase + (size_t)(k1 + bk_[i]) * 512 + bn4[i]);
            }
        }
#pragma unroll
        for (int ks = 0; ks < 4; ks++) {
            const float* Ac  = Asb + ks * 8 + qr;
            const float* Bch = Bhb + ks * 8 + qr;
            const float* Bcl = Blb + ks * 8 + qr;
            uint32_t ah[2][4], al[2][4];
#pragma unroll
            for (int mt = 0; mt < 2; mt++) {
                int r0 = wm + mt * 16 + grp;
                split_tf32(Ac[r0 * 36],           ah[mt][0], al[mt][0]);
                split_tf32(Ac[(r0 + 8) * 36],     ah[mt][1], al[mt][1]);
                split_tf32(Ac[r0 * 36 + 4],       ah[mt][2], al[mt][2]);
                split_tf32(Ac[(r0 + 8) * 36 + 4], ah[mt][3], al[mt][3]);
            }
            uint32_t bh[4][2], bl[4][2];
#pragma unroll
            for (int nt = 0; nt < 4; nt++) {
                int rn = wn + nt * 8 + grp;
                bh[nt][0] = __float_as_uint(Bch[rn * 36]);
                bh[nt][1] = __float_as_uint(Bch[rn * 36 + 4]);
                bl[nt][0] = __float_as_uint(Bcl[rn * 36]);
                bl[nt][1] = __float_as_uint(Bcl[rn * 36 + 4]);
            }
#pragma unroll
            for (int mt = 0; mt < 2; mt++)
#pragma unroll
                for (int nt = 0; nt < 4; nt++) {
                    MMA_TF32(acc[mt][nt], ah[mt][0], ah[mt][1], ah[mt][2], ah[mt][3],
                             bh[nt][0], bh[nt][1]);
                    MMA_TF32(acc[mt][nt], al[mt][0], al[mt][1], al[mt][2], al[mt][3],
                             bh[nt][0], bh[nt][1]);
                    MMA_TF32(acc[mt][nt], ah[mt][0], ah[mt][1], ah[mt][2], ah[mt][3],
                             bl[nt][0], bl[nt][1]);
                }
        }
        __syncthreads();
    }

#pragma unroll
    for (int mt = 0; mt < 2; mt++) {
        const int r0 = bt * 512 + bm + wm + mt * 16 + grp;
#pragma unroll
        for (int nt = 0; nt < 4; nt++) {
            const int col = kh * 64 + wn + nt * 8 + (qr << 1);
            *(float2*)(out + (size_t)r0 * 512 + col) =
                make_float2(acc[mt][nt][0], acc[mt][nt][1]);
            *(float2*)(out + (size_t)(r0 + 8) * 512 + col) =
                make_float2(acc[mt][nt][2], acc[mt][nt][3]);
        }
    }
}

// ---------------------------------------------------------------------------
// Graph bias precompute
// ---------------------------------------------------------------------------
__global__ __launch_bounds__(256) void bias_kernel(
    const float* __restrict__ E, const float* __restrict__ lap,
    const float* __restrict__ alphap, const float* __restrict__ betap,
    float* __restrict__ gb)
{
    __shared__ __align__(16) float ei[64];
    __shared__ float reda[8];
    __shared__ float redb[8];
    int i = blockIdx.x;
    int tid = threadIdx.x;
    if (tid < 16) ((float4*)ei)[tid] = ((const float4*)(E + (size_t)i * 64))[tid];
    __syncthreads();

    int j0 = tid, j1 = tid + 256;
    const float* e0 = E + (size_t)j0 * 64;
    const float* e1 = E + (size_t)j1 * 64;
    float r0 = 0.f, r1 = 0.f;
#pragma unroll
    for (int e = 0; e < 64; e += 4) {
        float4 a = *(const float4*)(ei + e);
        float4 u = *(const float4*)(e0 + e);
        float4 w = *(const float4*)(e1 + e);
        r0 += a.x * u.x + a.y * u.y + a.z * u.z + a.w * u.w;
        r1 += a.x * w.x + a.y * w.y + a.z * w.z + a.w * w.w;
    }
    r0 = fmaxf(r0, 0.f);
    r1 = fmaxf(r1, 0.f);

    float mx = fmaxf(r0, r1);
#pragma unroll
    for (int o = 16; o; o >>= 1) mx = fmaxf(mx, __shfl_xor_sync(0xffffffffu, mx, o));
    if ((tid & 31) == 0) reda[tid >> 5] = mx;
    __syncthreads();
    mx = fmaxf(fmaxf(fmaxf(reda[0], reda[1]), fmaxf(reda[2], reda[3])),
               fmaxf(fmaxf(reda[4], reda[5]), fmaxf(reda[6], reda[7])));

    float ex0 = __expf(r0 - mx), ex1 = __expf(r1 - mx);
    float s = ex0 + ex1;
#pragma unroll
    for (int o = 16; o; o >>= 1) s += __shfl_xor_sync(0xffffffffu, s, o);
    if ((tid & 31) == 0) redb[tid >> 5] = s;
    __syncthreads();
    s = redb[0] + redb[1] + redb[2] + redb[3] + redb[4] + redb[5] + redb[6] + redb[7];
    float inv = 1.0f / s;

    float alpha = *alphap, beta = *betap;
    float lp0 = lap[(size_t)i * 512 + j0];
    float lp1 = lap[(size_t)i * 512 + j1];
    float m0 = (lp0 != 0.f) ? 0.f : -1e9f;
    float m1 = (lp1 != 0.f) ? 0.f : -1e9f;
    gb[(size_t)i * 512 + j0] = alpha * ex0 * inv + beta * lp0 + m0;
    gb[(size_t)i * 512 + j1] = alpha * ex1 * inv + beta * lp1 + m1;
}

// ---------------------------------------------------------------------------
// LayerNorm over D=512. One warp per row.
// ---------------------------------------------------------------------------
__global__ __launch_bounds__(256) void ln_kernel(
    const float* __restrict__ X, const float* __restrict__ g,
    const float* __restrict__ b, float* __restrict__ Y, int rows)
{
    int gw = (blockIdx.x * 256 + threadIdx.x) >> 5;
    if (gw >= rows) return;
    int lane = threadIdx.x & 31;
    const float* xr = X + (size_t)gw * 512;
    float* yr = Y + (size_t)gw * 512;
    float4 v[4];
    float s = 0.f, ss = 0.f;
#pragma unroll
    for (int w = 0; w < 4; w++) {
        v[w] = *(const float4*)(xr + w * 128 + lane * 4);
        s += v[w].x + v[w].y + v[w].z + v[w].w;
        ss += v[w].x * v[w].x + v[w].y * v[w].y + v[w].z * v[w].z + v[w].w * v[w].w;
    }
#pragma unroll
    for (int o = 16; o; o >>= 1) {
        s += __shfl_xor_sync(0xffffffffu, s, o);
        ss += __shfl_xor_sync(0xffffffffu, ss, o);
    }
    float mean = s * (1.0f / 512.0f);
    float var = ss * (1.0f / 512.0f) - mean * mean;
    float rstd = rsqrtf(var + 1e-5f);
#pragma unroll
    for (int w = 0; w < 4; w++) {
        int c = w * 128 + lane * 4;
        float4 gg = *(const float4*)(g + c);
        float4 bb = *(const float4*)(b + c);
        float4 o;
        o.x = (v[w].x - mean) * rstd * gg.x + bb.x;
        o.y = (v[w].y - mean) * rstd * gg.y + bb.y;
        o.z = (v[w].z - mean) * rstd * gg.z + bb.z;
        o.w = (v[w].w - mean) * rstd * gg.w + bb.w;
        *(float4*)(yr + c) = o;
    }
}

// ---------------------------------------------------------------------------
// Row softmax, in place
// ---------------------------------------------------------------------------
__global__ __launch_bounds__(256) void softmax_kernel(float* __restrict__ L, int rows)
{
    int r = (blockIdx.x * 256 + threadIdx.x) >> 5;
    if (r >= rows) return;
    int lane = threadIdx.x & 31;
    float* row = L + (size_t)r * 512;
    float4 v[4];
    float mx = -3.0e38f;
#pragma unroll
    for (int w = 0; w < 4; w++) {
        v[w] = *(const float4*)(row + w * 128 + lane * 4);
        mx = fmaxf(mx, fmaxf(fmaxf(v[w].x, v[w].y), fmaxf(v[w].z, v[w].w)));
    }
#pragma unroll
    for (int o = 16; o; o >>= 1) mx = fmaxf(mx, __shfl_xor_sync(0xffffffffu, mx, o));
    float s = 0.f;
#pragma unroll
    for (int w = 0; w < 4; w++) {
        v[w].x = __expf(v[w].x - mx);
        v[w].y = __expf(v[w].y - mx);
        v[w].z = __expf(v[w].z - mx);
        v[w].w = __expf(v[w].w - mx);
        s += v[w].x + v[w].y + v[w].z + v[w].w;
    }
#pragma unroll
    for (int o = 16; o; o >>= 1) s += __shfl_xor_sync(0xffffffffu, s, o);
    float inv = 1.0f / s;
#pragma unroll
    for (int w = 0; w < 4; w++) {
        v[w].x *= inv; v[w].y *= inv; v[w].z *= inv; v[w].w *= inv;
        *(float4*)(row + w * 128 + lane * 4) = v[w];
    }
}

// ---------------------------------------------------------------------------
// Host launcher
// ---------------------------------------------------------------------------
extern "C" void kernel_launch(void* const* d_in, const int* in_sizes, int n_in,
                              void* d_out, int out_size)
{
    const float* x    = (const float*)d_in[0];
    const float* lap  = (const float*)d_in[1];
    const float* emb  = (const float*)d_in[2];
    const float* Wq   = (const float*)d_in[3];
    const float* bq   = (const float*)d_in[4];
    const float* Wk   = (const float*)d_in[5];
    const float* bk   = (const float*)d_in[6];
    const float* Wv   = (const float*)d_in[7];
    const float* bv   = (const float*)d_in[8];
    const float* ln1g = (const float*)d_in[9];
    const float* ln1b = (const float*)d_in[10];
    const float* ln2g = (const float*)d_in[11];
    const float* ln2b = (const float*)d_in[12];
    const float* alpha = (const float*)d_in[13];
    const float* beta  = (const float*)d_in[14];
    const float* Wo   = (const float*)d_in[15];
    const float* bo   = (const float*)d_in[16];
    const float* W1   = (const float*)d_in[17];
    const float* b1   = (const float*)d_in[18];
    const float* W2   = (const float*)d_in[19];
    const float* b2   = (const float*)d_in[20];
    float* out = (float*)d_out;

    float* base = nullptr;
    cudaGetSymbolAddress((void**)&base, g_scratch);
    float* xn     = base + OFF_XN;
    float* q      = base + OFF_Q;
    float* k_h    = base + OFF_KH;
    float* k_l    = base + OFF_KL;
    float* v_h    = base + OFF_VH;
    float* v_l    = base + OFF_VL;
    float* ao     = base + OFF_AO;
    float* x1     = base + OFF_X1;
    float* hin    = base + OFF_HIN;
    float* hbuf   = base + OFF_HB;
    float* logits = base + OFF_LOG;
    float* gb     = base + OFF_GB;
    float* wqh = base + OFF_WQH; float* wql = base + OFF_WQL;
    float* wkh = base + OFF_WKH; float* wkl = base + OFF_WKL;
    float* wvh = base + OFF_WVH; float* wvl = base + OFF_WVL;
    float* woh = base + OFF_WOH; float* wol = base + OFF_WOL;
    float* w1h = base + OFF_W1H; float* w1l = base + OFF_W1L;
    float* w2h = base + OFF_W2H; float* w2l = base + OFF_W2L;

    static bool attr_done = false;
    if (!attr_done) {
        cudaFuncSetAttribute(gemm_tc2_kernel,
                             cudaFuncAttributeMaxDynamicSharedMemorySize, G2_SMEM_BYTES);
        cudaFuncSetAttribute(tc_scores2_kernel,
                             cudaFuncAttributeMaxDynamicSharedMemorySize, G2_SMEM_BYTES);
        cudaFuncSetAttribute(tc_av2_kernel,
                             cudaFuncAttributeMaxDynamicSharedMemorySize, AV2_SMEM_BYTES);
        attr_done = true;
    }

    // 0. weight pre-splits (graph-capturable, deterministic)
    split_kernel<<<256, 256>>>(Wq, wqh, wql, 65536);
    split_kernel<<<256, 256>>>(Wk, wkh, wkl, 65536);
    split_kernel<<<256, 256>>>(Wv, wvh, wvl, 65536);
    split_kernel<<<256, 256>>>(Wo, woh, wol, 65536);
    split_kernel<<<1024, 256>>>(W1, w1h, w1l, 262144);
    split_kernel<<<1024, 256>>>(W2, w2h, w2l, 262144);

    // 1. graph bias
    bias_kernel<<<512, 256>>>(emb, lap, alpha, beta, gb);

    // 2. LN1
    ln_kernel<<<R_ROWS / 8, 256>>>(x, ln1g, ln1b, xn, R_ROWS);

    // 3. QKV projections (B pre-split). K,V epilogue-split for attention.
    dim3 gq(D_DIM / 128, R_ROWS / 128);
    gemm_tc2_kernel<<<gq, 256, G2_SMEM_BYTES>>>(
        xn, wqh, wql, bq, nullptr, q, nullptr, nullptr, R_ROWS, D_DIM, D_DIM, 0);
    gemm_tc2_kernel<<<gq, 256, G2_SMEM_BYTES>>>(
        xn, wkh, wkl, bk, nullptr, nullptr, k_h, k_l, R_ROWS, D_DIM, D_DIM, 0);
    gemm_tc2_kernel<<<gq, 256, G2_SMEM_BYTES>>>(
        xn, wvh, wvl, bv, nullptr, nullptr, v_h, v_l, R_ROWS, D_DIM, D_DIM, 0);

    // 4. scores + bias
    tc_scores2_kernel<<<dim3(4, 4, H_HEADS), 256, G2_SMEM_BYTES>>>(q, k_h, k_l, gb, logits);

    // 5. softmax
    softmax_kernel<<<(H_HEADS * N_NODES) / 8, 256>>>(logits, H_HEADS * N_NODES);

    // 6. attn @ V
    tc_av2_kernel<<<dim3(4, H_HEADS), 256, AV2_SMEM_BYTES>>>(logits, v_h, v_l, ao);

    // 7. output projection + residual
    gemm_tc2_kernel<<<gq, 256, G2_SMEM_BYTES>>>(
        ao, woh, wol, bo, x, x1, nullptr, nullptr, R_ROWS, D_DIM, D_DIM, 0);

    // 8. LN2
    ln_kernel<<<R_ROWS / 8, 256>>>(x1, ln2g, ln2b, hin, R_ROWS);

    // 9. FF up (relu)
    gemm_tc2_kernel<<<dim3(DFF / 128, R_ROWS / 128), 256, G2_SMEM_BYTES>>>(
        hin, w1h, w1l, b1, nullptr, hbuf, nullptr, nullptr, R_ROWS, DFF, D_DIM, 1);

    // 10. FF down + residual
    gemm_tc2_kernel<<<dim3(D_DIM / 128, R_ROWS / 128), 256, G2_SMEM_BYTES>>>(
        hbuf, w2h, w2l, b2, x1, out, nullptr, nullptr, R_ROWS, D_DIM, DFF, 0);
}

// round 7
// speedup vs baseline: 2.1149x; 1.3839x over previous
#include <cuda_runtime.h>
#include <cstdint>

// ---------------------------------------------------------------------------
// Problem constants
// ---------------------------------------------------------------------------
#define R_ROWS 16384
#define N_NODES 512
#define D_DIM 512
#define H_HEADS 256
#define DFF 2048

// Scratch layout (float offsets)
#define OFF_XN   0ull
#define OFF_Q    8388608ull
#define OFF_KH   16777216ull
#define OFF_KL   25165824ull
#define OFF_VH   33554432ull
#define OFF_VL   41943040ull
#define OFF_AO   50331648ull
#define OFF_X1   58720256ull
#define OFF_HIN  67108864ull
#define OFF_HB   75497472ull
#define OFF_LOG  109051904ull
#define OFF_GB   176160768ull
#define OFF_WQH  176422912ull
#define OFF_WQL  176685056ull
#define OFF_WKH  176947200ull
#define OFF_WKL  177209344ull
#define OFF_WVH  177471488ull
#define OFF_WVL  177733632ull
#define OFF_WOH  177995776ull
#define OFF_WOL  178257920ull

__device__ float g_scratch[182714368];

// ===========================================================================
// Helpers
// ===========================================================================
__device__ __forceinline__ uint32_t smem_u32(const void* p) {
    uint32_t a;
    asm("{ .reg .u64 t; cvta.to.shared.u64 t, %1; cvt.u32.u64 %0, t; }"
        : "=r"(a) : "l"(p));
    return a;
}

#define CP_ASYNC16(dst, src) \
    asm volatile("cp.async.cg.shared.global [%0], [%1], 16;" :: "r"(dst), "l"(src))
#define CP_COMMIT() asm volatile("cp.async.commit_group;" ::: "memory")
#define CP_WAIT1()  asm volatile("cp.async.wait_group 1;" ::: "memory")
#define CP_WAIT0()  asm volatile("cp.async.wait_group 0;" ::: "memory")

#define MMA_TF32(d, a0, a1, a2, a3, b0, b1) \
    asm volatile("mma.sync.aligned.m16n8k8.row.col.f32.tf32.tf32.f32 " \
        "{%0,%1,%2,%3}, {%4,%5,%6,%7}, {%8,%9}, {%0,%1,%2,%3};" \
        : "+f"((d)[0]), "+f"((d)[1]), "+f"((d)[2]), "+f"((d)[3]) \
        : "r"(a0), "r"(a1), "r"(a2), "r"(a3), "r"(b0), "r"(b1))

__device__ __forceinline__ void split_tf32(float x, uint32_t& hi, uint32_t& lo) {
    uint32_t h;
    asm("cvt.rna.tf32.f32 %0, %1;" : "=r"(h) : "f"(x));
    float l = x - __uint_as_float(h);
    uint32_t lb;
    asm("cvt.rna.tf32.f32 %0, %1;" : "=r"(lb) : "f"(l));
    hi = h; lo = lb;
}
__device__ __forceinline__ void split_f(float x, float& h, float& l) {
    uint32_t a, b;
    split_tf32(x, a, b);
    h = __uint_as_float(a); l = __uint_as_float(b);
}
__device__ __forceinline__ uint32_t f2tf(float x) {
    uint32_t r;
    asm("cvt.rna.tf32.f32 %0, %1;" : "=r"(r) : "f"(x));
    return r;
}

// ===========================================================================
// Elementwise pre-split: X -> (Xh, Xl)
// ===========================================================================
__global__ __launch_bounds__(256) void split_kernel(
    const float* __restrict__ X, float* __restrict__ Xh, float* __restrict__ Xl, int n4)
{
    int i = blockIdx.x * 256 + threadIdx.x;
    if (i >= n4) return;
    float4 x = ((const float4*)X)[i];
    float4 h, l;
    split_f(x.x, h.x, l.x);
    split_f(x.y, h.y, l.y);
    split_f(x.z, h.z, l.z);
    split_f(x.w, h.w, l.w);
    ((float4*)Xh)[i] = h;
    ((float4*)Xl)[i] = l;
}

// ===========================================================================
// 3xTF32 GEMM, B pre-split (QKV / Wo)
// ===========================================================================
#define G2_STAGE_FLOATS 13824
#define G2_SMEM_BYTES  (2 * G2_STAGE_FLOATS * 4)

__global__ __launch_bounds__(256, 2)
void gemm_tc2_kernel(const float* __restrict__ A, const float* __restrict__ Bh,
                     const float* __restrict__ Bl,
                     const float* __restrict__ bias, const float* __restrict__ res,
                     float* __restrict__ C, float* __restrict__ Ch, float* __restrict__ Cl,
                     int M, int N, int Kd, int relu)
{
    extern __shared__ float sm[];
    const int tid  = threadIdx.x;
    const int wid  = tid >> 5;
    const int lane = tid & 31;
    const int grp  = lane >> 2;
    const int qr   = lane & 3;
    const int bm   = blockIdx.y << 7;
    const int bn   = blockIdx.x << 7;
    const uint32_t sbase = smem_u32(sm);

    uint32_t soff[4];
    const float* gA[4];
    const float* gBh[4];
    const float* gBl[4];
#pragma unroll
    for (int i = 0; i < 4; i++) {
        int idx = i * 256 + tid;
        int row = idx >> 3;
        int c4  = idx & 7;
        soff[i] = (uint32_t)(row * 36 + c4 * 4) * 4u;
        gA[i]  = A  + (size_t)(bm + row) * Kd + (c4 << 2);
        gBh[i] = Bh + (size_t)(bn + row) * Kd + (c4 << 2);
        gBl[i] = Bl + (size_t)(bn + row) * Kd + (c4 << 2);
    }

    const int nc = Kd >> 5;

#pragma unroll
    for (int i = 0; i < 4; i++) {
        CP_ASYNC16(sbase + soff[i], gA[i]);
        CP_ASYNC16(sbase + 4608u * 4u + soff[i], gBh[i]);
        CP_ASYNC16(sbase + 9216u * 4u + soff[i], gBl[i]);
    }
    CP_COMMIT();

    const int wm = (wid & 3) << 5;
    const int wn = (wid >> 2) << 6;

    float acc[2][8][4];
#pragma unroll
    for (int mt = 0; mt < 2; mt++)
#pragma unroll
        for (int nt = 0; nt < 8; nt++)
#pragma unroll
            for (int r = 0; r < 4; r++) acc[mt][nt][r] = 0.f;

    for (int c = 0; c < nc; c++) {
        if (c + 1 < nc) {
            const int k1 = (c + 1) << 5;
            const uint32_t st = sbase + (uint32_t)((c + 1) & 1) * (G2_STAGE_FLOATS * 4u);
#pragma unroll
            for (int i = 0; i < 4; i++) {
                CP_ASYNC16(st + soff[i], gA[i] + k1);
                CP_ASYNC16(st + 4608u * 4u + soff[i], gBh[i] + k1);
                CP_ASYNC16(st + 9216u * 4u + soff[i], gBl[i] + k1);
            }
            CP_COMMIT();
            CP_WAIT1();
        } else {
            CP_WAIT0();
        }
        __syncthreads();

        const float* Asb = sm + (c & 1) * G2_STAGE_FLOATS;
        const float* Bhb = Asb + 4608;
        const float* Blb = Asb + 9216;
#pragma unroll
        for (int ks = 0; ks < 4; ks++) {
            const float* Ac  = Asb + ks * 8 + qr;
            const float* Bch = Bhb + ks * 8 + qr;
            const float* Bcl = Blb + ks * 8 + qr;
            uint32_t ah[2][4], al[2][4];
#pragma unroll
            for (int mt = 0; mt < 2; mt++) {
                int r0 = wm + mt * 16 + grp;
                split_tf32(Ac[r0 * 36],           ah[mt][0], al[mt][0]);
                split_tf32(Ac[(r0 + 8) * 36],     ah[mt][1], al[mt][1]);
                split_tf32(Ac[r0 * 36 + 4],       ah[mt][2], al[mt][2]);
                split_tf32(Ac[(r0 + 8) * 36 + 4], ah[mt][3], al[mt][3]);
            }
            uint32_t bh[8][2], bl[8][2];
#pragma unroll
            for (int nt = 0; nt < 8; nt++) {
                int rn = wn + nt * 8 + grp;
                bh[nt][0] = __float_as_uint(Bch[rn * 36]);
                bh[nt][1] = __float_as_uint(Bch[rn * 36 + 4]);
                bl[nt][0] = __float_as_uint(Bcl[rn * 36]);
                bl[nt][1] = __float_as_uint(Bcl[rn * 36 + 4]);
            }
#pragma unroll
            for (int mt = 0; mt < 2; mt++)
#pragma unroll
                for (int nt = 0; nt < 8; nt++) {
                    MMA_TF32(acc[mt][nt], ah[mt][0], ah[mt][1], ah[mt][2], ah[mt][3],
                             bh[nt][0], bh[nt][1]);
                    MMA_TF32(acc[mt][nt], al[mt][0], al[mt][1], al[mt][2], al[mt][3],
                             bh[nt][0], bh[nt][1]);
                    MMA_TF32(acc[mt][nt], ah[mt][0], ah[mt][1], ah[mt][2], ah[mt][3],
                             bl[nt][0], bl[nt][1]);
                }
        }
        __syncthreads();
    }

#pragma unroll
    for (int mt = 0; mt < 2; mt++) {
        const int r0 = bm + wm + mt * 16 + grp;
#pragma unroll
        for (int nt = 0; nt < 8; nt++) {
            const int col = bn + wn + nt * 8 + (qr << 1);
            float2 bb = *(const float2*)(bias + col);
            float v0 = acc[mt][nt][0] + bb.x;
            float v1 = acc[mt][nt][1] + bb.y;
            float v2 = acc[mt][nt][2] + bb.x;
            float v3 = acc[mt][nt][3] + bb.y;
            if (relu) {
                v0 = fmaxf(v0, 0.f); v1 = fmaxf(v1, 0.f);
                v2 = fmaxf(v2, 0.f); v3 = fmaxf(v3, 0.f);
            }
            if (res) {
                float2 ra = *(const float2*)(res + (size_t)r0 * N + col);
                float2 rb = *(const float2*)(res + (size_t)(r0 + 8) * N + col);
                v0 += ra.x; v1 += ra.y; v2 += rb.x; v3 += rb.y;
            }
            if (C) {
                *(float2*)(C + (size_t)r0 * N + col)       = make_float2(v0, v1);
                *(float2*)(C + (size_t)(r0 + 8) * N + col) = make_float2(v2, v3);
            }
            if (Ch) {
                float h0, l0, h1, l1, h2, l2, h3, l3;
                split_f(v0, h0, l0); split_f(v1, h1, l1);
                split_f(v2, h2, l2); split_f(v3, h3, l3);
                *(float2*)(Ch + (size_t)r0 * N + col)       = make_float2(h0, h1);
                *(float2*)(Cl + (size_t)r0 * N + col)       = make_float2(l0, l1);
                *(float2*)(Ch + (size_t)(r0 + 8) * N + col) = make_float2(h2, h3);
                *(float2*)(Cl + (size_t)(r0 + 8) * N + col) = make_float2(l2, l3);
            }
        }
    }
}

// ===========================================================================
// 1xTF32 GEMM with RNA rounding (MLP: W1, W2). A raw, B raw.
// Per-element error ~2^-12 unbiased; used only where accuracy budget allows.
// Stage: A 4608 + B 4608 = 9216 floats; 2 stages = 73728 B.
// ===========================================================================
#define G1_STAGE_FLOATS 9216
#define G1_SMEM_BYTES  (2 * G1_STAGE_FLOATS * 4)

__global__ __launch_bounds__(256, 2)
void gemm_tc1_kernel(const float* __restrict__ A, const float* __restrict__ Bw,
                     const float* __restrict__ bias, const float* __restrict__ res,
                     float* __restrict__ C, int M, int N, int Kd, int relu)
{
    extern __shared__ float sm[];
    const int tid  = threadIdx.x;
    const int wid  = tid >> 5;
    const int lane = tid & 31;
    const int grp  = lane >> 2;
    const int qr   = lane & 3;
    const int bm   = blockIdx.y << 7;
    const int bn   = blockIdx.x << 7;
    const uint32_t sbase = smem_u32(sm);

    uint32_t soff[4];
    const float* gA[4];
    const float* gB[4];
#pragma unroll
    for (int i = 0; i < 4; i++) {
        int idx = i * 256 + tid;
        int row = idx >> 3;
        int c4  = idx & 7;
        soff[i] = (uint32_t)(row * 36 + c4 * 4) * 4u;
        gA[i] = A  + (size_t)(bm + row) * Kd + (c4 << 2);
        gB[i] = Bw + (size_t)(bn + row) * Kd + (c4 << 2);
    }

    const int nc = Kd >> 5;

#pragma unroll
    for (int i = 0; i < 4; i++) {
        CP_ASYNC16(sbase + soff[i], gA[i]);
        CP_ASYNC16(sbase + 4608u * 4u + soff[i], gB[i]);
    }
    CP_COMMIT();

    const int wm = (wid & 3) << 5;
    const int wn = (wid >> 2) << 6;

    float acc[2][8][4];
#pragma unroll
    for (int mt = 0; mt < 2; mt++)
#pragma unroll
        for (int nt = 0; nt < 8; nt++)
#pragma unroll
            for (int r = 0; r < 4; r++) acc[mt][nt][r] = 0.f;

    for (int c = 0; c < nc; c++) {
        if (c + 1 < nc) {
            const int k1 = (c + 1) << 5;
            const uint32_t st = sbase + (uint32_t)((c + 1) & 1) * (G1_STAGE_FLOATS * 4u);
#pragma unroll
            for (int i = 0; i < 4; i++) {
                CP_ASYNC16(st + soff[i], gA[i] + k1);
                CP_ASYNC16(st + 4608u * 4u + soff[i], gB[i] + k1);
            }
            CP_COMMIT();
            CP_WAIT1();
        } else {
            CP_WAIT0();
        }
        __syncthreads();

        const float* Asb = sm + (c & 1) * G1_STAGE_FLOATS;
        const float* Bsb = Asb + 4608;
#pragma unroll
        for (int ks = 0; ks < 4; ks++) {
            const float* Ac = Asb + ks * 8 + qr;
            const float* Bc = Bsb + ks * 8 + qr;
            uint32_t a_[2][4];
#pragma unroll
            for (int mt = 0; mt < 2; mt++) {
                int r0 = wm + mt * 16 + grp;
                a_[mt][0] = f2tf(Ac[r0 * 36]);
                a_[mt][1] = f2tf(Ac[(r0 + 8) * 36]);
                a_[mt][2] = f2tf(Ac[r0 * 36 + 4]);
                a_[mt][3] = f2tf(Ac[(r0 + 8) * 36 + 4]);
            }
            uint32_t b_[8][2];
#pragma unroll
            for (int nt = 0; nt < 8; nt++) {
                int rn = wn + nt * 8 + grp;
                b_[nt][0] = f2tf(Bc[rn * 36]);
                b_[nt][1] = f2tf(Bc[rn * 36 + 4]);
            }
#pragma unroll
            for (int mt = 0; mt < 2; mt++)
#pragma unroll
                for (int nt = 0; nt < 8; nt++)
                    MMA_TF32(acc[mt][nt], a_[mt][0], a_[mt][1], a_[mt][2], a_[mt][3],
                             b_[nt][0], b_[nt][1]);
        }
        __syncthreads();
    }

#pragma unroll
    for (int mt = 0; mt < 2; mt++) {
        const int r0 = bm + wm + mt * 16 + grp;
#pragma unroll
        for (int nt = 0; nt < 8; nt++) {
            const int col = bn + wn + nt * 8 + (qr << 1);
            float2 bb = *(const float2*)(bias + col);
            float v0 = acc[mt][nt][0] + bb.x;
            float v1 = acc[mt][nt][1] + bb.y;
            float v2 = acc[mt][nt][2] + bb.x;
            float v3 = acc[mt][nt][3] + bb.y;
            if (relu) {
                v0 = fmaxf(v0, 0.f); v1 = fmaxf(v1, 0.f);
                v2 = fmaxf(v2, 0.f); v3 = fmaxf(v3, 0.f);
            }
            if (res) {
                float2 ra = *(const float2*)(res + (size_t)r0 * N + col);
                float2 rb = *(const float2*)(res + (size_t)(r0 + 8) * N + col);
                v0 += ra.x; v1 += ra.y; v2 += rb.x; v3 += rb.y;
            }
            *(float2*)(C + (size_t)r0 * N + col)       = make_float2(v0, v1);
            *(float2*)(C + (size_t)(r0 + 8) * N + col) = make_float2(v2, v3);
        }
    }
}

// ===========================================================================
// Scores: logits[h][i][j] = (Q_h[i].K_h[j])*0.125 + gb[i][j]  (3xTF32)
// ===========================================================================
__global__ __launch_bounds__(256, 2)
void tc_scores2_kernel(const float* __restrict__ q, const float* __restrict__ kh_,
                       const float* __restrict__ kl_, const float* __restrict__ gb,
                       float* __restrict__ logits)
{
    extern __shared__ float sm[];
    const int tid  = threadIdx.x;
    const int wid  = tid >> 5;
    const int lane = tid & 31;
    const int grp  = lane >> 2;
    const int qr   = lane & 3;
    const int h  = blockIdx.z;
    const int bt = h >> 3;
    const int kh = h & 7;
    const int bm = blockIdx.y << 7;
    const int bn = blockIdx.x << 7;
    const uint32_t sbase = smem_u32(sm);

    uint32_t soff[4];
    const float* gA[4];
    const float* gBh[4];
    const float* gBl[4];
#pragma unroll
    for (int i = 0; i < 4; i++) {
        int idx = i * 256 + tid;
        int row = idx >> 3;
        int c4  = idx & 7;
        soff[i] = (uint32_t)(row * 36 + c4 * 4) * 4u;
        gA[i]  = q   + (size_t)(bt * 512 + bm + row) * 512 + kh * 64 + (c4 << 2);
        gBh[i] = kh_ + (size_t)(bt * 512 + bn + row) * 512 + kh * 64 + (c4 << 2);
        gBl[i] = kl_ + (size_t)(bt * 512 + bn + row) * 512 + kh * 64 + (c4 << 2);
    }

#pragma unroll
    for (int i = 0; i < 4; i++) {
        CP_ASYNC16(sbase + soff[i], gA[i]);
        CP_ASYNC16(sbase + 4608u * 4u + soff[i], gBh[i]);
        CP_ASYNC16(sbase + 9216u * 4u + soff[i], gBl[i]);
    }
    CP_COMMIT();

    const int wm = (wid & 3) << 5;
    const int wn = (wid >> 2) << 6;

    float acc[2][8][4];
#pragma unroll
    for (int mt = 0; mt < 2; mt++)
#pragma unroll
        for (int nt = 0; nt < 8; nt++)
#pragma unroll
            for (int r = 0; r < 4; r++) acc[mt][nt][r] = 0.f;

#pragma unroll
    for (int c = 0; c < 2; c++) {
        if (c == 0) {
            const uint32_t st = sbase + (G2_STAGE_FLOATS * 4u);
#pragma unroll
            for (int i = 0; i < 4; i++) {
                CP_ASYNC16(st + soff[i], gA[i] + 32);
                CP_ASYNC16(st + 4608u * 4u + soff[i], gBh[i] + 32);
                CP_ASYNC16(st + 9216u * 4u + soff[i], gBl[i] + 32);
            }
            CP_COMMIT();
            CP_WAIT1();
        } else {
            CP_WAIT0();
        }
        __syncthreads();

        const float* Asb = sm + c * G2_STAGE_FLOATS;
        const float* Bhb = Asb + 4608;
        const float* Blb = Asb + 9216;
#pragma unroll
        for (int ks = 0; ks < 4; ks++) {
            const float* Ac  = Asb + ks * 8 + qr;
            const float* Bch = Bhb + ks * 8 + qr;
            const float* Bcl = Blb + ks * 8 + qr;
            uint32_t ah[2][4], al[2][4];
#pragma unroll
            for (int mt = 0; mt < 2; mt++) {
                int r0 = wm + mt * 16 + grp;
                split_tf32(Ac[r0 * 36],           ah[mt][0], al[mt][0]);
                split_tf32(Ac[(r0 + 8) * 36],     ah[mt][1], al[mt][1]);
                split_tf32(Ac[r0 * 36 + 4],       ah[mt][2], al[mt][2]);
                split_tf32(Ac[(r0 + 8) * 36 + 4], ah[mt][3], al[mt][3]);
            }
            uint32_t bh[8][2], bl[8][2];
#pragma unroll
            for (int nt = 0; nt < 8; nt++) {
                int rn = wn + nt * 8 + grp;
                bh[nt][0] = __float_as_uint(Bch[rn * 36]);
                bh[nt][1] = __float_as_uint(Bch[rn * 36 + 4]);
                bl[nt][0] = __float_as_uint(Bcl[rn * 36]);
                bl[nt][1] = __float_as_uint(Bcl[rn * 36 + 4]);
            }
#pragma unroll
            for (int mt = 0; mt < 2; mt++)
#pragma unroll
                for (int nt = 0; nt < 8; nt++) {
                    MMA_TF32(acc[mt][nt], ah[mt][0], ah[mt][1], ah[mt][2], ah[mt][3],
                             bh[nt][0], bh[nt][1]);
                    MMA_TF32(acc[mt][nt], al[mt][0], al[mt][1], al[mt][2], al[mt][3],
                             bh[nt][0], bh[nt][1]);
                    MMA_TF32(acc[mt][nt], ah[mt][0], ah[mt][1], ah[mt][2], ah[mt][3],
                             bl[nt][0], bl[nt][1]);
                }
        }
        __syncthreads();
    }

    float* Lh = logits + (size_t)h * 512 * 512;
#pragma unroll
    for (int mt = 0; mt < 2; mt++) {
        const int gi = bm + wm + mt * 16 + grp;
#pragma unroll
        for (int nt = 0; nt < 8; nt++) {
            const int gj = bn + wn + nt * 8 + (qr << 1);
            float2 g0 = *(const float2*)(gb + (size_t)gi * 512 + gj);
            float2 g1 = *(const float2*)(gb + (size_t)(gi + 8) * 512 + gj);
            float v0 = fmaf(acc[mt][nt][0], 0.125f, g0.x);
            float v1 = fmaf(acc[mt][nt][1], 0.125f, g0.y);
            float v2 = fmaf(acc[mt][nt][2], 0.125f, g1.x);
            float v3 = fmaf(acc[mt][nt][3], 0.125f, g1.y);
            *(float2*)(Lh + (size_t)gi * 512 + gj)       = make_float2(v0, v1);
            *(float2*)(Lh + (size_t)(gi + 8) * 512 + gj) = make_float2(v2, v3);
        }
    }
}

// ===========================================================================
// AV: out_h = P_h @ V_h  (3xTF32, V pre-split, transposed staging)
// ===========================================================================
#define AV2_STAGE_FLOATS 9216
#define AV2_SMEM_BYTES  (2 * AV2_STAGE_FLOATS * 4)

__global__ __launch_bounds__(256, 2)
void tc_av2_kernel(const float* __restrict__ attn, const float* __restrict__ vh_,
                   const float* __restrict__ vl_, float* __restrict__ out)
{
    extern __shared__ float sm[];
    const int tid  = threadIdx.x;
    const int wid  = tid >> 5;
    const int lane = tid & 31;
    const int grp  = lane >> 2;
    const int qr   = lane & 3;
    const int h  = blockIdx.y;
    const int bt = h >> 3;
    const int kh = h & 7;
    const int bm = blockIdx.x << 7;

    int arow[4], ac4[4];
#pragma unroll
    for (int i = 0; i < 4; i++) {
        int idx = i * 256 + tid;
        arow[i] = idx >> 3;
        ac4[i]  = (idx & 7) << 2;
    }
    int bk_[2], bn4[2];
#pragma unroll
    for (int i = 0; i < 2; i++) {
        int idx = i * 256 + tid;
        bk_[i] = idx >> 4;
        bn4[i] = (idx & 15) << 2;
    }

    const float* Abase  = attn + (size_t)(h * 512 + bm) * 512;
    const float* Vhbase = vh_ + (size_t)(bt * 512) * 512 + kh * 64;
    const float* Vlbase = vl_ + (size_t)(bt * 512) * 512 + kh * 64;

    float4 ra[4], rbh[2], rbl[2];
#pragma unroll
    for (int i = 0; i < 4; i++)
        ra[i] = *(const float4*)(Abase + (size_t)arow[i] * 512 + ac4[i]);
#pragma unroll
    for (int i = 0; i < 2; i++) {
        rbh[i] = *(const float4*)(Vhbase + (size_t)bk_[i] * 512 + bn4[i]);
        rbl[i] = *(const float4*)(Vlbase + (size_t)bk_[i] * 512 + bn4[i]);
    }

    const int wm = (wid & 3) << 5;
    const int wn = (wid >> 2) << 5;

    float acc[2][4][4];
#pragma unroll
    for (int mt = 0; mt < 2; mt++)
#pragma unroll
        for (int nt = 0; nt < 4; nt++)
#pragma unroll
            for (int r = 0; r < 4; r++) acc[mt][nt][r] = 0.f;

    for (int c = 0; c < 16; c++) {
        float* Asb = sm + (c & 1) * AV2_STAGE_FLOATS;
        float* Bhb = Asb + 4608;
        float* Blb = Asb + 6912;
#pragma unroll
        for (int i = 0; i < 4; i++) {
            float* p = Asb + arow[i] * 36 + ac4[i];
            p[0] = ra[i].x; p[1] = ra[i].y; p[2] = ra[i].z; p[3] = ra[i].w;
        }
#pragma unroll
        for (int i = 0; i < 2; i++) {
            Bhb[(bn4[i] + 0) * 36 + bk_[i]] = rbh[i].x;
            Bhb[(bn4[i] + 1) * 36 + bk_[i]] = rbh[i].y;
            Bhb[(bn4[i] + 2) * 36 + bk_[i]] = rbh[i].z;
            Bhb[(bn4[i] + 3) * 36 + bk_[i]] = rbh[i].w;
            Blb[(bn4[i] + 0) * 36 + bk_[i]] = rbl[i].x;
            Blb[(bn4[i] + 1) * 36 + bk_[i]] = rbl[i].y;
            Blb[(bn4[i] + 2) * 36 + bk_[i]] = rbl[i].z;
            Blb[(bn4[i] + 3) * 36 + bk_[i]] = rbl[i].w;
        }
        __syncthreads();
        if (c + 1 < 16) {
            const int k1 = (c + 1) << 5;
#pragma unroll
            for (int i = 0; i < 4; i++)
                ra[i] = *(const float4*)(Abase + (size_t)arow[i] * 512 + k1 + ac4[i]);
#pragma unroll
            for (int i = 0; i < 2; i++) {
                rbh[i] = *(const float4*)(Vhbase + (size_t)(k1 + bk_[i]) * 512 + bn4[i]);
                rbl[i] = *(const float4*)(Vlbase + (size_t)(k1 + bk_[i]) * 512 + bn4[i]);
            }
        }
#pragma unroll
        for (int ks = 0; ks < 4; ks++) {
            const float* Ac  = Asb + ks * 8 + qr;
            const float* Bch = Bhb + ks * 8 + qr;
            const float* Bcl = Blb + ks * 8 + qr;
            uint32_t ah[2][4], al[2][4];
#pragma unroll
            for (int mt = 0; mt < 2; mt++) {
                int r0 = wm + mt * 16 + grp;
                split_tf32(Ac[r0 * 36],           ah[mt][0], al[mt][0]);
                split_tf32(Ac[(r0 + 8) * 36],     ah[mt][1], al[mt][1]);
                split_tf32(Ac[r0 * 36 + 4],       ah[mt][2], al[mt][2]);
                split_tf32(Ac[(r0 + 8) * 36 + 4], ah[mt][3], al[mt][3]);
            }
            uint32_t bh[4][2], bl[4][2];
#pragma unroll
            for (int nt = 0; nt < 4; nt++) {
                int rn = wn + nt * 8 + grp;
                bh[nt][0] = __float_as_uint(Bch[rn * 36]);
                bh[nt][1] = __float_as_uint(Bch[rn * 36 + 4]);
                bl[nt][0] = __float_as_uint(Bcl[rn * 36]);
                bl[nt][1] = __float_as_uint(Bcl[rn * 36 + 4]);
            }
#pragma unroll
            for (int mt = 0; mt < 2; mt++)
#pragma unroll
                for (int nt = 0; nt < 4; nt++) {
                    MMA_TF32(acc[mt][nt], ah[mt][0], ah[mt][1], ah[mt][2], ah[mt][3],
                             bh[nt][0], bh[nt][1]);
                    MMA_TF32(acc[mt][nt], al[mt][0], al[mt][1], al[mt][2], al[mt][3],
                             bh[nt][0], bh[nt][1]);
                    MMA_TF32(acc[mt][nt], ah[mt][0], ah[mt][1], ah[mt][2], ah[mt][3],
                             bl[nt][0], bl[nt][1]);
                }
        }
        __syncthreads();
    }

#pragma unroll
    for (int mt = 0; mt < 2; mt++) {
        const int r0 = bt * 512 + bm + wm + mt * 16 + grp;
#pragma unroll
        for (int nt = 0; nt < 4; nt++) {
            const int col = kh * 64 + wn + nt * 8 + (qr << 1);
            *(float2*)(out + (size_t)r0 * 512 + col) =
                make_float2(acc[mt][nt][0], acc[mt][nt][1]);
            *(float2*)(out + (size_t)(r0 + 8) * 512 + col) =
                make_float2(acc[mt][nt][2], acc[mt][nt][3]);
        }
    }
}

// ---------------------------------------------------------------------------
// Graph bias precompute
// ---------------------------------------------------------------------------
__global__ __launch_bounds__(256) void bias_kernel(
    const float* __restrict__ E, const float* __restrict__ lap,
    const float* __restrict__ alphap, const float* __restrict__ betap,
    float* __restrict__ gb)
{
    __shared__ __align__(16) float ei[64];
    __shared__ float reda[8];
    __shared__ float redb[8];
    int i = blockIdx.x;
    int tid = threadIdx.x;
    if (tid < 16) ((float4*)ei)[tid] = ((const float4*)(E + (size_t)i * 64))[tid];
    __syncthreads();

    int j0 = tid, j1 = tid + 256;
    const float* e0 = E + (size_t)j0 * 64;
    const float* e1 = E + (size_t)j1 * 64;
    float r0 = 0.f, r1 = 0.f;
#pragma unroll
    for (int e = 0; e < 64; e += 4) {
        float4 a = *(const float4*)(ei + e);
        float4 u = *(const float4*)(e0 + e);
        float4 w = *(const float4*)(e1 + e);
        r0 += a.x * u.x + a.y * u.y + a.z * u.z + a.w * u.w;
        r1 += a.x * w.x + a.y * w.y + a.z * w.z + a.w * w.w;
    }
    r0 = fmaxf(r0, 0.f);
    r1 = fmaxf(r1, 0.f);

    float mx = fmaxf(r0, r1);
#pragma unroll
    for (int o = 16; o; o >>= 1) mx = fmaxf(mx, __shfl_xor_sync(0xffffffffu, mx, o));
    if ((tid & 31) == 0) reda[tid >> 5] = mx;
    __syncthreads();
    mx = fmaxf(fmaxf(fmaxf(reda[0], reda[1]), fmaxf(reda[2], reda[3])),
               fmaxf(fmaxf(reda[4], reda[5]), fmaxf(reda[6], reda[7])));

    float ex0 = __expf(r0 - mx), ex1 = __expf(r1 - mx);
    float s = ex0 + ex1;
#pragma unroll
    for (int o = 16; o; o >>= 1) s += __shfl_xor_sync(0xffffffffu, s, o);
    if ((tid & 31) == 0) redb[tid >> 5] = s;
    __syncthreads();
    s = redb[0] + redb[1] + redb[2] + redb[3] + redb[4] + redb[5] + redb[6] + redb[7];
    float inv = 1.0f / s;

    float alpha = *alphap, beta = *betap;
    float lp0 = lap[(size_t)i * 512 + j0];
    float lp1 = lap[(size_t)i * 512 + j1];
    float m0 = (lp0 != 0.f) ? 0.f : -1e9f;
    float m1 = (lp1 != 0.f) ? 0.f : -1e9f;
    gb[(size_t)i * 512 + j0] = alpha * ex0 * inv + beta * lp0 + m0;
    gb[(size_t)i * 512 + j1] = alpha * ex1 * inv + beta * lp1 + m1;
}

// ---------------------------------------------------------------------------
// LayerNorm over D=512. One warp per row.
// ---------------------------------------------------------------------------
__global__ __launch_bounds__(256) void ln_kernel(
    const float* __restrict__ X, const float* __restrict__ g,
    const float* __restrict__ b, float* __restrict__ Y, int rows)
{
    int gw = (blockIdx.x * 256 + threadIdx.x) >> 5;
    if (gw >= rows) return;
    int lane = threadIdx.x & 31;
    const float* xr = X + (size_t)gw * 512;
    float* yr = Y + (size_t)gw * 512;
    float4 v[4];
    float s = 0.f, ss = 0.f;
#pragma unroll
    for (int w = 0; w < 4; w++) {
        v[w] = *(const float4*)(xr + w * 128 + lane * 4);
        s += v[w].x + v[w].y + v[w].z + v[w].w;
        ss += v[w].x * v[w].x + v[w].y * v[w].y + v[w].z * v[w].z + v[w].w * v[w].w;
    }
#pragma unroll
    for (int o = 16; o; o >>= 1) {
        s += __shfl_xor_sync(0xffffffffu, s, o);
        ss += __shfl_xor_sync(0xffffffffu, ss, o);
    }
    float mean = s * (1.0f / 512.0f);
    float var = ss * (1.0f / 512.0f) - mean * mean;
    float rstd = rsqrtf(var + 1e-5f);
#pragma unroll
    for (int w = 0; w < 4; w++) {
        int c = w * 128 + lane * 4;
        float4 gg = *(const float4*)(g + c);
        float4 bb = *(const float4*)(b + c);
        float4 o;
        o.x = (v[w].x - mean) * rstd * gg.x + bb.x;
        o.y = (v[w].y - mean) * rstd * gg.y + bb.y;
        o.z = (v[w].z - mean) * rstd * gg.z + bb.z;
        o.w = (v[w].w - mean) * rstd * gg.w + bb.w;
        *(float4*)(yr + c) = o;
    }
}

// ---------------------------------------------------------------------------
// Row softmax, in place
// ---------------------------------------------------------------------------
__global__ __launch_bounds__(256) void softmax_kernel(float* __restrict__ L, int rows)
{
    int r = (blockIdx.x * 256 + threadIdx.x) >> 5;
    if (r >= rows) return;
    int lane = threadIdx.x & 31;
    float* row = L + (size_t)r * 512;
    float4 v[4];
    float mx = -3.0e38f;
#pragma unroll
    for (int w = 0; w < 4; w++) {
        v[w] = *(const float4*)(row + w * 128 + lane * 4);
        mx = fmaxf(mx, fmaxf(fmaxf(v[w].x, v[w].y), fmaxf(v[w].z, v[w].w)));
    }
#pragma unroll
    for (int o = 16; o; o >>= 1) mx = fmaxf(mx, __shfl_xor_sync(0xffffffffu, mx, o));
    float s = 0.f;
#pragma unroll
    for (int w = 0; w < 4; w++) {
        v[w].x = __expf(v[w].x - mx);
        v[w].y = __expf(v[w].y - mx);
        v[w].z = __expf(v[w].z - mx);
        v[w].w = __expf(v[w].w - mx);
        s += v[w].x + v[w].y + v[w].z + v[w].w;
    }
#pragma unroll
    for (int o = 16; o; o >>= 1) s += __shfl_xor_sync(0xffffffffu, s, o);
    float inv = 1.0f / s;
#pragma unroll
    for (int w = 0; w < 4; w++) {
        v[w].x *= inv; v[w].y *= inv; v[w].z *= inv; v[w].w *= inv;
        *(float4*)(row + w * 128 + lane * 4) = v[w];
    }
}

// ---------------------------------------------------------------------------
// Host launcher
// ---------------------------------------------------------------------------
extern "C" void kernel_launch(void* const* d_in, const int* in_sizes, int n_in,
                              void* d_out, int out_size)
{
    const float* x    = (const float*)d_in[0];
    const float* lap  = (const float*)d_in[1];
    const float* emb  = (const float*)d_in[2];
    const float* Wq   = (const float*)d_in[3];
    const float* bq   = (const float*)d_in[4];
    const float* Wk   = (const float*)d_in[5];
    const float* bk   = (const float*)d_in[6];
    const float* Wv   = (const float*)d_in[7];
    const float* bv   = (const float*)d_in[8];
    const float* ln1g = (const float*)d_in[9];
    const float* ln1b = (const float*)d_in[10];
    const float* ln2g = (const float*)d_in[11];
    const float* ln2b = (const float*)d_in[12];
    const float* alpha = (const float*)d_in[13];
    const float* beta  = (const float*)d_in[14];
    const float* Wo   = (const float*)d_in[15];
    const float* bo   = (const float*)d_in[16];
    const float* W1   = (const float*)d_in[17];
    const float* b1   = (const float*)d_in[18];
    const float* W2   = (const float*)d_in[19];
    const float* b2   = (const float*)d_in[20];
    float* out = (float*)d_out;

    float* base = nullptr;
    cudaGetSymbolAddress((void**)&base, g_scratch);
    float* xn     = base + OFF_XN;
    float* q      = base + OFF_Q;
    float* k_h    = base + OFF_KH;
    float* k_l    = base + OFF_KL;
    float* v_h    = base + OFF_VH;
    float* v_l    = base + OFF_VL;
    float* ao     = base + OFF_AO;
    float* x1     = base + OFF_X1;
    float* hin    = base + OFF_HIN;
    float* hbuf   = base + OFF_HB;
    float* logits = base + OFF_LOG;
    float* gb     = base + OFF_GB;
    float* wqh = base + OFF_WQH; float* wql = base + OFF_WQL;
    float* wkh = base + OFF_WKH; float* wkl = base + OFF_WKL;
    float* wvh = base + OFF_WVH; float* wvl = base + OFF_WVL;
    float* woh = base + OFF_WOH; float* wol = base + OFF_WOL;

    static bool attr_done = false;
    if (!attr_done) {
        cudaFuncSetAttribute(gemm_tc2_kernel,
                             cudaFuncAttributeMaxDynamicSharedMemorySize, G2_SMEM_BYTES);
        cudaFuncSetAttribute(gemm_tc1_kernel,
                             cudaFuncAttributeMaxDynamicSharedMemorySize, G1_SMEM_BYTES);
        cudaFuncSetAttribute(tc_scores2_kernel,
                             cudaFuncAttributeMaxDynamicSharedMemorySize, G2_SMEM_BYTES);
        cudaFuncSetAttribute(tc_av2_kernel,
                             cudaFuncAttributeMaxDynamicSharedMemorySize, AV2_SMEM_BYTES);
        attr_done = true;
    }

    // 0. weight pre-splits (attention-path weights only)
    split_kernel<<<256, 256>>>(Wq, wqh, wql, 65536);
    split_kernel<<<256, 256>>>(Wk, wkh, wkl, 65536);
    split_kernel<<<256, 256>>>(Wv, wvh, wvl, 65536);
    split_kernel<<<256, 256>>>(Wo, woh, wol, 65536);

    // 1. graph bias
    bias_kernel<<<512, 256>>>(emb, lap, alpha, beta, gb);

    // 2. LN1
    ln_kernel<<<R_ROWS / 8, 256>>>(x, ln1g, ln1b, xn, R_ROWS);

    // 3. QKV projections (3xTF32). K,V epilogue-split for attention.
    dim3 gq(D_DIM / 128, R_ROWS / 128);
    gemm_tc2_kernel<<<gq, 256, G2_SMEM_BYTES>>>(
        xn, wqh, wql, bq, nullptr, q, nullptr, nullptr, R_ROWS, D_DIM, D_DIM, 0);
    gemm_tc2_kernel<<<gq, 256, G2_SMEM_BYTES>>>(
        xn, wkh, wkl, bk, nullptr, nullptr, k_h, k_l, R_ROWS, D_DIM, D_DIM, 0);
    gemm_tc2_kernel<<<gq, 256, G2_SMEM_BYTES>>>(
        xn, wvh, wvl, bv, nullptr, nullptr, v_h, v_l, R_ROWS, D_DIM, D_DIM, 0);

    // 4. scores + bias (3xTF32)
    tc_scores2_kernel<<<dim3(4, 4, H_HEADS), 256, G2_SMEM_BYTES>>>(q, k_h, k_l, gb, logits);

    // 5. softmax
    softmax_kernel<<<(H_HEADS * N_NODES) / 8, 256>>>(logits, H_HEADS * N_NODES);

    // 6. attn @ V (3xTF32)
    tc_av2_kernel<<<dim3(4, H_HEADS), 256, AV2_SMEM_BYTES>>>(logits, v_h, v_l, ao);

    // 7. output projection + residual (3xTF32)
    gemm_tc2_kernel<<<gq, 256, G2_SMEM_BYTES>>>(
        ao, woh, wol, bo, x, x1, nullptr, nullptr, R_ROWS, D_DIM, D_DIM, 0);

    // 8. LN2
    ln_kernel<<<R_ROWS / 8, 256>>>(x1, ln2g, ln2b, hin, R_ROWS);

    // 9. FF up (1xTF32-RNA, relu)
    gemm_tc1_kernel<<<dim3(DFF / 128, R_ROWS / 128), 256, G1_SMEM_BYTES>>>(
        hin, W1, b1, nullptr, hbuf, R_ROWS, DFF, D_DIM, 1);

    // 10. FF down + residual (1xTF32-RNA)
    gemm_tc1_kernel<<<dim3(D_DIM / 128, R_ROWS / 128), 256, G1_SMEM_BYTES>>>(
        hbuf, W2, b2, x1, out, R_ROWS, D_DIM, DFF, 0);
}

// round 8
// speedup vs baseline: 2.6162x; 1.2371x over previous
#include <cuda_runtime.h>
#include <cstdint>

// ---------------------------------------------------------------------------
// Problem constants
// ---------------------------------------------------------------------------
#define R_ROWS 16384
#define N_NODES 512
#define D_DIM 512
#define H_HEADS 256
#define DFF 2048

// Scratch layout (float offsets)
#define OFF_XN   0ull
#define OFF_Q    8388608ull
#define OFF_KH   16777216ull
#define OFF_KL   25165824ull
#define OFF_VH   33554432ull
#define OFF_VL   41943040ull
#define OFF_AO   50331648ull
#define OFF_X1   58720256ull
#define OFF_HIN  67108864ull
#define OFF_HB   75497472ull
#define OFF_LOG  109051904ull
#define OFF_GB   176160768ull

__device__ float g_scratch[182714368];

// ===========================================================================
// Helpers
// ===========================================================================
__device__ __forceinline__ uint32_t smem_u32(const void* p) {
    uint32_t a;
    asm("{ .reg .u64 t; cvta.to.shared.u64 t, %1; cvt.u32.u64 %0, t; }"
        : "=r"(a) : "l"(p));
    return a;
}

#define CP_ASYNC16(dst, src) \
    asm volatile("cp.async.cg.shared.global [%0], [%1], 16;" :: "r"(dst), "l"(src))
#define CP_COMMIT() asm volatile("cp.async.commit_group;" ::: "memory")
#define CP_WAIT1()  asm volatile("cp.async.wait_group 1;" ::: "memory")
#define CP_WAIT0()  asm volatile("cp.async.wait_group 0;" ::: "memory")

#define MMA_TF32(d, a0, a1, a2, a3, b0, b1) \
    asm volatile("mma.sync.aligned.m16n8k8.row.col.f32.tf32.tf32.f32 " \
        "{%0,%1,%2,%3}, {%4,%5,%6,%7}, {%8,%9}, {%0,%1,%2,%3};" \
        : "+f"((d)[0]), "+f"((d)[1]), "+f"((d)[2]), "+f"((d)[3]) \
        : "r"(a0), "r"(a1), "r"(a2), "r"(a3), "r"(b0), "r"(b1))

__device__ __forceinline__ void split_tf32(float x, uint32_t& hi, uint32_t& lo) {
    uint32_t h;
    asm("cvt.rna.tf32.f32 %0, %1;" : "=r"(h) : "f"(x));
    float l = x - __uint_as_float(h);
    uint32_t lb;
    asm("cvt.rna.tf32.f32 %0, %1;" : "=r"(lb) : "f"(l));
    hi = h; lo = lb;
}
__device__ __forceinline__ void split_f(float x, float& h, float& l) {
    uint32_t a, b;
    split_tf32(x, a, b);
    h = __uint_as_float(a); l = __uint_as_float(b);
}
__device__ __forceinline__ uint32_t f2tf(float x) {
    uint32_t r;
    asm("cvt.rna.tf32.f32 %0, %1;" : "=r"(r) : "f"(x));
    return r;
}

// ===========================================================================
// 1xTF32-RNA GEMM (QKV / Wo / W1 / W2): C = A @ B^T + bias (+relu)(+res)
// Optional split outputs (Ch, Cl) for downstream 3x consumers (K, V).
// CTA 128x128, 8 warps (4m x 2n), BK=32, cp.async double-buffered.
// ===========================================================================
#define G1_STAGE_FLOATS 9216
#define G1_SMEM_BYTES  (2 * G1_STAGE_FLOATS * 4)

__global__ __launch_bounds__(256, 2)
void gemm_tc1_kernel(const float* __restrict__ A, const float* __restrict__ Bw,
                     const float* __restrict__ bias, const float* __restrict__ res,
                     float* __restrict__ C, float* __restrict__ Ch, float* __restrict__ Cl,
                     int M, int N, int Kd, int relu)
{
    extern __shared__ float sm[];
    const int tid  = threadIdx.x;
    const int wid  = tid >> 5;
    const int lane = tid & 31;
    const int grp  = lane >> 2;
    const int qr   = lane & 3;
    const int bm   = blockIdx.y << 7;
    const int bn   = blockIdx.x << 7;
    const uint32_t sbase = smem_u32(sm);

    uint32_t soff[4];
    const float* gA[4];
    const float* gB[4];
#pragma unroll
    for (int i = 0; i < 4; i++) {
        int idx = i * 256 + tid;
        int row = idx >> 3;
        int c4  = idx & 7;
        soff[i] = (uint32_t)(row * 36 + c4 * 4) * 4u;
        gA[i] = A  + (size_t)(bm + row) * Kd + (c4 << 2);
        gB[i] = Bw + (size_t)(bn + row) * Kd + (c4 << 2);
    }

    const int nc = Kd >> 5;

#pragma unroll
    for (int i = 0; i < 4; i++) {
        CP_ASYNC16(sbase + soff[i], gA[i]);
        CP_ASYNC16(sbase + 4608u * 4u + soff[i], gB[i]);
    }
    CP_COMMIT();

    const int wm = (wid & 3) << 5;
    const int wn = (wid >> 2) << 6;

    float acc[2][8][4];
#pragma unroll
    for (int mt = 0; mt < 2; mt++)
#pragma unroll
        for (int nt = 0; nt < 8; nt++)
#pragma unroll
            for (int r = 0; r < 4; r++) acc[mt][nt][r] = 0.f;

    for (int c = 0; c < nc; c++) {
        if (c + 1 < nc) {
            const int k1 = (c + 1) << 5;
            const uint32_t st = sbase + (uint32_t)((c + 1) & 1) * (G1_STAGE_FLOATS * 4u);
#pragma unroll
            for (int i = 0; i < 4; i++) {
                CP_ASYNC16(st + soff[i], gA[i] + k1);
                CP_ASYNC16(st + 4608u * 4u + soff[i], gB[i] + k1);
            }
            CP_COMMIT();
            CP_WAIT1();
        } else {
            CP_WAIT0();
        }
        __syncthreads();

        const float* Asb = sm + (c & 1) * G1_STAGE_FLOATS;
        const float* Bsb = Asb + 4608;
#pragma unroll
        for (int ks = 0; ks < 4; ks++) {
            const float* Ac = Asb + ks * 8 + qr;
            const float* Bc = Bsb + ks * 8 + qr;
            uint32_t a_[2][4];
#pragma unroll
            for (int mt = 0; mt < 2; mt++) {
                int r0 = wm + mt * 16 + grp;
                a_[mt][0] = f2tf(Ac[r0 * 36]);
                a_[mt][1] = f2tf(Ac[(r0 + 8) * 36]);
                a_[mt][2] = f2tf(Ac[r0 * 36 + 4]);
                a_[mt][3] = f2tf(Ac[(r0 + 8) * 36 + 4]);
            }
            uint32_t b_[8][2];
#pragma unroll
            for (int nt = 0; nt < 8; nt++) {
                int rn = wn + nt * 8 + grp;
                b_[nt][0] = f2tf(Bc[rn * 36]);
                b_[nt][1] = f2tf(Bc[rn * 36 + 4]);
            }
#pragma unroll
            for (int mt = 0; mt < 2; mt++)
#pragma unroll
                for (int nt = 0; nt < 8; nt++)
                    MMA_TF32(acc[mt][nt], a_[mt][0], a_[mt][1], a_[mt][2], a_[mt][3],
                             b_[nt][0], b_[nt][1]);
        }
        __syncthreads();
    }

#pragma unroll
    for (int mt = 0; mt < 2; mt++) {
        const int r0 = bm + wm + mt * 16 + grp;
#pragma unroll
        for (int nt = 0; nt < 8; nt++) {
            const int col = bn + wn + nt * 8 + (qr << 1);
            float2 bb = *(const float2*)(bias + col);
            float v0 = acc[mt][nt][0] + bb.x;
            float v1 = acc[mt][nt][1] + bb.y;
            float v2 = acc[mt][nt][2] + bb.x;
            float v3 = acc[mt][nt][3] + bb.y;
            if (relu) {
                v0 = fmaxf(v0, 0.f); v1 = fmaxf(v1, 0.f);
                v2 = fmaxf(v2, 0.f); v3 = fmaxf(v3, 0.f);
            }
            if (res) {
                float2 ra = *(const float2*)(res + (size_t)r0 * N + col);
                float2 rb = *(const float2*)(res + (size_t)(r0 + 8) * N + col);
                v0 += ra.x; v1 += ra.y; v2 += rb.x; v3 += rb.y;
            }
            if (C) {
                *(float2*)(C + (size_t)r0 * N + col)       = make_float2(v0, v1);
                *(float2*)(C + (size_t)(r0 + 8) * N + col) = make_float2(v2, v3);
            }
            if (Ch) {
                float h0, l0, h1, l1, h2, l2, h3, l3;
                split_f(v0, h0, l0); split_f(v1, h1, l1);
                split_f(v2, h2, l2); split_f(v3, h3, l3);
                *(float2*)(Ch + (size_t)r0 * N + col)       = make_float2(h0, h1);
                *(float2*)(Cl + (size_t)r0 * N + col)       = make_float2(l0, l1);
                *(float2*)(Ch + (size_t)(r0 + 8) * N + col) = make_float2(h2, h3);
                *(float2*)(Cl + (size_t)(r0 + 8) * N + col) = make_float2(l2, l3);
            }
        }
    }
}

// ===========================================================================
// Scores (3xTF32): logits[h][i][j] = (Q_h[i].K_h[j])*0.125 + gb[i][j]
// A = q raw (in-loop split); B = (k_h, k_l) pre-split. K=64 (2 chunks).
// ===========================================================================
#define G2_STAGE_FLOATS 13824
#define G2_SMEM_BYTES  (2 * G2_STAGE_FLOATS * 4)

__global__ __launch_bounds__(256, 2)
void tc_scores2_kernel(const float* __restrict__ q, const float* __restrict__ kh_,
                       const float* __restrict__ kl_, const float* __restrict__ gb,
                       float* __restrict__ logits)
{
    extern __shared__ float sm[];
    const int tid  = threadIdx.x;
    const int wid  = tid >> 5;
    const int lane = tid & 31;
    const int grp  = lane >> 2;
    const int qr   = lane & 3;
    const int h  = blockIdx.z;
    const int bt = h >> 3;
    const int kh = h & 7;
    const int bm = blockIdx.y << 7;
    const int bn = blockIdx.x << 7;
    const uint32_t sbase = smem_u32(sm);

    uint32_t soff[4];
    const float* gA[4];
    const float* gBh[4];
    const float* gBl[4];
#pragma unroll
    for (int i = 0; i < 4; i++) {
        int idx = i * 256 + tid;
        int row = idx >> 3;
        int c4  = idx & 7;
        soff[i] = (uint32_t)(row * 36 + c4 * 4) * 4u;
        gA[i]  = q   + (size_t)(bt * 512 + bm + row) * 512 + kh * 64 + (c4 << 2);
        gBh[i] = kh_ + (size_t)(bt * 512 + bn + row) * 512 + kh * 64 + (c4 << 2);
        gBl[i] = kl_ + (size_t)(bt * 512 + bn + row) * 512 + kh * 64 + (c4 << 2);
    }

#pragma unroll
    for (int i = 0; i < 4; i++) {
        CP_ASYNC16(sbase + soff[i], gA[i]);
        CP_ASYNC16(sbase + 4608u * 4u + soff[i], gBh[i]);
        CP_ASYNC16(sbase + 9216u * 4u + soff[i], gBl[i]);
    }
    CP_COMMIT();

    const int wm = (wid & 3) << 5;
    const int wn = (wid >> 2) << 6;

    float acc[2][8][4];
#pragma unroll
    for (int mt = 0; mt < 2; mt++)
#pragma unroll
        for (int nt = 0; nt < 8; nt++)
#pragma unroll
            for (int r = 0; r < 4; r++) acc[mt][nt][r] = 0.f;

#pragma unroll
    for (int c = 0; c < 2; c++) {
        if (c == 0) {
            const uint32_t st = sbase + (G2_STAGE_FLOATS * 4u);
#pragma unroll
            for (int i = 0; i < 4; i++) {
                CP_ASYNC16(st + soff[i], gA[i] + 32);
                CP_ASYNC16(st + 4608u * 4u + soff[i], gBh[i] + 32);
                CP_ASYNC16(st + 9216u * 4u + soff[i], gBl[i] + 32);
            }
            CP_COMMIT();
            CP_WAIT1();
        } else {
            CP_WAIT0();
        }
        __syncthreads();

        const float* Asb = sm + c * G2_STAGE_FLOATS;
        const float* Bhb = Asb + 4608;
        const float* Blb = Asb + 9216;
#pragma unroll
        for (int ks = 0; ks < 4; ks++) {
            const float* Ac  = Asb + ks * 8 + qr;
            const float* Bch = Bhb + ks * 8 + qr;
            const float* Bcl = Blb + ks * 8 + qr;
            uint32_t ah[2][4], al[2][4];
#pragma unroll
            for (int mt = 0; mt < 2; mt++) {
                int r0 = wm + mt * 16 + grp;
                split_tf32(Ac[r0 * 36],           ah[mt][0], al[mt][0]);
                split_tf32(Ac[(r0 + 8) * 36],     ah[mt][1], al[mt][1]);
                split_tf32(Ac[r0 * 36 + 4],       ah[mt][2], al[mt][2]);
                split_tf32(Ac[(r0 + 8) * 36 + 4], ah[mt][3], al[mt][3]);
            }
            uint32_t bh[8][2], bl[8][2];
#pragma unroll
            for (int nt = 0; nt < 8; nt++) {
                int rn = wn + nt * 8 + grp;
                bh[nt][0] = __float_as_uint(Bch[rn * 36]);
                bh[nt][1] = __float_as_uint(Bch[rn * 36 + 4]);
                bl[nt][0] = __float_as_uint(Bcl[rn * 36]);
                bl[nt][1] = __float_as_uint(Bcl[rn * 36 + 4]);
            }
#pragma unroll
            for (int mt = 0; mt < 2; mt++)
#pragma unroll
                for (int nt = 0; nt < 8; nt++) {
                    MMA_TF32(acc[mt][nt], ah[mt][0], ah[mt][1], ah[mt][2], ah[mt][3],
                             bh[nt][0], bh[nt][1]);
                    MMA_TF32(acc[mt][nt], al[mt][0], al[mt][1], al[mt][2], al[mt][3],
                             bh[nt][0], bh[nt][1]);
                    MMA_TF32(acc[mt][nt], ah[mt][0], ah[mt][1], ah[mt][2], ah[mt][3],
                             bl[nt][0], bl[nt][1]);
                }
        }
        __syncthreads();
    }

    float* Lh = logits + (size_t)h * 512 * 512;
#pragma unroll
    for (int mt = 0; mt < 2; mt++) {
        const int gi = bm + wm + mt * 16 + grp;
#pragma unroll
        for (int nt = 0; nt < 8; nt++) {
            const int gj = bn + wn + nt * 8 + (qr << 1);
            float2 g0 = *(const float2*)(gb + (size_t)gi * 512 + gj);
            float2 g1 = *(const float2*)(gb + (size_t)(gi + 8) * 512 + gj);
            float v0 = fmaf(acc[mt][nt][0], 0.125f, g0.x);
            float v1 = fmaf(acc[mt][nt][1], 0.125f, g0.y);
            float v2 = fmaf(acc[mt][nt][2], 0.125f, g1.x);
            float v3 = fmaf(acc[mt][nt][3], 0.125f, g1.y);
            *(float2*)(Lh + (size_t)gi * 512 + gj)       = make_float2(v0, v1);
            *(float2*)(Lh + (size_t)(gi + 8) * 512 + gj) = make_float2(v2, v3);
        }
    }
}

// ===========================================================================
// AV (3xTF32): out_h = P_h @ V_h.  V pre-split (from projection epilogue),
// transposed staging. BM=128, BN=64, K=512, 16 chunks.
// ===========================================================================
#define AV2_STAGE_FLOATS 9216
#define AV2_SMEM_BYTES  (2 * AV2_STAGE_FLOATS * 4)

__global__ __launch_bounds__(256, 2)
void tc_av2_kernel(const float* __restrict__ attn, const float* __restrict__ vh_,
                   const float* __restrict__ vl_, float* __restrict__ out)
{
    extern __shared__ float sm[];
    const int tid  = threadIdx.x;
    const int wid  = tid >> 5;
    const int lane = tid & 31;
    const int grp  = lane >> 2;
    const int qr   = lane & 3;
    const int h  = blockIdx.y;
    const int bt = h >> 3;
    const int kh = h & 7;
    const int bm = blockIdx.x << 7;

    int arow[4], ac4[4];
#pragma unroll
    for (int i = 0; i < 4; i++) {
        int idx = i * 256 + tid;
        arow[i] = idx >> 3;
        ac4[i]  = (idx & 7) << 2;
    }
    int bk_[2], bn4[2];
#pragma unroll
    for (int i = 0; i < 2; i++) {
        int idx = i * 256 + tid;
        bk_[i] = idx >> 4;
        bn4[i] = (idx & 15) << 2;
    }

    const float* Abase  = attn + (size_t)(h * 512 + bm) * 512;
    const float* Vhbase = vh_ + (size_t)(bt * 512) * 512 + kh * 64;
    const float* Vlbase = vl_ + (size_t)(bt * 512) * 512 + kh * 64;

    float4 ra[4], rbh[2], rbl[2];
#pragma unroll
    for (int i = 0; i < 4; i++)
        ra[i] = *(const float4*)(Abase + (size_t)arow[i] * 512 + ac4[i]);
#pragma unroll
    for (int i = 0; i < 2; i++) {
        rbh[i] = *(const float4*)(Vhbase + (size_t)bk_[i] * 512 + bn4[i]);
        rbl[i] = *(const float4*)(Vlbase + (size_t)bk_[i] * 512 + bn4[i]);
    }

    const int wm = (wid & 3) << 5;
    const int wn = (wid >> 2) << 5;

    float acc[2][4][4];
#pragma unroll
    for (int mt = 0; mt < 2; mt++)
#pragma unroll
        for (int nt = 0; nt < 4; nt++)
#pragma unroll
            for (int r = 0; r < 4; r++) acc[mt][nt][r] = 0.f;

    for (int c = 0; c < 16; c++) {
        float* Asb = sm + (c & 1) * AV2_STAGE_FLOATS;
        float* Bhb = Asb + 4608;
        float* Blb = Asb + 6912;
#pragma unroll
        for (int i = 0; i < 4; i++) {
            float* p = Asb + arow[i] * 36 + ac4[i];
            p[0] = ra[i].x; p[1] = ra[i].y; p[2] = ra[i].z; p[3] = ra[i].w;
        }
#pragma unroll
        for (int i = 0; i < 2; i++) {
            Bhb[(bn4[i] + 0) * 36 + bk_[i]] = rbh[i].x;
            Bhb[(bn4[i] + 1) * 36 + bk_[i]] = rbh[i].y;
            Bhb[(bn4[i] + 2) * 36 + bk_[i]] = rbh[i].z;
            Bhb[(bn4[i] + 3) * 36 + bk_[i]] = rbh[i].w;
            Blb[(bn4[i] + 0) * 36 + bk_[i]] = rbl[i].x;
            Blb[(bn4[i] + 1) * 36 + bk_[i]] = rbl[i].y;
            Blb[(bn4[i] + 2) * 36 + bk_[i]] = rbl[i].z;
            Blb[(bn4[i] + 3) * 36 + bk_[i]] = rbl[i].w;
        }
        __syncthreads();
        if (c + 1 < 16) {
            const int k1 = (c + 1) << 5;
#pragma unroll
            for (int i = 0; i < 4; i++)
                ra[i] = *(const float4*)(Abase + (size_t)arow[i] * 512 + k1 + ac4[i]);
#pragma unroll
            for (int i = 0; i < 2; i++) {
                rbh[i] = *(const float4*)(Vhbase + (size_t)(k1 + bk_[i]) * 512 + bn4[i]);
                rbl[i] = *(const float4*)(Vlbase + (size_t)(k1 + bk_[i]) * 512 + bn4[i]);
            }
        }
#pragma unroll
        for (int ks = 0; ks < 4; ks++) {
            const float* Ac  = Asb + ks * 8 + qr;
            const float* Bch = Bhb + ks * 8 + qr;
            const float* Bcl = Blb + ks * 8 + qr;
            uint32_t ah[2][4], al[2][4];
#pragma unroll
            for (int mt = 0; mt < 2; mt++) {
                int r0 = wm + mt * 16 + grp;
                split_tf32(Ac[r0 * 36],           ah[mt][0], al[mt][0]);
                split_tf32(Ac[(r0 + 8) * 36],     ah[mt][1], al[mt][1]);
                split_tf32(Ac[r0 * 36 + 4],       ah[mt][2], al[mt][2]);
                split_tf32(Ac[(r0 + 8) * 36 + 4], ah[mt][3], al[mt][3]);
            }
            uint32_t bh[4][2], bl[4][2];
#pragma unroll
            for (int nt = 0; nt < 4; nt++) {
                int rn = wn + nt * 8 + grp;
                bh[nt][0] = __float_as_uint(Bch[rn * 36]);
                bh[nt][1] = __float_as_uint(Bch[rn * 36 + 4]);
                bl[nt][0] = __float_as_uint(Bcl[rn * 36]);
                bl[nt][1] = __float_as_uint(Bcl[rn * 36 + 4]);
            }
#pragma unroll
            for (int mt = 0; mt < 2; mt++)
#pragma unroll
                for (int nt = 0; nt < 4; nt++) {
                    MMA_TF32(acc[mt][nt], ah[mt][0], ah[mt][1], ah[mt][2], ah[mt][3],
                             bh[nt][0], bh[nt][1]);
                    MMA_TF32(acc[mt][nt], al[mt][0], al[mt][1], al[mt][2], al[mt][3],
                             bh[nt][0], bh[nt][1]);
                    MMA_TF32(acc[mt][nt], ah[mt][0], ah[mt][1], ah[mt][2], ah[mt][3],
                             bl[nt][0], bl[nt][1]);
                }
        }
        __syncthreads();
    }

#pragma unroll
    for (int mt = 0; mt < 2; mt++) {
        const int r0 = bt * 512 + bm + wm + mt * 16 + grp;
#pragma unroll
        for (int nt = 0; nt < 4; nt++) {
            const int col = kh * 64 + wn + nt * 8 + (qr << 1);
            *(float2*)(out + (size_t)r0 * 512 + col) =
                make_float2(acc[mt][nt][0], acc[mt][nt][1]);
            *(float2*)(out + (size_t)(r0 + 8) * 512 + col) =
                make_float2(acc[mt][nt][2], acc[mt][nt][3]);
        }
    }
}

// ---------------------------------------------------------------------------
// Graph bias precompute
// ---------------------------------------------------------------------------
__global__ __launch_bounds__(256) void bias_kernel(
    const float* __restrict__ E, const float* __restrict__ lap,
    const float* __restrict__ alphap, const float* __restrict__ betap,
    float* __restrict__ gb)
{
    __shared__ __align__(16) float ei[64];
    __shared__ float reda[8];
    __shared__ float redb[8];
    int i = blockIdx.x;
    int tid = threadIdx.x;
    if (tid < 16) ((float4*)ei)[tid] = ((const float4*)(E + (size_t)i * 64))[tid];
    __syncthreads();

    int j0 = tid, j1 = tid + 256;
    const float* e0 = E + (size_t)j0 * 64;
    const float* e1 = E + (size_t)j1 * 64;
    float r0 = 0.f, r1 = 0.f;
#pragma unroll
    for (int e = 0; e < 64; e += 4) {
        float4 a = *(const float4*)(ei + e);
        float4 u = *(const float4*)(e0 + e);
        float4 w = *(const float4*)(e1 + e);
        r0 += a.x * u.x + a.y * u.y + a.z * u.z + a.w * u.w;
        r1 += a.x * w.x + a.y * w.y + a.z * w.z + a.w * w.w;
    }
    r0 = fmaxf(r0, 0.f);
    r1 = fmaxf(r1, 0.f);

    float mx = fmaxf(r0, r1);
#pragma unroll
    for (int o = 16; o; o >>= 1) mx = fmaxf(mx, __shfl_xor_sync(0xffffffffu, mx, o));
    if ((tid & 31) == 0) reda[tid >> 5] = mx;
    __syncthreads();
    mx = fmaxf(fmaxf(fmaxf(reda[0], reda[1]), fmaxf(reda[2], reda[3])),
               fmaxf(fmaxf(reda[4], reda[5]), fmaxf(reda[6], reda[7])));

    float ex0 = __expf(r0 - mx), ex1 = __expf(r1 - mx);
    float s = ex0 + ex1;
#pragma unroll
    for (int o = 16; o; o >>= 1) s += __shfl_xor_sync(0xffffffffu, s, o);
    if ((tid & 31) == 0) redb[tid >> 5] = s;
    __syncthreads();
    s = redb[0] + redb[1] + redb[2] + redb[3] + redb[4] + redb[5] + redb[6] + redb[7];
    float inv = 1.0f / s;

    float alpha = *alphap, beta = *betap;
    float lp0 = lap[(size_t)i * 512 + j0];
    float lp1 = lap[(size_t)i * 512 + j1];
    float m0 = (lp0 != 0.f) ? 0.f : -1e9f;
    float m1 = (lp1 != 0.f) ? 0.f : -1e9f;
    gb[(size_t)i * 512 + j0] = alpha * ex0 * inv + beta * lp0 + m0;
    gb[(size_t)i * 512 + j1] = alpha * ex1 * inv + beta * lp1 + m1;
}

// ---------------------------------------------------------------------------
// LayerNorm over D=512. One warp per row.
// ---------------------------------------------------------------------------
__global__ __launch_bounds__(256) void ln_kernel(
    const float* __restrict__ X, const float* __restrict__ g,
    const float* __restrict__ b, float* __restrict__ Y, int rows)
{
    int gw = (blockIdx.x * 256 + threadIdx.x) >> 5;
    if (gw >= rows) return;
    int lane = threadIdx.x & 31;
    const float* xr = X + (size_t)gw * 512;
    float* yr = Y + (size_t)gw * 512;
    float4 v[4];
    float s = 0.f, ss = 0.f;
#pragma unroll
    for (int w = 0; w < 4; w++) {
        v[w] = *(const float4*)(xr + w * 128 + lane * 4);
        s += v[w].x + v[w].y + v[w].z + v[w].w;
        ss += v[w].x * v[w].x + v[w].y * v[w].y + v[w].z * v[w].z + v[w].w * v[w].w;
    }
#pragma unroll
    for (int o = 16; o; o >>= 1) {
        s += __shfl_xor_sync(0xffffffffu, s, o);
        ss += __shfl_xor_sync(0xffffffffu, ss, o);
    }
    float mean = s * (1.0f / 512.0f);
    float var = ss * (1.0f / 512.0f) - mean * mean;
    float rstd = rsqrtf(var + 1e-5f);
#pragma unroll
    for (int w = 0; w < 4; w++) {
        int c = w * 128 + lane * 4;
        float4 gg = *(const float4*)(g + c);
        float4 bb = *(const float4*)(b + c);
        float4 o;
        o.x = (v[w].x - mean) * rstd * gg.x + bb.x;
        o.y = (v[w].y - mean) * rstd * gg.y + bb.y;
        o.z = (v[w].z - mean) * rstd * gg.z + bb.z;
        o.w = (v[w].w - mean) * rstd * gg.w + bb.w;
        *(float4*)(yr + c) = o;
    }
}

// ---------------------------------------------------------------------------
// Row softmax, in place
// ---------------------------------------------------------------------------
__global__ __launch_bounds__(256) void softmax_kernel(float* __restrict__ L, int rows)
{
    int r = (blockIdx.x * 256 + threadIdx.x) >> 5;
    if (r >= rows) return;
    int lane = threadIdx.x & 31;
    float* row = L + (size_t)r * 512;
    float4 v[4];
    float mx = -3.0e38f;
#pragma unroll
    for (int w = 0; w < 4; w++) {
        v[w] = *(const float4*)(row + w * 128 + lane * 4);
        mx = fmaxf(mx, fmaxf(fmaxf(v[w].x, v[w].y), fmaxf(v[w].z, v[w].w)));
    }
#pragma unroll
    for (int o = 16; o; o >>= 1) mx = fmaxf(mx, __shfl_xor_sync(0xffffffffu, mx, o));
    float s = 0.f;
#pragma unroll
    for (int w = 0; w < 4; w++) {
        v[w].x = __expf(v[w].x - mx);
        v[w].y = __expf(v[w].y - mx);
        v[w].z = __expf(v[w].z - mx);
        v[w].w = __expf(v[w].w - mx);
        s += v[w].x + v[w].y + v[w].z + v[w].w;
    }
#pragma unroll
    for (int o = 16; o; o >>= 1) s += __shfl_xor_sync(0xffffffffu, s, o);
    float inv = 1.0f / s;
#pragma unroll
    for (int w = 0; w < 4; w++) {
        v[w].x *= inv; v[w].y *= inv; v[w].z *= inv; v[w].w *= inv;
        *(float4*)(row + w * 128 + lane * 4) = v[w];
    }
}

// ---------------------------------------------------------------------------
// Host launcher
// ---------------------------------------------------------------------------
extern "C" void kernel_launch(void* const* d_in, const int* in_sizes, int n_in,
                              void* d_out, int out_size)
{
    const float* x    = (const float*)d_in[0];
    const float* lap  = (const float*)d_in[1];
    const float* emb  = (const float*)d_in[2];
    const float* Wq   = (const float*)d_in[3];
    const float* bq   = (const float*)d_in[4];
    const float* Wk   = (const float*)d_in[5];
    const float* bk   = (const float*)d_in[6];
    const float* Wv   = (const float*)d_in[7];
    const float* bv   = (const float*)d_in[8];
    const float* ln1g = (const float*)d_in[9];
    const float* ln1b = (const float*)d_in[10];
    const float* ln2g = (const float*)d_in[11];
    const float* ln2b = (const float*)d_in[12];
    const float* alpha = (const float*)d_in[13];
    const float* beta  = (const float*)d_in[14];
    const float* Wo   = (const float*)d_in[15];
    const float* bo   = (const float*)d_in[16];
    const float* W1   = (const float*)d_in[17];
    const float* b1   = (const float*)d_in[18];
    const float* W2   = (const float*)d_in[19];
    const float* b2   = (const float*)d_in[20];
    float* out = (float*)d_out;

    float* base = nullptr;
    cudaGetSymbolAddress((void**)&base, g_scratch);
    float* xn     = base + OFF_XN;
    float* q      = base + OFF_Q;
    float* k_h    = base + OFF_KH;
    float* k_l    = base + OFF_KL;
    float* v_h    = base + OFF_VH;
    float* v_l    = base + OFF_VL;
    float* ao     = base + OFF_AO;
    float* x1     = base + OFF_X1;
    float* hin    = base + OFF_HIN;
    float* hbuf   = base + OFF_HB;
    float* logits = base + OFF_LOG;
    float* gb     = base + OFF_GB;

    static bool attr_done = false;
    if (!attr_done) {
        cudaFuncSetAttribute(gemm_tc1_kernel,
                             cudaFuncAttributeMaxDynamicSharedMemorySize, G1_SMEM_BYTES);
        cudaFuncSetAttribute(tc_scores2_kernel,
                             cudaFuncAttributeMaxDynamicSharedMemorySize, G2_SMEM_BYTES);
        cudaFuncSetAttribute(tc_av2_kernel,
                             cudaFuncAttributeMaxDynamicSharedMemorySize, AV2_SMEM_BYTES);
        attr_done = true;
    }

    // 1. graph bias
    bias_kernel<<<512, 256>>>(emb, lap, alpha, beta, gb);

    // 2. LN1
    ln_kernel<<<R_ROWS / 8, 256>>>(x, ln1g, ln1b, xn, R_ROWS);

    // 3. QKV projections (1xTF32-RNA). K,V outputs epilogue-split for 3x attention.
    dim3 gq(D_DIM / 128, R_ROWS / 128);
    gemm_tc1_kernel<<<gq, 256, G1_SMEM_BYTES>>>(
        xn, Wq, bq, nullptr, q, nullptr, nullptr, R_ROWS, D_DIM, D_DIM, 0);
    gemm_tc1_kernel<<<gq, 256, G1_SMEM_BYTES>>>(
        xn, Wk, bk, nullptr, nullptr, k_h, k_l, R_ROWS, D_DIM, D_DIM, 0);
    gemm_tc1_kernel<<<gq, 256, G1_SMEM_BYTES>>>(
        xn, Wv, bv, nullptr, nullptr, v_h, v_l, R_ROWS, D_DIM, D_DIM, 0);

    // 4. scores + bias (3xTF32)
    tc_scores2_kernel<<<dim3(4, 4, H_HEADS), 256, G2_SMEM_BYTES>>>(q, k_h, k_l, gb, logits);

    // 5. softmax
    softmax_kernel<<<(H_HEADS * N_NODES) / 8, 256>>>(logits, H_HEADS * N_NODES);

    // 6. attn @ V (3xTF32)
    tc_av2_kernel<<<dim3(4, H_HEADS), 256, AV2_SMEM_BYTES>>>(logits, v_h, v_l, ao);

    // 7. output projection + residual (1xTF32-RNA)
    gemm_tc1_kernel<<<gq, 256, G1_SMEM_BYTES>>>(
        ao, Wo, bo, x, x1, nullptr, nullptr, R_ROWS, D_DIM, D_DIM, 0);

    // 8. LN2
    ln_kernel<<<R_ROWS / 8, 256>>>(x1, ln2g, ln2b, hin, R_ROWS);

    // 9. FF up (1xTF32-RNA, relu)
    gemm_tc1_kernel<<<dim3(DFF / 128, R_ROWS / 128), 256, G1_SMEM_BYTES>>>(
        hin, W1, b1, nullptr, hbuf, nullptr, nullptr, R_ROWS, DFF, D_DIM, 1);

    // 10. FF down + residual (1xTF32-RNA)
    gemm_tc1_kernel<<<dim3(D_DIM / 128, R_ROWS / 128), 256, G1_SMEM_BYTES>>>(
        hbuf, W2, b2, x1, out, nullptr, nullptr, R_ROWS, D_DIM, DFF, 0);
}

// round 9
// speedup vs baseline: 2.8751x; 1.0990x over previous
#include <cuda_runtime.h>
#include <cstdint>

// ---------------------------------------------------------------------------
// Problem constants
// ---------------------------------------------------------------------------
#define R_ROWS 16384
#define N_NODES 512
#define D_DIM 512
#define H_HEADS 256
#define DFF 2048

// Scratch layout (float offsets)
#define OFF_XN   0ull
#define OFF_Q    8388608ull
#define OFF_KH   16777216ull
#define OFF_KL   25165824ull
#define OFF_VH   33554432ull
#define OFF_VL   41943040ull
#define OFF_AO   50331648ull
#define OFF_X1   58720256ull
#define OFF_HIN  67108864ull
#define OFF_HB   75497472ull
#define OFF_LOG  109051904ull
#define OFF_GB   176160768ull
#define OFF_WQT  176422912ull
#define OFF_WKT  176685056ull
#define OFF_WVT  176947200ull
#define OFF_WOT  177209344ull
#define OFF_W1T  177471488ull
#define OFF_W2T  178520064ull

__device__ float g_scratch[182714368];

// ===========================================================================
// Helpers
// ===========================================================================
__device__ __forceinline__ uint32_t smem_u32(const void* p) {
    uint32_t a;
    asm("{ .reg .u64 t; cvta.to.shared.u64 t, %1; cvt.u32.u64 %0, t; }"
        : "=r"(a) : "l"(p));
    return a;
}

#define CP_ASYNC16(dst, src) \
    asm volatile("cp.async.cg.shared.global [%0], [%1], 16;" :: "r"(dst), "l"(src))
#define CP_COMMIT() asm volatile("cp.async.commit_group;" ::: "memory")
#define CP_WAIT1()  asm volatile("cp.async.wait_group 1;" ::: "memory")
#define CP_WAIT0()  asm volatile("cp.async.wait_group 0;" ::: "memory")

#define MMA_TF32(d, a0, a1, a2, a3, b0, b1) \
    asm volatile("mma.sync.aligned.m16n8k8.row.col.f32.tf32.tf32.f32 " \
        "{%0,%1,%2,%3}, {%4,%5,%6,%7}, {%8,%9}, {%0,%1,%2,%3};" \
        : "+f"((d)[0]), "+f"((d)[1]), "+f"((d)[2]), "+f"((d)[3]) \
        : "r"(a0), "r"(a1), "r"(a2), "r"(a3), "r"(b0), "r"(b1))

__device__ __forceinline__ void split_tf32(float x, uint32_t& hi, uint32_t& lo) {
    uint32_t h;
    asm("cvt.rna.tf32.f32 %0, %1;" : "=r"(h) : "f"(x));
    float l = x - __uint_as_float(h);
    uint32_t lb;
    asm("cvt.rna.tf32.f32 %0, %1;" : "=r"(lb) : "f"(l));
    hi = h; lo = lb;
}
__device__ __forceinline__ void split_f(float x, float& h, float& l) {
    uint32_t a, b;
    split_tf32(x, a, b);
    h = __uint_as_float(a); l = __uint_as_float(b);
}
__device__ __forceinline__ float f2tf_f(float x) {
    uint32_t r;
    asm("cvt.rna.tf32.f32 %0, %1;" : "=r"(r) : "f"(x));
    return __uint_as_float(r);
}

// ===========================================================================
// Elementwise tf32-truncate (weights, once per launch)
// ===========================================================================
__global__ __launch_bounds__(256) void trunc_kernel(
    const float* __restrict__ X, float* __restrict__ Xt, int n4)
{
    int i = blockIdx.x * 256 + threadIdx.x;
    if (i >= n4) return;
    float4 x = ((const float4*)X)[i];
    x.x = f2tf_f(x.x); x.y = f2tf_f(x.y);
    x.z = f2tf_f(x.z); x.w = f2tf_f(x.w);
    ((float4*)Xt)[i] = x;
}

// ===========================================================================
// 1xTF32 GEMM, ALL operands pre-truncated to tf32 values (no in-loop cvt):
//   C = A @ B^T + bias (+relu)(+res); optional tf32-truncated store (tout),
//   optional (Ch, Cl) split outputs for 3x consumers (K, V).
// CTA 128x128, 8 warps (4m x 2n), BK=32, cp.async double-buffered,
// ONE __syncthreads per chunk.
// ===========================================================================
#define G1_STAGE_FLOATS 9216
#define G1_SMEM_BYTES  (2 * G1_STAGE_FLOATS * 4)

__global__ __launch_bounds__(256, 2)
void gemm_tc1_kernel(const float* __restrict__ A, const float* __restrict__ Bw,
                     const float* __restrict__ bias, const float* __restrict__ res,
                     float* __restrict__ C, float* __restrict__ Ch, float* __restrict__ Cl,
                     int M, int N, int Kd, int relu, int tout)
{
    extern __shared__ float sm[];
    const int tid  = threadIdx.x;
    const int wid  = tid >> 5;
    const int lane = tid & 31;
    const int grp  = lane >> 2;
    const int qr   = lane & 3;
    const int bm   = blockIdx.y << 7;
    const int bn   = blockIdx.x << 7;
    const uint32_t sbase = smem_u32(sm);

    uint32_t soff[4];
    const float* gA[4];
    const float* gB[4];
#pragma unroll
    for (int i = 0; i < 4; i++) {
        int idx = i * 256 + tid;
        int row = idx >> 3;
        int c4  = idx & 7;
        soff[i] = (uint32_t)(row * 36 + c4 * 4) * 4u;
        gA[i] = A  + (size_t)(bm + row) * Kd + (c4 << 2);
        gB[i] = Bw + (size_t)(bn + row) * Kd + (c4 << 2);
    }

    const int nc = Kd >> 5;

    // prologue: stage 0
#pragma unroll
    for (int i = 0; i < 4; i++) {
        CP_ASYNC16(sbase + soff[i], gA[i]);
        CP_ASYNC16(sbase + 4608u * 4u + soff[i], gB[i]);
    }
    CP_COMMIT();

    const int wm = (wid & 3) << 5;
    const int wn = (wid >> 2) << 6;

    float acc[2][8][4];
#pragma unroll
    for (int mt = 0; mt < 2; mt++)
#pragma unroll
        for (int nt = 0; nt < 8; nt++)
#pragma unroll
            for (int r = 0; r < 4; r++) acc[mt][nt][r] = 0.f;

    for (int c = 0; c < nc; c++) {
        CP_WAIT0();          // stage c data complete (this thread's copies)
        __syncthreads();     // all threads' copies visible; all done with c-1
        if (c + 1 < nc) {    // refill the slot freed by chunk c-1
            const int k1 = (c + 1) << 5;
            const uint32_t st = sbase + (uint32_t)((c + 1) & 1) * (G1_STAGE_FLOATS * 4u);
#pragma unroll
            for (int i = 0; i < 4; i++) {
                CP_ASYNC16(st + soff[i], gA[i] + k1);
                CP_ASYNC16(st + 4608u * 4u + soff[i], gB[i] + k1);
            }
            CP_COMMIT();
        }

        const float* Asb = sm + (c & 1) * G1_STAGE_FLOATS;
        const float* Bsb = Asb + 4608;
#pragma unroll
        for (int ks = 0; ks < 4; ks++) {
            const float* Ac = Asb + ks * 8 + qr;
            const float* Bc = Bsb + ks * 8 + qr;
            uint32_t a_[2][4];
#pragma unroll
            for (int mt = 0; mt < 2; mt++) {
                int r0 = wm + mt * 16 + grp;
                a_[mt][0] = __float_as_uint(Ac[r0 * 36]);
                a_[mt][1] = __float_as_uint(Ac[(r0 + 8) * 36]);
                a_[mt][2] = __float_as_uint(Ac[r0 * 36 + 4]);
                a_[mt][3] = __float_as_uint(Ac[(r0 + 8) * 36 + 4]);
            }
            uint32_t b_[8][2];
#pragma unroll
            for (int nt = 0; nt < 8; nt++) {
                int rn = wn + nt * 8 + grp;
                b_[nt][0] = __float_as_uint(Bc[rn * 36]);
                b_[nt][1] = __float_as_uint(Bc[rn * 36 + 4]);
            }
#pragma unroll
            for (int mt = 0; mt < 2; mt++)
#pragma unroll
                for (int nt = 0; nt < 8; nt++)
                    MMA_TF32(acc[mt][nt], a_[mt][0], a_[mt][1], a_[mt][2], a_[mt][3],
                             b_[nt][0], b_[nt][1]);
        }
    }

#pragma unroll
    for (int mt = 0; mt < 2; mt++) {
        const int r0 = bm + wm + mt * 16 + grp;
#pragma unroll
        for (int nt = 0; nt < 8; nt++) {
            const int col = bn + wn + nt * 8 + (qr << 1);
            float2 bb = *(const float2*)(bias + col);
            float v0 = acc[mt][nt][0] + bb.x;
            float v1 = acc[mt][nt][1] + bb.y;
            float v2 = acc[mt][nt][2] + bb.x;
            float v3 = acc[mt][nt][3] + bb.y;
            if (relu) {
                v0 = fmaxf(v0, 0.f); v1 = fmaxf(v1, 0.f);
                v2 = fmaxf(v2, 0.f); v3 = fmaxf(v3, 0.f);
            }
            if (res) {
                float2 ra = *(const float2*)(res + (size_t)r0 * N + col);
                float2 rb = *(const float2*)(res + (size_t)(r0 + 8) * N + col);
                v0 += ra.x; v1 += ra.y; v2 += rb.x; v3 += rb.y;
            }
            if (tout) {
                v0 = f2tf_f(v0); v1 = f2tf_f(v1);
                v2 = f2tf_f(v2); v3 = f2tf_f(v3);
            }
            if (C) {
                *(float2*)(C + (size_t)r0 * N + col)       = make_float2(v0, v1);
                *(float2*)(C + (size_t)(r0 + 8) * N + col) = make_float2(v2, v3);
            }
            if (Ch) {
                float h0, l0, h1, l1, h2, l2, h3, l3;
                split_f(v0, h0, l0); split_f(v1, h1, l1);
                split_f(v2, h2, l2); split_f(v3, h3, l3);
                *(float2*)(Ch + (size_t)r0 * N + col)       = make_float2(h0, h1);
                *(float2*)(Cl + (size_t)r0 * N + col)       = make_float2(l0, l1);
                *(float2*)(Ch + (size_t)(r0 + 8) * N + col) = make_float2(h2, h3);
                *(float2*)(Cl + (size_t)(r0 + 8) * N + col) = make_float2(l2, l3);
            }
        }
    }
}

// ===========================================================================
// Scores (3xTF32): logits[h][i][j] = (Q_h[i].K_h[j])*0.125 + gb[i][j]
// A = q raw (in-loop split); B = (k_h, k_l) pre-split. K=64 (2 chunks).
// ===========================================================================
#define G2_STAGE_FLOATS 13824
#define G2_SMEM_BYTES  (2 * G2_STAGE_FLOATS * 4)

__global__ __launch_bounds__(256, 2)
void tc_scores2_kernel(const float* __restrict__ q, const float* __restrict__ kh_,
                       const float* __restrict__ kl_, const float* __restrict__ gb,
                       float* __restrict__ logits)
{
    extern __shared__ float sm[];
    const int tid  = threadIdx.x;
    const int wid  = tid >> 5;
    const int lane = tid & 31;
    const int grp  = lane >> 2;
    const int qr   = lane & 3;
    const int h  = blockIdx.z;
    const int bt = h >> 3;
    const int kh = h & 7;
    const int bm = blockIdx.y << 7;
    const int bn = blockIdx.x << 7;
    const uint32_t sbase = smem_u32(sm);

    uint32_t soff[4];
    const float* gA[4];
    const float* gBh[4];
    const float* gBl[4];
#pragma unroll
    for (int i = 0; i < 4; i++) {
        int idx = i * 256 + tid;
        int row = idx >> 3;
        int c4  = idx & 7;
        soff[i] = (uint32_t)(row * 36 + c4 * 4) * 4u;
        gA[i]  = q   + (size_t)(bt * 512 + bm + row) * 512 + kh * 64 + (c4 << 2);
        gBh[i] = kh_ + (size_t)(bt * 512 + bn + row) * 512 + kh * 64 + (c4 << 2);
        gBl[i] = kl_ + (size_t)(bt * 512 + bn + row) * 512 + kh * 64 + (c4 << 2);
    }

#pragma unroll
    for (int i = 0; i < 4; i++) {
        CP_ASYNC16(sbase + soff[i], gA[i]);
        CP_ASYNC16(sbase + 4608u * 4u + soff[i], gBh[i]);
        CP_ASYNC16(sbase + 9216u * 4u + soff[i], gBl[i]);
    }
    CP_COMMIT();

    const int wm = (wid & 3) << 5;
    const int wn = (wid >> 2) << 6;

    float acc[2][8][4];
#pragma unroll
    for (int mt = 0; mt < 2; mt++)
#pragma unroll
        for (int nt = 0; nt < 8; nt++)
#pragma unroll
            for (int r = 0; r < 4; r++) acc[mt][nt][r] = 0.f;

#pragma unroll
    for (int c = 0; c < 2; c++) {
        if (c == 0) {
            const uint32_t st = sbase + (G2_STAGE_FLOATS * 4u);
#pragma unroll
            for (int i = 0; i < 4; i++) {
                CP_ASYNC16(st + soff[i], gA[i] + 32);
                CP_ASYNC16(st + 4608u * 4u + soff[i], gBh[i] + 32);
                CP_ASYNC16(st + 9216u * 4u + soff[i], gBl[i] + 32);
            }
            CP_COMMIT();
            CP_WAIT1();
        } else {
            CP_WAIT0();
        }
        __syncthreads();

        const float* Asb = sm + c * G2_STAGE_FLOATS;
        const float* Bhb = Asb + 4608;
        const float* Blb = Asb + 9216;
#pragma unroll
        for (int ks = 0; ks < 4; ks++) {
            const float* Ac  = Asb + ks * 8 + qr;
            const float* Bch = Bhb + ks * 8 + qr;
            const float* Bcl = Blb + ks * 8 + qr;
            uint32_t ah[2][4], al[2][4];
#pragma unroll
            for (int mt = 0; mt < 2; mt++) {
                int r0 = wm + mt * 16 + grp;
                split_tf32(Ac[r0 * 36],           ah[mt][0], al[mt][0]);
                split_tf32(Ac[(r0 + 8) * 36],     ah[mt][1], al[mt][1]);
                split_tf32(Ac[r0 * 36 + 4],       ah[mt][2], al[mt][2]);
                split_tf32(Ac[(r0 + 8) * 36 + 4], ah[mt][3], al[mt][3]);
            }
            uint32_t bh[8][2], bl[8][2];
#pragma unroll
            for (int nt = 0; nt < 8; nt++) {
                int rn = wn + nt * 8 + grp;
                bh[nt][0] = __float_as_uint(Bch[rn * 36]);
                bh[nt][1] = __float_as_uint(Bch[rn * 36 + 4]);
                bl[nt][0] = __float_as_uint(Bcl[rn * 36]);
                bl[nt][1] = __float_as_uint(Bcl[rn * 36 + 4]);
            }
#pragma unroll
            for (int mt = 0; mt < 2; mt++)
#pragma unroll
                for (int nt = 0; nt < 8; nt++) {
                    MMA_TF32(acc[mt][nt], ah[mt][0], ah[mt][1], ah[mt][2], ah[mt][3],
                             bh[nt][0], bh[nt][1]);
                    MMA_TF32(acc[mt][nt], al[mt][0], al[mt][1], al[mt][2], al[mt][3],
                             bh[nt][0], bh[nt][1]);
                    MMA_TF32(acc[mt][nt], ah[mt][0], ah[mt][1], ah[mt][2], ah[mt][3],
                             bl[nt][0], bl[nt][1]);
                }
        }
        __syncthreads();
    }

    float* Lh = logits + (size_t)h * 512 * 512;
#pragma unroll
    for (int mt = 0; mt < 2; mt++) {
        const int gi = bm + wm + mt * 16 + grp;
#pragma unroll
        for (int nt = 0; nt < 8; nt++) {
            const int gj = bn + wn + nt * 8 + (qr << 1);
            float2 g0 = *(const float2*)(gb + (size_t)gi * 512 + gj);
            float2 g1 = *(const float2*)(gb + (size_t)(gi + 8) * 512 + gj);
            float v0 = fmaf(acc[mt][nt][0], 0.125f, g0.x);
            float v1 = fmaf(acc[mt][nt][1], 0.125f, g0.y);
            float v2 = fmaf(acc[mt][nt][2], 0.125f, g1.x);
            float v3 = fmaf(acc[mt][nt][3], 0.125f, g1.y);
            *(float2*)(Lh + (size_t)gi * 512 + gj)       = make_float2(v0, v1);
            *(float2*)(Lh + (size_t)(gi + 8) * 512 + gj) = make_float2(v2, v3);
        }
    }
}

// ===========================================================================
// AV (3xTF32): out_h = P_h @ V_h.  V pre-split; transposed staging.
// Output ao is tf32-truncated (sole consumer is the 1x Wo GEMM).
// ===========================================================================
#define AV2_STAGE_FLOATS 9216
#define AV2_SMEM_BYTES  (2 * AV2_STAGE_FLOATS * 4)

__global__ __launch_bounds__(256, 2)
void tc_av2_kernel(const float* __restrict__ attn, const float* __restrict__ vh_,
                   const float* __restrict__ vl_, float* __restrict__ out)
{
    extern __shared__ float sm[];
    const int tid  = threadIdx.x;
    const int wid  = tid >> 5;
    const int lane = tid & 31;
    const int grp  = lane >> 2;
    const int qr   = lane & 3;
    const int h  = blockIdx.y;
    const int bt = h >> 3;
    const int kh = h & 7;
    const int bm = blockIdx.x << 7;

    int arow[4], ac4[4];
#pragma unroll
    for (int i = 0; i < 4; i++) {
        int idx = i * 256 + tid;
        arow[i] = idx >> 3;
        ac4[i]  = (idx & 7) << 2;
    }
    int bk_[2], bn4[2];
#pragma unroll
    for (int i = 0; i < 2; i++) {
        int idx = i * 256 + tid;
        bk_[i] = idx >> 4;
        bn4[i] = (idx & 15) << 2;
    }

    const float* Abase  = attn + (size_t)(h * 512 + bm) * 512;
    const float* Vhbase = vh_ + (size_t)(bt * 512) * 512 + kh * 64;
    const float* Vlbase = vl_ + (size_t)(bt * 512) * 512 + kh * 64;

    float4 ra[4], rbh[2], rbl[2];
#pragma unroll
    for (int i = 0; i < 4; i++)
        ra[i] = *(const float4*)(Abase + (size_t)arow[i] * 512 + ac4[i]);
#pragma unroll
    for (int i = 0; i < 2; i++) {
        rbh[i] = *(const float4*)(Vhbase + (size_t)bk_[i] * 512 + bn4[i]);
        rbl[i] = *(const float4*)(Vlbase + (size_t)bk_[i] * 512 + bn4[i]);
    }

    const int wm = (wid & 3) << 5;
    const int wn = (wid >> 2) << 5;

    float acc[2][4][4];
#pragma unroll
    for (int mt = 0; mt < 2; mt++)
#pragma unroll
        for (int nt = 0; nt < 4; nt++)
#pragma unroll
            for (int r = 0; r < 4; r++) acc[mt][nt][r] = 0.f;

    for (int c = 0; c < 16; c++) {
        float* Asb = sm + (c & 1) * AV2_STAGE_FLOATS;
        float* Bhb = Asb + 4608;
        float* Blb = Asb + 6912;
#pragma unroll
        for (int i = 0; i < 4; i++) {
            float* p = Asb + arow[i] * 36 + ac4[i];
            p[0] = ra[i].x; p[1] = ra[i].y; p[2] = ra[i].z; p[3] = ra[i].w;
        }
#pragma unroll
        for (int i = 0; i < 2; i++) {
            Bhb[(bn4[i] + 0) * 36 + bk_[i]] = rbh[i].x;
            Bhb[(bn4[i] + 1) * 36 + bk_[i]] = rbh[i].y;
            Bhb[(bn4[i] + 2) * 36 + bk_[i]] = rbh[i].z;
            Bhb[(bn4[i] + 3) * 36 + bk_[i]] = rbh[i].w;
            Blb[(bn4[i] + 0) * 36 + bk_[i]] = rbl[i].x;
            Blb[(bn4[i] + 1) * 36 + bk_[i]] = rbl[i].y;
            Blb[(bn4[i] + 2) * 36 + bk_[i]] = rbl[i].z;
            Blb[(bn4[i] + 3) * 36 + bk_[i]] = rbl[i].w;
        }
        __syncthreads();
        if (c + 1 < 16) {
            const int k1 = (c + 1) << 5;
#pragma unroll
            for (int i = 0; i < 4; i++)
                ra[i] = *(const float4*)(Abase + (size_t)arow[i] * 512 + k1 + ac4[i]);
#pragma unroll
            for (int i = 0; i < 2; i++) {
                rbh[i] = *(const float4*)(Vhbase + (size_t)(k1 + bk_[i]) * 512 + bn4[i]);
                rbl[i] = *(const float4*)(Vlbase + (size_t)(k1 + bk_[i]) * 512 + bn4[i]);
            }
        }
#pragma unroll
        for (int ks = 0; ks < 4; ks++) {
            const float* Ac  = Asb + ks * 8 + qr;
            const float* Bch = Bhb + ks * 8 + qr;
            const float* Bcl = Blb + ks * 8 + qr;
            uint32_t ah[2][4], al[2][4];
#pragma unroll
            for (int mt = 0; mt < 2; mt++) {
                int r0 = wm + mt * 16 + grp;
                split_tf32(Ac[r0 * 36],           ah[mt][0], al[mt][0]);
                split_tf32(Ac[(r0 + 8) * 36],     ah[mt][1], al[mt][1]);
                split_tf32(Ac[r0 * 36 + 4],       ah[mt][2], al[mt][2]);
                split_tf32(Ac[(r0 + 8) * 36 + 4], ah[mt][3], al[mt][3]);
            }
            uint32_t bh[4][2], bl[4][2];
#pragma unroll
            for (int nt = 0; nt < 4; nt++) {
                int rn = wn + nt * 8 + grp;
                bh[nt][0] = __float_as_uint(Bch[rn * 36]);
                bh[nt][1] = __float_as_uint(Bch[rn * 36 + 4]);
                bl[nt][0] = __float_as_uint(Bcl[rn * 36]);
                bl[nt][1] = __float_as_uint(Bcl[rn * 36 + 4]);
            }
#pragma unroll
            for (int mt = 0; mt < 2; mt++)
#pragma unroll
                for (int nt = 0; nt < 4; nt++) {
                    MMA_TF32(acc[mt][nt], ah[mt][0], ah[mt][1], ah[mt][2], ah[mt][3],
                             bh[nt][0], bh[nt][1]);
                    MMA_TF32(acc[mt][nt], al[mt][0], al[mt][1], al[mt][2], al[mt][3],
                             bh[nt][0], bh[nt][1]);
                    MMA_TF32(acc[mt][nt], ah[mt][0], ah[mt][1], ah[mt][2], ah[mt][3],
                             bl[nt][0], bl[nt][1]);
                }
        }
        __syncthreads();
    }

#pragma unroll
    for (int mt = 0; mt < 2; mt++) {
        const int r0 = bt * 512 + bm + wm + mt * 16 + grp;
#pragma unroll
        for (int nt = 0; nt < 4; nt++) {
            const int col = kh * 64 + wn + nt * 8 + (qr << 1);
            *(float2*)(out + (size_t)r0 * 512 + col) =
                make_float2(f2tf_f(acc[mt][nt][0]), f2tf_f(acc[mt][nt][1]));
            *(float2*)(out + (size_t)(r0 + 8) * 512 + col) =
                make_float2(f2tf_f(acc[mt][nt][2]), f2tf_f(acc[mt][nt][3]));
        }
    }
}

// ---------------------------------------------------------------------------
// Graph bias precompute
// ---------------------------------------------------------------------------
__global__ __launch_bounds__(256) void bias_kernel(
    const float* __restrict__ E, const float* __restrict__ lap,
    const float* __restrict__ alphap, const float* __restrict__ betap,
    float* __restrict__ gb)
{
    __shared__ __align__(16) float ei[64];
    __shared__ float reda[8];
    __shared__ float redb[8];
    int i = blockIdx.x;
    int tid = threadIdx.x;
    if (tid < 16) ((float4*)ei)[tid] = ((const float4*)(E + (size_t)i * 64))[tid];
    __syncthreads();

    int j0 = tid, j1 = tid + 256;
    const float* e0 = E + (size_t)j0 * 64;
    const float* e1 = E + (size_t)j1 * 64;
    float r0 = 0.f, r1 = 0.f;
#pragma unroll
    for (int e = 0; e < 64; e += 4) {
        float4 a = *(const float4*)(ei + e);
        float4 u = *(const float4*)(e0 + e);
        float4 w = *(const float4*)(e1 + e);
        r0 += a.x * u.x + a.y * u.y + a.z * u.z + a.w * u.w;
        r1 += a.x * w.x + a.y * w.y + a.z * w.z + a.w * w.w;
    }
    r0 = fmaxf(r0, 0.f);
    r1 = fmaxf(r1, 0.f);

    float mx = fmaxf(r0, r1);
#pragma unroll
    for (int o = 16; o; o >>= 1) mx = fmaxf(mx, __shfl_xor_sync(0xffffffffu, mx, o));
    if ((tid & 31) == 0) reda[tid >> 5] = mx;
    __syncthreads();
    mx = fmaxf(fmaxf(fmaxf(reda[0], reda[1]), fmaxf(reda[2], reda[3])),
               fmaxf(fmaxf(reda[4], reda[5]), fmaxf(reda[6], reda[7])));

    float ex0 = __expf(r0 - mx), ex1 = __expf(r1 - mx);
    float s = ex0 + ex1;
#pragma unroll
    for (int o = 16; o; o >>= 1) s += __shfl_xor_sync(0xffffffffu, s, o);
    if ((tid & 31) == 0) redb[tid >> 5] = s;
    __syncthreads();
    s = redb[0] + redb[1] + redb[2] + redb[3] + redb[4] + redb[5] + redb[6] + redb[7];
    float inv = 1.0f / s;

    float alpha = *alphap, beta = *betap;
    float lp0 = lap[(size_t)i * 512 + j0];
    float lp1 = lap[(size_t)i * 512 + j1];
    float m0 = (lp0 != 0.f) ? 0.f : -1e9f;
    float m1 = (lp1 != 0.f) ? 0.f : -1e9f;
    gb[(size_t)i * 512 + j0] = alpha * ex0 * inv + beta * lp0 + m0;
    gb[(size_t)i * 512 + j1] = alpha * ex1 * inv + beta * lp1 + m1;
}

// ---------------------------------------------------------------------------
// LayerNorm over D=512, one warp per row. Output tf32-truncated (sole
// consumers are 1x GEMM A-operands) — identical numerics to in-loop cvt.
// ---------------------------------------------------------------------------
__global__ __launch_bounds__(256) void ln_kernel(
    const float* __restrict__ X, const float* __restrict__ g,
    const float* __restrict__ b, float* __restrict__ Y, int rows)
{
    int gw = (blockIdx.x * 256 + threadIdx.x) >> 5;
    if (gw >= rows) return;
    int lane = threadIdx.x & 31;
    const float* xr = X + (size_t)gw * 512;
    float* yr = Y + (size_t)gw * 512;
    float4 v[4];
    float s = 0.f, ss = 0.f;
#pragma unroll
    for (int w = 0; w < 4; w++) {
        v[w] = *(const float4*)(xr + w * 128 + lane * 4);
        s += v[w].x + v[w].y + v[w].z + v[w].w;
        ss += v[w].x * v[w].x + v[w].y * v[w].y + v[w].z * v[w].z + v[w].w * v[w].w;
    }
#pragma unroll
    for (int o = 16; o; o >>= 1) {
        s += __shfl_xor_sync(0xffffffffu, s, o);
        ss += __shfl_xor_sync(0xffffffffu, ss, o);
    }
    float mean = s * (1.0f / 512.0f);
    float var = ss * (1.0f / 512.0f) - mean * mean;
    float rstd = rsqrtf(var + 1e-5f);
#pragma unroll
    for (int w = 0; w < 4; w++) {
        int c = w * 128 + lane * 4;
        float4 gg = *(const float4*)(g + c);
        float4 bb = *(const float4*)(b + c);
        float4 o;
        o.x = f2tf_f((v[w].x - mean) * rstd * gg.x + bb.x);
        o.y = f2tf_f((v[w].y - mean) * rstd * gg.y + bb.y);
        o.z = f2tf_f((v[w].z - mean) * rstd * gg.z + bb.z);
        o.w = f2tf_f((v[w].w - mean) * rstd * gg.w + bb.w);
        *(float4*)(yr + c) = o;
    }
}

// ---------------------------------------------------------------------------
// Row softmax, in place
// ---------------------------------------------------------------------------
__global__ __launch_bounds__(256) void softmax_kernel(float* __restrict__ L, int rows)
{
    int r = (blockIdx.x * 256 + threadIdx.x) >> 5;
    if (r >= rows) return;
    int lane = threadIdx.x & 31;
    float* row = L + (size_t)r * 512;
    float4 v[4];
    float mx = -3.0e38f;
#pragma unroll
    for (int w = 0; w < 4; w++) {
        v[w] = *(const float4*)(row + w * 128 + lane * 4);
        mx = fmaxf(mx, fmaxf(fmaxf(v[w].x, v[w].y), fmaxf(v[w].z, v[w].w)));
    }
#pragma unroll
    for (int o = 16; o; o >>= 1) mx = fmaxf(mx, __shfl_xor_sync(0xffffffffu, mx, o));
    float s = 0.f;
#pragma unroll
    for (int w = 0; w < 4; w++) {
        v[w].x = __expf(v[w].x - mx);
        v[w].y = __expf(v[w].y - mx);
        v[w].z = __expf(v[w].z - mx);
        v[w].w = __expf(v[w].w - mx);
        s += v[w].x + v[w].y + v[w].z + v[w].w;
    }
#pragma unroll
    for (int o = 16; o; o >>= 1) s += __shfl_xor_sync(0xffffffffu, s, o);
    float inv = 1.0f / s;
#pragma unroll
    for (int w = 0; w < 4; w++) {
        v[w].x *= inv; v[w].y *= inv; v[w].z *= inv; v[w].w *= inv;
        *(float4*)(row + w * 128 + lane * 4) = v[w];
    }
}

// ---------------------------------------------------------------------------
// Host launcher
// ---------------------------------------------------------------------------
extern "C" void kernel_launch(void* const* d_in, const int* in_sizes, int n_in,
                              void* d_out, int out_size)
{
    const float* x    = (const float*)d_in[0];
    const float* lap  = (const float*)d_in[1];
    const float* emb  = (const float*)d_in[2];
    const float* Wq   = (const float*)d_in[3];
    const float* bq   = (const float*)d_in[4];
    const float* Wk   = (const float*)d_in[5];
    const float* bk   = (const float*)d_in[6];
    const float* Wv   = (const float*)d_in[7];
    const float* bv   = (const float*)d_in[8];
    const float* ln1g = (const float*)d_in[9];
    const float* ln1b = (const float*)d_in[10];
    const float* ln2g = (const float*)d_in[11];
    const float* ln2b = (const float*)d_in[12];
    const float* alpha = (const float*)d_in[13];
    const float* beta  = (const float*)d_in[14];
    const float* Wo   = (const float*)d_in[15];
    const float* bo   = (const float*)d_in[16];
    const float* W1   = (const float*)d_in[17];
    const float* b1   = (const float*)d_in[18];
    const float* W2   = (const float*)d_in[19];
    const float* b2   = (const float*)d_in[20];
    float* out = (float*)d_out;

    float* base = nullptr;
    cudaGetSymbolAddress((void**)&base, g_scratch);
    float* xn     = base + OFF_XN;
    float* q      = base + OFF_Q;
    float* k_h    = base + OFF_KH;
    float* k_l    = base + OFF_KL;
    float* v_h    = base + OFF_VH;
    float* v_l    = base + OFF_VL;
    float* ao     = base + OFF_AO;
    float* x1     = base + OFF_X1;
    float* hin    = base + OFF_HIN;
    float* hbuf   = base + OFF_HB;
    float* logits = base + OFF_LOG;
    float* gb     = base + OFF_GB;
    float* wqt = base + OFF_WQT;
    float* wkt = base + OFF_WKT;
    float* wvt = base + OFF_WVT;
    float* wot = base + OFF_WOT;
    float* w1t = base + OFF_W1T;
    float* w2t = base + OFF_W2T;

    static bool attr_done = false;
    if (!attr_done) {
        cudaFuncSetAttribute(gemm_tc1_kernel,
                             cudaFuncAttributeMaxDynamicSharedMemorySize, G1_SMEM_BYTES);
        cudaFuncSetAttribute(tc_scores2_kernel,
                             cudaFuncAttributeMaxDynamicSharedMemorySize, G2_SMEM_BYTES);
        cudaFuncSetAttribute(tc_av2_kernel,
                             cudaFuncAttributeMaxDynamicSharedMemorySize, AV2_SMEM_BYTES);
        attr_done = true;
    }

    // 0. weight tf32 pre-truncation (once per launch, ~12 us)
    trunc_kernel<<<256, 256>>>(Wq, wqt, 65536);
    trunc_kernel<<<256, 256>>>(Wk, wkt, 65536);
    trunc_kernel<<<256, 256>>>(Wv, wvt, 65536);
    trunc_kernel<<<256, 256>>>(Wo, wot, 65536);
    trunc_kernel<<<1024, 256>>>(W1, w1t, 262144);
    trunc_kernel<<<1024, 256>>>(W2, w2t, 262144);

    // 1. graph bias
    bias_kernel<<<512, 256>>>(emb, lap, alpha, beta, gb);

    // 2. LN1 (tf32-truncated output)
    ln_kernel<<<R_ROWS / 8, 256>>>(x, ln1g, ln1b, xn, R_ROWS);

    // 3. QKV projections (1xTF32, cvt-free mainloop). K,V epilogue-split.
    dim3 gq(D_DIM / 128, R_ROWS / 128);
    gemm_tc1_kernel<<<gq, 256, G1_SMEM_BYTES>>>(
        xn, wqt, bq, nullptr, q, nullptr, nullptr, R_ROWS, D_DIM, D_DIM, 0, 0);
    gemm_tc1_kernel<<<gq, 256, G1_SMEM_BYTES>>>(
        xn, wkt, bk, nullptr, nullptr, k_h, k_l, R_ROWS, D_DIM, D_DIM, 0, 0);
    gemm_tc1_kernel<<<gq, 256, G1_SMEM_BYTES>>>(
        xn, wvt, bv, nullptr, nullptr, v_h, v_l, R_ROWS, D_DIM, D_DIM, 0, 0);

    // 4. scores + bias (3xTF32)
    tc_scores2_kernel<<<dim3(4, 4, H_HEADS), 256, G2_SMEM_BYTES>>>(q, k_h, k_l, gb, logits);

    // 5. softmax
    softmax_kernel<<<(H_HEADS * N_NODES) / 8, 256>>>(logits, H_HEADS * N_NODES);

    // 6. attn @ V (3xTF32; ao stored tf32-truncated)
    tc_av2_kernel<<<dim3(4, H_HEADS), 256, AV2_SMEM_BYTES>>>(logits, v_h, v_l, ao);

    // 7. output projection + residual (1xTF32)
    gemm_tc1_kernel<<<gq, 256, G1_SMEM_BYTES>>>(
        ao, wot, bo, x, x1, nullptr, nullptr, R_ROWS, D_DIM, D_DIM, 0, 0);

    // 8. LN2 (tf32-truncated output)
    ln_kernel<<<R_ROWS / 8, 256>>>(x1, ln2g, ln2b, hin, R_ROWS);

    // 9. FF up (1xTF32, relu, tf32-truncated output for W2)
    gemm_tc1_kernel<<<dim3(DFF / 128, R_ROWS / 128), 256, G1_SMEM_BYTES>>>(
        hin, w1t, b1, nullptr, hbuf, nullptr, nullptr, R_ROWS, DFF, D_DIM, 1, 1);

    // 10. FF down + residual (1xTF32)
    gemm_tc1_kernel<<<dim3(D_DIM / 128, R_ROWS / 128), 256, G1_SMEM_BYTES>>>(
        hbuf, w2t, b2, x1, out, nullptr, nullptr, R_ROWS, D_DIM, DFF, 0, 0);
}

// round 10
// speedup vs baseline: 3.2051x; 1.1148x over previous
#include <cuda_runtime.h>
#include <cstdint>

// ---------------------------------------------------------------------------
// Problem constants
// ---------------------------------------------------------------------------
#define R_ROWS 16384
#define N_NODES 512
#define D_DIM 512
#define H_HEADS 256
#define DFF 2048

// Scratch layout (float offsets)
#define OFF_XN   0ull
#define OFF_Q    8388608ull
#define OFF_K    16777216ull
#define OFF_V    25165824ull
#define OFF_AO   33554432ull
#define OFF_X1   41943040ull
#define OFF_HIN  50331648ull
#define OFF_HB   58720256ull
#define OFF_LOG  92274688ull
#define OFF_GB   159383552ull
#define OFF_WQT  159645696ull
#define OFF_WKT  159907840ull
#define OFF_WVT  160169984ull
#define OFF_WOT  160432128ull
#define OFF_W1T  160694272ull
#define OFF_W2T  161742848ull

__device__ float g_scratch[162791424];

// ===========================================================================
// Helpers
// ===========================================================================
__device__ __forceinline__ uint32_t smem_u32(const void* p) {
    uint32_t a;
    asm("{ .reg .u64 t; cvta.to.shared.u64 t, %1; cvt.u32.u64 %0, t; }"
        : "=r"(a) : "l"(p));
    return a;
}

#define CP_ASYNC16(dst, src) \
    asm volatile("cp.async.cg.shared.global [%0], [%1], 16;" :: "r"(dst), "l"(src))
#define CP_COMMIT() asm volatile("cp.async.commit_group;" ::: "memory")
#define CP_WAIT1()  asm volatile("cp.async.wait_group 1;" ::: "memory")
#define CP_WAIT0()  asm volatile("cp.async.wait_group 0;" ::: "memory")

#define MMA_TF32(d, a0, a1, a2, a3, b0, b1) \
    asm volatile("mma.sync.aligned.m16n8k8.row.col.f32.tf32.tf32.f32 " \
        "{%0,%1,%2,%3}, {%4,%5,%6,%7}, {%8,%9}, {%0,%1,%2,%3};" \
        : "+f"((d)[0]), "+f"((d)[1]), "+f"((d)[2]), "+f"((d)[3]) \
        : "r"(a0), "r"(a1), "r"(a2), "r"(a3), "r"(b0), "r"(b1))

__device__ __forceinline__ float f2tf_f(float x) {
    uint32_t r;
    asm("cvt.rna.tf32.f32 %0, %1;" : "=r"(r) : "f"(x));
    return __uint_as_float(r);
}

// ===========================================================================
// Elementwise tf32-truncate (weights, once per launch)
// ===========================================================================
__global__ __launch_bounds__(256) void trunc_kernel(
    const float* __restrict__ X, float* __restrict__ Xt, int n4)
{
    int i = blockIdx.x * 256 + threadIdx.x;
    if (i >= n4) return;
    float4 x = ((const float4*)X)[i];
    x.x = f2tf_f(x.x); x.y = f2tf_f(x.y);
    x.z = f2tf_f(x.z); x.w = f2tf_f(x.w);
    ((float4*)Xt)[i] = x;
}

// ===========================================================================
// 1xTF32 GEMM, all operands pre-truncated (cvt-free mainloop):
//   C = A @ B^T + bias (+relu)(+res); optional tf32-truncated store (tout).
// CTA 128x128, 8 warps (4m x 2n), BK=32, cp.async double-buffered,
// one __syncthreads per chunk.
// ===========================================================================
#define G1_STAGE_FLOATS 9216
#define G1_SMEM_BYTES  (2 * G1_STAGE_FLOATS * 4)

__global__ __launch_bounds__(256, 2)
void gemm_tc1_kernel(const float* __restrict__ A, const float* __restrict__ Bw,
                     const float* __restrict__ bias, const float* __restrict__ res,
                     float* __restrict__ C, int M, int N, int Kd, int relu, int tout)
{
    extern __shared__ float sm[];
    const int tid  = threadIdx.x;
    const int wid  = tid >> 5;
    const int lane = tid & 31;
    const int grp  = lane >> 2;
    const int qr   = lane & 3;
    const int bm   = blockIdx.y << 7;
    const int bn   = blockIdx.x << 7;
    const uint32_t sbase = smem_u32(sm);

    uint32_t soff[4];
    const float* gA[4];
    const float* gB[4];
#pragma unroll
    for (int i = 0; i < 4; i++) {
        int idx = i * 256 + tid;
        int row = idx >> 3;
        int c4  = idx & 7;
        soff[i] = (uint32_t)(row * 36 + c4 * 4) * 4u;
        gA[i] = A  + (size_t)(bm + row) * Kd + (c4 << 2);
        gB[i] = Bw + (size_t)(bn + row) * Kd + (c4 << 2);
    }

    const int nc = Kd >> 5;

#pragma unroll
    for (int i = 0; i < 4; i++) {
        CP_ASYNC16(sbase + soff[i], gA[i]);
        CP_ASYNC16(sbase + 4608u * 4u + soff[i], gB[i]);
    }
    CP_COMMIT();

    const int wm = (wid & 3) << 5;
    const int wn = (wid >> 2) << 6;

    float acc[2][8][4];
#pragma unroll
    for (int mt = 0; mt < 2; mt++)
#pragma unroll
        for (int nt = 0; nt < 8; nt++)
#pragma unroll
            for (int r = 0; r < 4; r++) acc[mt][nt][r] = 0.f;

    for (int c = 0; c < nc; c++) {
        CP_WAIT0();
        __syncthreads();
        if (c + 1 < nc) {
            const int k1 = (c + 1) << 5;
            const uint32_t st = sbase + (uint32_t)((c + 1) & 1) * (G1_STAGE_FLOATS * 4u);
#pragma unroll
            for (int i = 0; i < 4; i++) {
                CP_ASYNC16(st + soff[i], gA[i] + k1);
                CP_ASYNC16(st + 4608u * 4u + soff[i], gB[i] + k1);
            }
            CP_COMMIT();
        }

        const float* Asb = sm + (c & 1) * G1_STAGE_FLOATS;
        const float* Bsb = Asb + 4608;
#pragma unroll
        for (int ks = 0; ks < 4; ks++) {
            const float* Ac = Asb + ks * 8 + qr;
            const float* Bc = Bsb + ks * 8 + qr;
            uint32_t a_[2][4];
#pragma unroll
            for (int mt = 0; mt < 2; mt++) {
                int r0 = wm + mt * 16 + grp;
                a_[mt][0] = __float_as_uint(Ac[r0 * 36]);
                a_[mt][1] = __float_as_uint(Ac[(r0 + 8) * 36]);
                a_[mt][2] = __float_as_uint(Ac[r0 * 36 + 4]);
                a_[mt][3] = __float_as_uint(Ac[(r0 + 8) * 36 + 4]);
            }
            uint32_t b_[8][2];
#pragma unroll
            for (int nt = 0; nt < 8; nt++) {
                int rn = wn + nt * 8 + grp;
                b_[nt][0] = __float_as_uint(Bc[rn * 36]);
                b_[nt][1] = __float_as_uint(Bc[rn * 36 + 4]);
            }
#pragma unroll
            for (int mt = 0; mt < 2; mt++)
#pragma unroll
                for (int nt = 0; nt < 8; nt++)
                    MMA_TF32(acc[mt][nt], a_[mt][0], a_[mt][1], a_[mt][2], a_[mt][3],
                             b_[nt][0], b_[nt][1]);
        }
    }

#pragma unroll
    for (int mt = 0; mt < 2; mt++) {
        const int r0 = bm + wm + mt * 16 + grp;
#pragma unroll
        for (int nt = 0; nt < 8; nt++) {
            const int col = bn + wn + nt * 8 + (qr << 1);
            float2 bb = *(const float2*)(bias + col);
            float v0 = acc[mt][nt][0] + bb.x;
            float v1 = acc[mt][nt][1] + bb.y;
            float v2 = acc[mt][nt][2] + bb.x;
            float v3 = acc[mt][nt][3] + bb.y;
            if (relu) {
                v0 = fmaxf(v0, 0.f); v1 = fmaxf(v1, 0.f);
                v2 = fmaxf(v2, 0.f); v3 = fmaxf(v3, 0.f);
            }
            if (res) {
                float2 ra = *(const float2*)(res + (size_t)r0 * N + col);
                float2 rb = *(const float2*)(res + (size_t)(r0 + 8) * N + col);
                v0 += ra.x; v1 += ra.y; v2 += rb.x; v3 += rb.y;
            }
            if (tout) {
                v0 = f2tf_f(v0); v1 = f2tf_f(v1);
                v2 = f2tf_f(v2); v3 = f2tf_f(v3);
            }
            *(float2*)(C + (size_t)r0 * N + col)       = make_float2(v0, v1);
            *(float2*)(C + (size_t)(r0 + 8) * N + col) = make_float2(v2, v3);
        }
    }
}

// ===========================================================================
// Scores (1xTF32, cvt-free): logits[h][i][j] = (Q_h[i].K_h[j])*0.125 + gb[i][j]
// q, k pre-truncated by projection epilogues. K=64 (2 chunks, both prefetched).
// ===========================================================================
__global__ __launch_bounds__(256, 2)
void tc_scores1_kernel(const float* __restrict__ q, const float* __restrict__ kt,
                       const float* __restrict__ gb, float* __restrict__ logits)
{
    extern __shared__ float sm[];
    const int tid  = threadIdx.x;
    const int wid  = tid >> 5;
    const int lane = tid & 31;
    const int grp  = lane >> 2;
    const int qr   = lane & 3;
    const int h  = blockIdx.z;
    const int bt = h >> 3;
    const int kh = h & 7;
    const int bm = blockIdx.y << 7;
    const int bn = blockIdx.x << 7;
    const uint32_t sbase = smem_u32(sm);

    uint32_t soff[4];
    const float* gA[4];
    const float* gB[4];
#pragma unroll
    for (int i = 0; i < 4; i++) {
        int idx = i * 256 + tid;
        int row = idx >> 3;
        int c4  = idx & 7;
        soff[i] = (uint32_t)(row * 36 + c4 * 4) * 4u;
        gA[i] = q  + (size_t)(bt * 512 + bm + row) * 512 + kh * 64 + (c4 << 2);
        gB[i] = kt + (size_t)(bt * 512 + bn + row) * 512 + kh * 64 + (c4 << 2);
    }

    // prefetch both chunks
#pragma unroll
    for (int i = 0; i < 4; i++) {
        CP_ASYNC16(sbase + soff[i], gA[i]);
        CP_ASYNC16(sbase + 4608u * 4u + soff[i], gB[i]);
    }
    CP_COMMIT();
#pragma unroll
    for (int i = 0; i < 4; i++) {
        CP_ASYNC16(sbase + G1_STAGE_FLOATS * 4u + soff[i], gA[i] + 32);
        CP_ASYNC16(sbase + G1_STAGE_FLOATS * 4u + 4608u * 4u + soff[i], gB[i] + 32);
    }
    CP_COMMIT();

    const int wm = (wid & 3) << 5;
    const int wn = (wid >> 2) << 6;

    float acc[2][8][4];
#pragma unroll
    for (int mt = 0; mt < 2; mt++)
#pragma unroll
        for (int nt = 0; nt < 8; nt++)
#pragma unroll
            for (int r = 0; r < 4; r++) acc[mt][nt][r] = 0.f;

#pragma unroll
    for (int c = 0; c < 2; c++) {
        if (c == 0) { CP_WAIT1(); } else { CP_WAIT0(); }
        __syncthreads();
        const float* Asb = sm + c * G1_STAGE_FLOATS;
        const float* Bsb = Asb + 4608;
#pragma unroll
        for (int ks = 0; ks < 4; ks++) {
            const float* Ac = Asb + ks * 8 + qr;
            const float* Bc = Bsb + ks * 8 + qr;
            uint32_t a_[2][4];
#pragma unroll
            for (int mt = 0; mt < 2; mt++) {
                int r0 = wm + mt * 16 + grp;
                a_[mt][0] = __float_as_uint(Ac[r0 * 36]);
                a_[mt][1] = __float_as_uint(Ac[(r0 + 8) * 36]);
                a_[mt][2] = __float_as_uint(Ac[r0 * 36 + 4]);
                a_[mt][3] = __float_as_uint(Ac[(r0 + 8) * 36 + 4]);
            }
            uint32_t b_[8][2];
#pragma unroll
            for (int nt = 0; nt < 8; nt++) {
                int rn = wn + nt * 8 + grp;
                b_[nt][0] = __float_as_uint(Bc[rn * 36]);
                b_[nt][1] = __float_as_uint(Bc[rn * 36 + 4]);
            }
#pragma unroll
            for (int mt = 0; mt < 2; mt++)
#pragma unroll
                for (int nt = 0; nt < 8; nt++)
                    MMA_TF32(acc[mt][nt], a_[mt][0], a_[mt][1], a_[mt][2], a_[mt][3],
                             b_[nt][0], b_[nt][1]);
        }
    }

    float* Lh = logits + (size_t)h * 512 * 512;
#pragma unroll
    for (int mt = 0; mt < 2; mt++) {
        const int gi = bm + wm + mt * 16 + grp;
#pragma unroll
        for (int nt = 0; nt < 8; nt++) {
            const int gj = bn + wn + nt * 8 + (qr << 1);
            float2 g0 = *(const float2*)(gb + (size_t)gi * 512 + gj);
            float2 g1 = *(const float2*)(gb + (size_t)(gi + 8) * 512 + gj);
            float v0 = fmaf(acc[mt][nt][0], 0.125f, g0.x);
            float v1 = fmaf(acc[mt][nt][1], 0.125f, g0.y);
            float v2 = fmaf(acc[mt][nt][2], 0.125f, g1.x);
            float v3 = fmaf(acc[mt][nt][3], 0.125f, g1.y);
            *(float2*)(Lh + (size_t)gi * 512 + gj)       = make_float2(v0, v1);
            *(float2*)(Lh + (size_t)(gi + 8) * 512 + gj) = make_float2(v2, v3);
        }
    }
}

// ===========================================================================
// AV (1xTF32, cvt-free): out_h = P_h @ V_h.  P truncated by softmax, V by
// projection. V transposed into SMEM [n][k]. BM=128, BN=64, K=512, 16 chunks.
// Output ao truncated (consumer: 1x Wo GEMM).
// ===========================================================================
#define AV1_STAGE_FLOATS 6912   // A 128*36 + B 64*36
#define AV1_SMEM_BYTES  (2 * AV1_STAGE_FLOATS * 4)

__global__ __launch_bounds__(256, 2)
void tc_av1_kernel(const float* __restrict__ attn, const float* __restrict__ vt,
                   float* __restrict__ out)
{
    extern __shared__ float sm[];
    const int tid  = threadIdx.x;
    const int wid  = tid >> 5;
    const int lane = tid & 31;
    const int grp  = lane >> 2;
    const int qr   = lane & 3;
    const int h  = blockIdx.y;
    const int bt = h >> 3;
    const int kh = h & 7;
    const int bm = blockIdx.x << 7;

    int arow[4], ac4[4];
#pragma unroll
    for (int i = 0; i < 4; i++) {
        int idx = i * 256 + tid;
        arow[i] = idx >> 3;
        ac4[i]  = (idx & 7) << 2;
    }
    int bk_[2], bn4[2];
#pragma unroll
    for (int i = 0; i < 2; i++) {
        int idx = i * 256 + tid;
        bk_[i] = idx >> 4;
        bn4[i] = (idx & 15) << 2;
    }

    const float* Abase = attn + (size_t)(h * 512 + bm) * 512;
    const float* Vbase = vt + (size_t)(bt * 512) * 512 + kh * 64;

    float4 ra[4], rb[2];
#pragma unroll
    for (int i = 0; i < 4; i++)
        ra[i] = *(const float4*)(Abase + (size_t)arow[i] * 512 + ac4[i]);
#pragma unroll
    for (int i = 0; i < 2; i++)
        rb[i] = *(const float4*)(Vbase + (size_t)bk_[i] * 512 + bn4[i]);

    const int wm = (wid & 3) << 5;
    const int wn = (wid >> 2) << 5;

    float acc[2][4][4];
#pragma unroll
    for (int mt = 0; mt < 2; mt++)
#pragma unroll
        for (int nt = 0; nt < 4; nt++)
#pragma unroll
            for (int r = 0; r < 4; r++) acc[mt][nt][r] = 0.f;

    for (int c = 0; c < 16; c++) {
        float* Asb = sm + (c & 1) * AV1_STAGE_FLOATS;
        float* Bsb = Asb + 4608;
#pragma unroll
        for (int i = 0; i < 4; i++) {
            float* p = Asb + arow[i] * 36 + ac4[i];
            p[0] = ra[i].x; p[1] = ra[i].y; p[2] = ra[i].z; p[3] = ra[i].w;
        }
#pragma unroll
        for (int i = 0; i < 2; i++) {
            Bsb[(bn4[i] + 0) * 36 + bk_[i]] = rb[i].x;
            Bsb[(bn4[i] + 1) * 36 + bk_[i]] = rb[i].y;
            Bsb[(bn4[i] + 2) * 36 + bk_[i]] = rb[i].z;
            Bsb[(bn4[i] + 3) * 36 + bk_[i]] = rb[i].w;
        }
        __syncthreads();
        if (c + 1 < 16) {
            const int k1 = (c + 1) << 5;
#pragma unroll
            for (int i = 0; i < 4; i++)
                ra[i] = *(const float4*)(Abase + (size_t)arow[i] * 512 + k1 + ac4[i]);
#pragma unroll
            for (int i = 0; i < 2; i++)
                rb[i] = *(const float4*)(Vbase + (size_t)(k1 + bk_[i]) * 512 + bn4[i]);
        }
#pragma unroll
        for (int ks = 0; ks < 4; ks++) {
            const float* Ac = Asb + ks * 8 + qr;
            const float* Bc = Bsb + ks * 8 + qr;
            uint32_t a_[2][4];
#pragma unroll
            for (int mt = 0; mt < 2; mt++) {
                int r0 = wm + mt * 16 + grp;
                a_[mt][0] = __float_as_uint(Ac[r0 * 36]);
                a_[mt][1] = __float_as_uint(Ac[(r0 + 8) * 36]);
                a_[mt][2] = __float_as_uint(Ac[r0 * 36 + 4]);
                a_[mt][3] = __float_as_uint(Ac[(r0 + 8) * 36 + 4]);
            }
            uint32_t b_[4][2];
#pragma unroll
            for (int nt = 0; nt < 4; nt++) {
                int rn = wn + nt * 8 + grp;
                b_[nt][0] = __float_as_uint(Bc[rn * 36]);
                b_[nt][1] = __float_as_uint(Bc[rn * 36 + 4]);
            }
#pragma unroll
            for (int mt = 0; mt < 2; mt++)
#pragma unroll
                for (int nt = 0; nt < 4; nt++)
                    MMA_TF32(acc[mt][nt], a_[mt][0], a_[mt][1], a_[mt][2], a_[mt][3],
                             b_[nt][0], b_[nt][1]);
        }
        __syncthreads();
    }

#pragma unroll
    for (int mt = 0; mt < 2; mt++) {
        const int r0 = bt * 512 + bm + wm + mt * 16 + grp;
#pragma unroll
        for (int nt = 0; nt < 4; nt++) {
            const int col = kh * 64 + wn + nt * 8 + (qr << 1);
            *(float2*)(out + (size_t)r0 * 512 + col) =
                make_float2(f2tf_f(acc[mt][nt][0]), f2tf_f(acc[mt][nt][1]));
            *(float2*)(out + (size_t)(r0 + 8) * 512 + col) =
                make_float2(f2tf_f(acc[mt][nt][2]), f2tf_f(acc[mt][nt][3]));
        }
    }
}

// ---------------------------------------------------------------------------
// Graph bias precompute
// ---------------------------------------------------------------------------
__global__ __launch_bounds__(256) void bias_kernel(
    const float* __restrict__ E, const float* __restrict__ lap,
    const float* __restrict__ alphap, const float* __restrict__ betap,
    float* __restrict__ gb)
{
    __shared__ __align__(16) float ei[64];
    __shared__ float reda[8];
    __shared__ float redb[8];
    int i = blockIdx.x;
    int tid = threadIdx.x;
    if (tid < 16) ((float4*)ei)[tid] = ((const float4*)(E + (size_t)i * 64))[tid];
    __syncthreads();

    int j0 = tid, j1 = tid + 256;
    const float* e0 = E + (size_t)j0 * 64;
    const float* e1 = E + (size_t)j1 * 64;
    float r0 = 0.f, r1 = 0.f;
#pragma unroll
    for (int e = 0; e < 64; e += 4) {
        float4 a = *(const float4*)(ei + e);
        float4 u = *(const float4*)(e0 + e);
        float4 w = *(const float4*)(e1 + e);
        r0 += a.x * u.x + a.y * u.y + a.z * u.z + a.w * u.w;
        r1 += a.x * w.x + a.y * w.y + a.z * w.z + a.w * w.w;
    }
    r0 = fmaxf(r0, 0.f);
    r1 = fmaxf(r1, 0.f);

    float mx = fmaxf(r0, r1);
#pragma unroll
    for (int o = 16; o; o >>= 1) mx = fmaxf(mx, __shfl_xor_sync(0xffffffffu, mx, o));
    if ((tid & 31) == 0) reda[tid >> 5] = mx;
    __syncthreads();
    mx = fmaxf(fmaxf(fmaxf(reda[0], reda[1]), fmaxf(reda[2], reda[3])),
               fmaxf(fmaxf(reda[4], reda[5]), fmaxf(reda[6], reda[7])));

    float ex0 = __expf(r0 - mx), ex1 = __expf(r1 - mx);
    float s = ex0 + ex1;
#pragma unroll
    for (int o = 16; o; o >>= 1) s += __shfl_xor_sync(0xffffffffu, s, o);
    if ((tid & 31) == 0) redb[tid >> 5] = s;
    __syncthreads();
    s = redb[0] + redb[1] + redb[2] + redb[3] + redb[4] + redb[5] + redb[6] + redb[7];
    float inv = 1.0f / s;

    float alpha = *alphap, beta = *betap;
    float lp0 = lap[(size_t)i * 512 + j0];
    float lp1 = lap[(size_t)i * 512 + j1];
    float m0 = (lp0 != 0.f) ? 0.f : -1e9f;
    float m1 = (lp1 != 0.f) ? 0.f : -1e9f;
    gb[(size_t)i * 512 + j0] = alpha * ex0 * inv + beta * lp0 + m0;
    gb[(size_t)i * 512 + j1] = alpha * ex1 * inv + beta * lp1 + m1;
}

// ---------------------------------------------------------------------------
// LayerNorm over D=512, one warp per row, tf32-truncated output.
// ---------------------------------------------------------------------------
__global__ __launch_bounds__(256) void ln_kernel(
    const float* __restrict__ X, const float* __restrict__ g,
    const float* __restrict__ b, float* __restrict__ Y, int rows)
{
    int gw = (blockIdx.x * 256 + threadIdx.x) >> 5;
    if (gw >= rows) return;
    int lane = threadIdx.x & 31;
    const float* xr = X + (size_t)gw * 512;
    float* yr = Y + (size_t)gw * 512;
    float4 v[4];
    float s = 0.f, ss = 0.f;
#pragma unroll
    for (int w = 0; w < 4; w++) {
        v[w] = *(const float4*)(xr + w * 128 + lane * 4);
        s += v[w].x + v[w].y + v[w].z + v[w].w;
        ss += v[w].x * v[w].x + v[w].y * v[w].y + v[w].z * v[w].z + v[w].w * v[w].w;
    }
#pragma unroll
    for (int o = 16; o; o >>= 1) {
        s += __shfl_xor_sync(0xffffffffu, s, o);
        ss += __shfl_xor_sync(0xffffffffu, ss, o);
    }
    float mean = s * (1.0f / 512.0f);
    float var = ss * (1.0f / 512.0f) - mean * mean;
    float rstd = rsqrtf(var + 1e-5f);
#pragma unroll
    for (int w = 0; w < 4; w++) {
        int c = w * 128 + lane * 4;
        float4 gg = *(const float4*)(g + c);
        float4 bb = *(const float4*)(b + c);
        float4 o;
        o.x = f2tf_f((v[w].x - mean) * rstd * gg.x + bb.x);
        o.y = f2tf_f((v[w].y - mean) * rstd * gg.y + bb.y);
        o.z = f2tf_f((v[w].z - mean) * rstd * gg.z + bb.z);
        o.w = f2tf_f((v[w].w - mean) * rstd * gg.w + bb.w);
        *(float4*)(yr + c) = o;
    }
}

// ---------------------------------------------------------------------------
// Row softmax, in place, tf32-truncated output (consumer: 1x AV GEMM).
// ---------------------------------------------------------------------------
__global__ __launch_bounds__(256) void softmax_kernel(float* __restrict__ L, int rows)
{
    int r = (blockIdx.x * 256 + threadIdx.x) >> 5;
    if (r >= rows) return;
    int lane = threadIdx.x & 31;
    float* row = L + (size_t)r * 512;
    float4 v[4];
    float mx = -3.0e38f;
#pragma unroll
    for (int w = 0; w < 4; w++) {
        v[w] = *(const float4*)(row + w * 128 + lane * 4);
        mx = fmaxf(mx, fmaxf(fmaxf(v[w].x, v[w].y), fmaxf(v[w].z, v[w].w)));
    }
#pragma unroll
    for (int o = 16; o; o >>= 1) mx = fmaxf(mx, __shfl_xor_sync(0xffffffffu, mx, o));
    float s = 0.f;
#pragma unroll
    for (int w = 0; w < 4; w++) {
        v[w].x = __expf(v[w].x - mx);
        v[w].y = __expf(v[w].y - mx);
        v[w].z = __expf(v[w].z - mx);
        v[w].w = __expf(v[w].w - mx);
        s += v[w].x + v[w].y + v[w].z + v[w].w;
    }
#pragma unroll
    for (int o = 16; o; o >>= 1) s += __shfl_xor_sync(0xffffffffu, s, o);
    float inv = 1.0f / s;
#pragma unroll
    for (int w = 0; w < 4; w++) {
        v[w].x = f2tf_f(v[w].x * inv);
        v[w].y = f2tf_f(v[w].y * inv);
        v[w].z = f2tf_f(v[w].z * inv);
        v[w].w = f2tf_f(v[w].w * inv);
        *(float4*)(row + w * 128 + lane * 4) = v[w];
    }
}

// ---------------------------------------------------------------------------
// Host launcher
// ---------------------------------------------------------------------------
extern "C" void kernel_launch(void* const* d_in, const int* in_sizes, int n_in,
                              void* d_out, int out_size)
{
    const float* x    = (const float*)d_in[0];
    const float* lap  = (const float*)d_in[1];
    const float* emb  = (const float*)d_in[2];
    const float* Wq   = (const float*)d_in[3];
    const float* bq   = (const float*)d_in[4];
    const float* Wk   = (const float*)d_in[5];
    const float* bk   = (const float*)d_in[6];
    const float* Wv   = (const float*)d_in[7];
    const float* bv   = (const float*)d_in[8];
    const float* ln1g = (const float*)d_in[9];
    const float* ln1b = (const float*)d_in[10];
    const float* ln2g = (const float*)d_in[11];
    const float* ln2b = (const float*)d_in[12];
    const float* alpha = (const float*)d_in[13];
    const float* beta  = (const float*)d_in[14];
    const float* Wo   = (const float*)d_in[15];
    const float* bo   = (const float*)d_in[16];
    const float* W1   = (const float*)d_in[17];
    const float* b1   = (const float*)d_in[18];
    const float* W2   = (const float*)d_in[19];
    const float* b2   = (const float*)d_in[20];
    float* out = (float*)d_out;

    float* base = nullptr;
    cudaGetSymbolAddress((void**)&base, g_scratch);
    float* xn     = base + OFF_XN;
    float* q      = base + OFF_Q;
    float* kbuf   = base + OFF_K;
    float* vbuf   = base + OFF_V;
    float* ao     = base + OFF_AO;
    float* x1     = base + OFF_X1;
    float* hin    = base + OFF_HIN;
    float* hbuf   = base + OFF_HB;
    float* logits = base + OFF_LOG;
    float* gb     = base + OFF_GB;
    float* wqt = base + OFF_WQT;
    float* wkt = base + OFF_WKT;
    float* wvt = base + OFF_WVT;
    float* wot = base + OFF_WOT;
    float* w1t = base + OFF_W1T;
    float* w2t = base + OFF_W2T;

    static bool attr_done = false;
    if (!attr_done) {
        cudaFuncSetAttribute(gemm_tc1_kernel,
                             cudaFuncAttributeMaxDynamicSharedMemorySize, G1_SMEM_BYTES);
        cudaFuncSetAttribute(tc_scores1_kernel,
                             cudaFuncAttributeMaxDynamicSharedMemorySize, G1_SMEM_BYTES);
        cudaFuncSetAttribute(tc_av1_kernel,
                             cudaFuncAttributeMaxDynamicSharedMemorySize, AV1_SMEM_BYTES);
        attr_done = true;
    }

    // 0. weight tf32 pre-truncation
    trunc_kernel<<<256, 256>>>(Wq, wqt, 65536);
    trunc_kernel<<<256, 256>>>(Wk, wkt, 65536);
    trunc_kernel<<<256, 256>>>(Wv, wvt, 65536);
    trunc_kernel<<<256, 256>>>(Wo, wot, 65536);
    trunc_kernel<<<1024, 256>>>(W1, w1t, 262144);
    trunc_kernel<<<1024, 256>>>(W2, w2t, 262144);

    // 1. graph bias
    bias_kernel<<<512, 256>>>(emb, lap, alpha, beta, gb);

    // 2. LN1 (tf32-truncated)
    ln_kernel<<<R_ROWS / 8, 256>>>(x, ln1g, ln1b, xn, R_ROWS);

    // 3. QKV projections (1x, truncated outputs for 1x attention)
    dim3 gq(D_DIM / 128, R_ROWS / 128);
    gemm_tc1_kernel<<<gq, 256, G1_SMEM_BYTES>>>(
        xn, wqt, bq, nullptr, q,    R_ROWS, D_DIM, D_DIM, 0, 1);
    gemm_tc1_kernel<<<gq, 256, G1_SMEM_BYTES>>>(
        xn, wkt, bk, nullptr, kbuf, R_ROWS, D_DIM, D_DIM, 0, 1);
    gemm_tc1_kernel<<<gq, 256, G1_SMEM_BYTES>>>(
        xn, wvt, bv, nullptr, vbuf, R_ROWS, D_DIM, D_DIM, 0, 1);

    // 4. scores + bias (1x)
    tc_scores1_kernel<<<dim3(4, 4, H_HEADS), 256, G1_SMEM_BYTES>>>(q, kbuf, gb, logits);

    // 5. softmax (truncated output)
    softmax_kernel<<<(H_HEADS * N_NODES) / 8, 256>>>(logits, H_HEADS * N_NODES);

    // 6. attn @ V (1x; ao truncated)
    tc_av1_kernel<<<dim3(4, H_HEADS), 256, AV1_SMEM_BYTES>>>(logits, vbuf, ao);

    // 7. output projection + residual (1x)
    gemm_tc1_kernel<<<gq, 256, G1_SMEM_BYTES>>>(
        ao, wot, bo, x, x1, R_ROWS, D_DIM, D_DIM, 0, 0);

    // 8. LN2 (tf32-truncated)
    ln_kernel<<<R_ROWS / 8, 256>>>(x1, ln2g, ln2b, hin, R_ROWS);

    // 9. FF up (1x, relu, truncated output)
    gemm_tc1_kernel<<<dim3(DFF / 128, R_ROWS / 128), 256, G1_SMEM_BYTES>>>(
        hin, w1t, b1, nullptr, hbuf, R_ROWS, DFF, D_DIM, 1, 1);

    // 10. FF down + residual (1x)
    gemm_tc1_kernel<<<dim3(D_DIM / 128, R_ROWS / 128), 256, G1_SMEM_BYTES>>>(
        hbuf, w2t, b2, x1, out, R_ROWS, D_DIM, DFF, 0, 0);
}